// round 1
// baseline (speedup 1.0000x reference)
#include <cuda_runtime.h>
#include <math.h>

#define Bb 4
#define Nn 2048
#define Dd 1024
#define Mm (Bb*Nn)      // 8192 rows total
#define SMS 132         // padded smem stride (128 + 4) to break STS conflicts

// ---------------- scratch (static device globals; no allocation allowed) ----
__device__ float  g_q  [(size_t)Mm*Dd];
__device__ float  g_k  [(size_t)Mm*Dd];
__device__ float  g_v  [(size_t)Mm*Dd];
__device__ float  g_ctx[(size_t)Mm*Dd];
__device__ float  g_w  [(size_t)Bb*Nn*Nn];   // masked scores, then weights (in place)
__device__ float  g_qp [Mm*2];
__device__ double g_s1[Bb], g_s2[Bb];
__device__ float  g_thr[Bb];

// ---------------- shared SGEMM micro-kernel (128x128 tile, 8x8/thread) -----
__device__ __forceinline__ void mm_compute(const float* sA, const float* sB,
                                           float acc[8][8], int ty, int tx) {
#pragma unroll
    for (int k = 0; k < 8; k++) {
        float ra[8], rb[8];
#pragma unroll
        for (int i = 0; i < 8; i++) ra[i] = sA[k*SMS + ty*8 + i];
#pragma unroll
        for (int j = 0; j < 8; j++) rb[j] = sB[k*SMS + tx*8 + j];
#pragma unroll
        for (int i = 0; i < 8; i++)
#pragma unroll
            for (int j = 0; j < 8; j++)
                acc[i][j] = fmaf(ra[i], rb[j], acc[i][j]);
    }
}

// C[128,128] += A[128,K] * B[128,K]^T   (both operands K-contiguous, "NT")
__device__ __forceinline__ void nt_loop(const float* __restrict__ A,
                                        const float* __restrict__ B,
                                        int K, int kIters,
                                        float acc[8][8], float* sA, float* sB) {
    int tid = threadIdx.x;
    int lr = tid >> 1, lc = (tid & 1) * 4;
    int ty = tid >> 4, tx = tid & 15;
    const float* aP = A + (size_t)lr * K + lc;
    const float* bP = B + (size_t)lr * K + lc;
    for (int kt = 0; kt < kIters; kt++) {
        float4 av = *(const float4*)aP;
        float4 bv = *(const float4*)bP;
        __syncthreads();
        sA[(lc+0)*SMS+lr]=av.x; sA[(lc+1)*SMS+lr]=av.y;
        sA[(lc+2)*SMS+lr]=av.z; sA[(lc+3)*SMS+lr]=av.w;
        sB[(lc+0)*SMS+lr]=bv.x; sB[(lc+1)*SMS+lr]=bv.y;
        sB[(lc+2)*SMS+lr]=bv.z; sB[(lc+3)*SMS+lr]=bv.w;
        __syncthreads();
        mm_compute(sA, sB, acc, ty, tx);
        aP += 8; bP += 8;
    }
}

// C[128,128] += A[128,K] * B[K,128]     (A K-contiguous, B N-contiguous, "NN")
__device__ __forceinline__ void nn_loop(const float* __restrict__ A,
                                        const float* __restrict__ B,
                                        int K, int ldb, int kIters,
                                        float acc[8][8], float* sA, float* sB) {
    int tid = threadIdx.x;
    int lrA = tid >> 1,  lcA = (tid & 1) * 4;
    int lrB = tid >> 5,  lcB = (tid & 31) * 4;
    int ty = tid >> 4, tx = tid & 15;
    const float* aP = A + (size_t)lrA * K + lcA;
    const float* bP = B + (size_t)lrB * ldb + lcB;
    for (int kt = 0; kt < kIters; kt++) {
        float4 av = *(const float4*)aP;
        float4 bv = *(const float4*)bP;
        __syncthreads();
        sA[(lcA+0)*SMS+lrA]=av.x; sA[(lcA+1)*SMS+lrA]=av.y;
        sA[(lcA+2)*SMS+lrA]=av.z; sA[(lcA+3)*SMS+lrA]=av.w;
        *(float4*)(sB + lrB*SMS + lcB) = bv;
        __syncthreads();
        mm_compute(sA, sB, acc, ty, tx);
        aP += 8; bP += (size_t)8 * ldb;
    }
}

// ---------------- small kernels --------------------------------------------
__global__ void zero_stats_kernel() {
    if (threadIdx.x < Bb) { g_s1[threadIdx.x] = 0.0; g_s2[threadIdx.x] = 0.0; }
}

// qp = x @ Wtq^T + btq  : one warp per row
__global__ void __launch_bounds__(256) qp_kernel(const float* __restrict__ X,
                                                 const float* __restrict__ Wtq,
                                                 const float* __restrict__ btq) {
    int warp = threadIdx.x >> 5, lane = threadIdx.x & 31;
    int row = blockIdx.x * 8 + warp;
    const float* x = X + (size_t)row * Dd;
    float s0 = 0.f, s1 = 0.f;
    for (int k = lane * 4; k < Dd; k += 128) {
        float4 xv = *(const float4*)(x + k);
        float4 w0 = *(const float4*)(Wtq + k);
        float4 w1 = *(const float4*)(Wtq + Dd + k);
        s0 += xv.x*w0.x + xv.y*w0.y + xv.z*w0.z + xv.w*w0.w;
        s1 += xv.x*w1.x + xv.y*w1.y + xv.z*w1.z + xv.w*w1.w;
    }
#pragma unroll
    for (int o = 16; o; o >>= 1) {
        s0 += __shfl_xor_sync(0xffffffffu, s0, o);
        s1 += __shfl_xor_sync(0xffffffffu, s1, o);
    }
    if (lane == 0) {
        g_qp[row*2+0] = s0 + btq[0];
        g_qp[row*2+1] = s1 + btq[1];
    }
}

// per-batch sum(dist_sq) and sum(dist_sq^2) over all N*N pairs
__global__ void __launch_bounds__(256) stats_kernel() {
    __shared__ float r1[256], r2[256];
    int b = blockIdx.y, i = blockIdx.x, tid = threadIdx.x;
    const float2* qp2 = (const float2*)g_qp + (size_t)b * Nn;
    float2 qi = qp2[i];
    float s1 = 0.f, s2 = 0.f;
    for (int j = tid; j < Nn; j += 256) {
        float2 qj = qp2[j];
        float dx = qi.x - qj.x, dy = qi.y - qj.y;
        float d = dx*dx + dy*dy;
        s1 += d; s2 += d*d;
    }
    r1[tid] = s1; r2[tid] = s2; __syncthreads();
    for (int o = 128; o; o >>= 1) {
        if (tid < o) { r1[tid] += r1[tid+o]; r2[tid] += r2[tid+o]; }
        __syncthreads();
    }
    if (tid == 0) {
        atomicAdd(&g_s1[b], (double)r1[0]);
        atomicAdd(&g_s2[b], (double)r2[0]);
    }
}

__global__ void thr_kernel() {
    int b = threadIdx.x;
    if (b < Bb) {
        double M = (double)Nn * (double)Nn;
        double mean = g_s1[b] / M;
        double var = (g_s2[b] - g_s1[b]*g_s1[b]/M) / (M - 1.0);
        if (var < 0.0) var = 0.0;
        g_thr[b] = (float)(mean + 1.25 * sqrt(var));
    }
}

// q/k/v GEMMs: grid.z selects which projection
__global__ void __launch_bounds__(256) qkv_kernel(const float* __restrict__ X,
        const float* __restrict__ Wq, const float* __restrict__ bq,
        const float* __restrict__ Wk, const float* __restrict__ bk,
        const float* __restrict__ Wv, const float* __restrict__ bv) {
    __shared__ float sA[8*SMS], sB[8*SMS];
    const float *W, *bias; float* out;
    if (blockIdx.z == 0)      { W = Wq; bias = bq; out = g_q; }
    else if (blockIdx.z == 1) { W = Wk; bias = bk; out = g_k; }
    else                      { W = Wv; bias = bv; out = g_v; }
    int m0 = blockIdx.y * 128, n0 = blockIdx.x * 128;
    float acc[8][8] = {};
    nt_loop(X + (size_t)m0*Dd, W + (size_t)n0*Dd, Dd, Dd/8, acc, sA, sB);
    int ty = threadIdx.x >> 4, tx = threadIdx.x & 15;
    int col = n0 + tx*8;
    float bv_[8];
#pragma unroll
    for (int j = 0; j < 8; j++) bv_[j] = bias[col+j];
#pragma unroll
    for (int i = 0; i < 8; i++) {
        float* o = out + (size_t)(m0 + ty*8 + i)*Dd + col;
        *(float4*)(o)   = make_float4(acc[i][0]+bv_[0], acc[i][1]+bv_[1],
                                      acc[i][2]+bv_[2], acc[i][3]+bv_[3]);
        *(float4*)(o+4) = make_float4(acc[i][4]+bv_[4], acc[i][5]+bv_[5],
                                      acc[i][6]+bv_[6], acc[i][7]+bv_[7]);
    }
}

// scores = q@k^T / 32, fused phase/distance/causal mask (-inf where masked)
__global__ void __launch_bounds__(256) scores_kernel() {
    int b = blockIdx.z;
    int i0 = blockIdx.y * 128, j0 = blockIdx.x * 128;
    if (j0 > i0 + 127) return;   // fully above diagonal: never read downstream
    __shared__ float sA[8*SMS], sB[8*SMS];
    float acc[8][8] = {};
    nt_loop(g_q + (size_t)b*Nn*Dd + (size_t)i0*Dd,
            g_k + (size_t)b*Nn*Dd + (size_t)j0*Dd, Dd, Dd/8, acc, sA, sB);
    int ty = threadIdx.x >> 4, tx = threadIdx.x & 15;
    float thr = g_thr[b];
    const float2* qp2 = (const float2*)g_qp + (size_t)b * Nn;
    float2 qi[8], qj[8];
#pragma unroll
    for (int r = 0; r < 8; r++) qi[r] = qp2[i0 + ty*8 + r];
#pragma unroll
    for (int c = 0; c < 8; c++) qj[c] = qp2[j0 + tx*8 + c];
    const float NEG = __int_as_float(0xff800000);
    float* wBase = g_w + (size_t)b*Nn*Nn;
#pragma unroll
    for (int i = 0; i < 8; i++) {
        int gi = i0 + ty*8 + i;
        float res[8];
#pragma unroll
        for (int j = 0; j < 8; j++) {
            int gj = j0 + tx*8 + j;
            float dx = qi[i].x - qj[j].x, dy = qi[i].y - qj[j].y;
            float d = dx*dx + dy*dy;
            bool ok = (gj <= gi) && (d <= thr);
            // forward_bias == 0 only possible when phase ~= pi, i.e. dy ~ 0, dx < 0.
            // Only there do we evaluate the reference's exact expression.
            if (ok && dx < 0.f && fabsf(dy) < 1e-3f * (-dx)) {
                float bias = 0.5f * (1.f + cosf(atan2f(dy, dx)));
                ok = (bias != 0.f);
            }
            res[j] = ok ? acc[i][j] * 0.03125f : NEG;
        }
        float* o = wBase + (size_t)gi*Nn + j0 + tx*8;
        *(float4*)(o)   = make_float4(res[0], res[1], res[2], res[3]);
        *(float4*)(o+4) = make_float4(res[4], res[5], res[6], res[7]);
    }
}

// row softmax over j<=i; zero-fills j>i so context GEMM can read full tiles
__global__ void __launch_bounds__(256) softmax_kernel() {
    __shared__ float red[256];
    int row = blockIdx.x;
    int b = row >> 11, i = row & (Nn - 1);
    float* s = g_w + (size_t)b*Nn*Nn + (size_t)i*Nn;
    int tid = threadIdx.x;
    float mx = __int_as_float(0xff800000);
    for (int j = tid; j <= i; j += 256) mx = fmaxf(mx, s[j]);
    red[tid] = mx; __syncthreads();
    for (int o = 128; o; o >>= 1) {
        if (tid < o) red[tid] = fmaxf(red[tid], red[tid+o]);
        __syncthreads();
    }
    mx = red[0]; __syncthreads();
    float sum = 0.f;
    for (int j = tid; j <= i; j += 256) {
        float e = expf(s[j] - mx);
        s[j] = e; sum += e;
    }
    red[tid] = sum; __syncthreads();
    for (int o = 128; o; o >>= 1) {
        if (tid < o) red[tid] += red[tid+o];
        __syncthreads();
    }
    float inv = 1.f / red[0];
    for (int j = tid; j < Nn; j += 256) s[j] = (j <= i) ? s[j] * inv : 0.f;
}

// context = weights @ v  (causal k-limit per row tile)
__global__ void __launch_bounds__(256) context_kernel() {
    int b = blockIdx.z, m0 = blockIdx.y * 128, n0 = blockIdx.x * 128;
    __shared__ float sA[8*SMS], sB[8*SMS];
    float acc[8][8] = {};
    const float* A  = g_w + (size_t)b*Nn*Nn + (size_t)m0*Nn;
    const float* Bv = g_v + (size_t)b*Nn*Dd + n0;
    nn_loop(A, Bv, Nn, Dd, (m0 + 128) / 8, acc, sA, sB);
    int ty = threadIdx.x >> 4, tx = threadIdx.x & 15;
#pragma unroll
    for (int i = 0; i < 8; i++) {
        float* o = g_ctx + (size_t)(b*Nn + m0 + ty*8 + i)*Dd + n0 + tx*8;
        *(float4*)(o)   = make_float4(acc[i][0], acc[i][1], acc[i][2], acc[i][3]);
        *(float4*)(o+4) = make_float4(acc[i][4], acc[i][5], acc[i][6], acc[i][7]);
    }
}

// out = hidden + (ctx @ Wo^T + bo) + 0.1 * (normalize(qp) @ Wfq^T + bfq)
__global__ void __launch_bounds__(256) final_kernel(const float* __restrict__ X,
        const float* __restrict__ Wo, const float* __restrict__ bo,
        const float* __restrict__ Wfq, const float* __restrict__ bfq,
        float* __restrict__ out) {
    int m0 = blockIdx.y * 128, n0 = blockIdx.x * 128;
    __shared__ float sA[8*SMS], sB[8*SMS];
    float acc[8][8] = {};
    nt_loop(g_ctx + (size_t)m0*Dd, Wo + (size_t)n0*Dd, Dd, Dd/8, acc, sA, sB);
    int ty = threadIdx.x >> 4, tx = threadIdx.x & 15;
    int col = n0 + tx*8;
    float w0[8], w1[8], bb[8], qb[8];
#pragma unroll
    for (int j = 0; j < 8; j++) {
        int c = col + j;
        w0[j] = Wfq[2*c]; w1[j] = Wfq[2*c+1];
        bb[j] = bo[c]; qb[j] = bfq[c];
    }
    const float2* qp2 = (const float2*)g_qp;
#pragma unroll
    for (int i = 0; i < 8; i++) {
        int row = m0 + ty*8 + i;
        float2 qp = qp2[row];
        float nrm = fmaxf(sqrtf(qp.x*qp.x + qp.y*qp.y), 1e-12f);
        float r0 = qp.x / nrm, r1 = qp.y / nrm;
        const float* h = X + (size_t)row*Dd + col;
        float4 h0 = *(const float4*)h, h1 = *(const float4*)(h + 4);
        float res[8];
        float hv[8] = {h0.x,h0.y,h0.z,h0.w,h1.x,h1.y,h1.z,h1.w};
#pragma unroll
        for (int j = 0; j < 8; j++)
            res[j] = hv[j] + acc[i][j] + bb[j] + 0.1f*(r0*w0[j] + r1*w1[j] + qb[j]);
        float* o = out + (size_t)row*Dd + col;
        *(float4*)(o)   = make_float4(res[0], res[1], res[2], res[3]);
        *(float4*)(o+4) = make_float4(res[4], res[5], res[6], res[7]);
    }
}

// ---------------- launch ----------------------------------------------------
extern "C" void kernel_launch(void* const* d_in, const int* in_sizes, int n_in,
                              void* d_out, int out_size) {
    const float* X   = (const float*)d_in[0];
    const float* Wq  = (const float*)d_in[1];
    const float* bq  = (const float*)d_in[2];
    const float* Wk  = (const float*)d_in[3];
    const float* bk  = (const float*)d_in[4];
    const float* Wv  = (const float*)d_in[5];
    const float* bv  = (const float*)d_in[6];
    const float* Wo  = (const float*)d_in[7];
    const float* bo  = (const float*)d_in[8];
    const float* Wtq = (const float*)d_in[9];
    const float* btq = (const float*)d_in[10];
    const float* Wfq = (const float*)d_in[11];
    const float* bfq = (const float*)d_in[12];
    float* out = (float*)d_out;

    zero_stats_kernel<<<1, 32>>>();
    qp_kernel<<<Mm/8, 256>>>(X, Wtq, btq);
    stats_kernel<<<dim3(Nn, Bb), 256>>>();
    thr_kernel<<<1, 32>>>();
    qkv_kernel<<<dim3(Dd/128, Mm/128, 3), 256>>>(X, Wq, bq, Wk, bk, Wv, bv);
    scores_kernel<<<dim3(Nn/128, Nn/128, Bb), 256>>>();
    softmax_kernel<<<Mm, 256>>>();
    context_kernel<<<dim3(Dd/128, Nn/128, Bb), 256>>>();
    final_kernel<<<dim3(Dd/128, Mm/128), 256>>>(X, Wo, bo, Wfq, bfq, out);
}

// round 4
// speedup vs baseline: 2.2572x; 2.2572x over previous
#include <cuda_runtime.h>
#include <cuda_bf16.h>
#include <math.h>
#include <stdint.h>

#define Bb 4
#define Nn 2048
#define Dd 1024
#define Mm (Bb*Nn)

typedef __nv_bfloat16 bf16;

// ---------------- scratch (static device globals) ---------------------------
__device__ bf16 g_xhi[(size_t)Mm*Dd], g_xlo[(size_t)Mm*Dd];
__device__ bf16 g_wqhi[Dd*Dd], g_wqlo[Dd*Dd];
__device__ bf16 g_wkhi[Dd*Dd], g_wklo[Dd*Dd];
__device__ bf16 g_wvhi[Dd*Dd], g_wvlo[Dd*Dd];
__device__ bf16 g_wohi[Dd*Dd], g_wolo[Dd*Dd];
__device__ bf16 g_qhi[(size_t)Mm*Dd], g_qlo[(size_t)Mm*Dd];
__device__ bf16 g_khi[(size_t)Mm*Dd], g_klo[(size_t)Mm*Dd];
__device__ bf16 g_vThi[(size_t)Bb*Dd*Nn], g_vTlo[(size_t)Bb*Dd*Nn];
__device__ bf16 g_ctxhi[(size_t)Mm*Dd], g_ctxlo[(size_t)Mm*Dd];
__device__ bf16 g_whi[(size_t)Bb*Nn*Nn], g_wlo[(size_t)Bb*Nn*Nn];
__device__ float  g_w [(size_t)Bb*Nn*Nn];
__device__ float  g_qp[Mm*2];
__device__ double g_s1[Bb], g_s2[Bb];
__device__ float  g_thr[Bb];

// ---------------- PTX helpers (sm_80-class only; no tcgen05) ----------------
__device__ __forceinline__ uint32_t smem_u32(const void* p) {
    uint32_t a;
    asm("{ .reg .u64 t; cvta.to.shared.u64 t, %1; cvt.u32.u64 %0, t; }" : "=r"(a) : "l"(p));
    return a;
}
#define CP16(dst, src) \
    asm volatile("cp.async.cg.shared.global [%0], [%1], 16;" :: "r"(dst), "l"(src) : "memory")
#define CP_COMMIT() asm volatile("cp.async.commit_group;" ::: "memory")

#define LDM_X4(r, addr) \
    asm volatile("ldmatrix.sync.aligned.m8n8.x4.shared.b16 {%0,%1,%2,%3}, [%4];" \
        : "=r"((r)[0]), "=r"((r)[1]), "=r"((r)[2]), "=r"((r)[3]) : "r"(addr))

#define MMA_BF16(d, a, b) \
    asm volatile("mma.sync.aligned.m16n8k16.row.col.f32.bf16.bf16.f32 " \
        "{%0,%1,%2,%3}, {%4,%5,%6,%7}, {%8,%9}, {%0,%1,%2,%3};" \
        : "+f"((d)[0]), "+f"((d)[1]), "+f"((d)[2]), "+f"((d)[3]) \
        : "r"((a)[0]), "r"((a)[1]), "r"((a)[2]), "r"((a)[3]), "r"((b)[0]), "r"((b)[1]))

// ---------------- tiling constants ------------------------------------------
#define KS 32                 // k elements per stage
#define LDSB 80               // smem row stride in bytes (32*2 + 16 pad)
#define TILEB (128*LDSB)      // 10240 B per operand tile
#define STAGEB (4*TILEB)      // Ahi, Alo, Bhi, Blo
#define NSTAGE 3
#define SMEM_BYTES (NSTAGE*STAGEB)

// ---------------- stage load via cp.async -----------------------------------
__device__ __forceinline__ void load_stage(uint32_t sb,
        const bf16* __restrict__ Ahi, const bf16* __restrict__ Alo,
        const bf16* __restrict__ Bhi, const bf16* __restrict__ Blo,
        size_t lda, size_t ldb, int kt) {
    int tid = threadIdx.x;
    int r0 = tid >> 2, seg = tid & 3;
    size_t koff = (size_t)kt * KS + seg * 8;
#pragma unroll
    for (int p = 0; p < 2; p++) {
        int row = r0 + p * 64;
        uint32_t ds = sb + (uint32_t)row * LDSB + seg * 16;
        CP16(ds,           Ahi + (size_t)row * lda + koff);
        CP16(ds +   TILEB, Alo + (size_t)row * lda + koff);
        CP16(ds + 2*TILEB, Bhi + (size_t)row * ldb + koff);
        CP16(ds + 3*TILEB, Blo + (size_t)row * ldb + koff);
    }
    CP_COMMIT();
}

// ---------------- per-stage compute: 2 x k16, 3-term split -------------------
__device__ __forceinline__ void compute_stage(uint32_t sb, int wm, int wn, int lane,
                                              float acc[4][4][4]) {
    int arow = lane & 15;
    int acol = (lane >> 4) << 3;                      // 0 or 8
    int brow = (lane & 7) + ((lane >> 4) << 3);
    int bcol = ((lane >> 3) & 1) << 3;
#pragma unroll
    for (int ks = 0; ks < 2; ks++) {
        uint32_t ah[4][4], al[4][4];
#pragma unroll
        for (int am = 0; am < 4; am++) {
            uint32_t ad = sb + (uint32_t)(wm*64 + am*16 + arow) * LDSB + (ks*16 + acol) * 2;
            LDM_X4(ah[am], ad);
            LDM_X4(al[am], ad + TILEB);
        }
        uint32_t bh[4][2], bl[4][2];
#pragma unroll
        for (int bp = 0; bp < 2; bp++) {
            uint32_t bd = sb + 2*TILEB + (uint32_t)(wn*32 + bp*16 + brow) * LDSB
                        + (ks*16 + bcol) * 2;
            uint32_t t[4];
            LDM_X4(t, bd);
            bh[2*bp][0] = t[0]; bh[2*bp][1] = t[1];
            bh[2*bp+1][0] = t[2]; bh[2*bp+1][1] = t[3];
            LDM_X4(t, bd + TILEB);
            bl[2*bp][0] = t[0]; bl[2*bp][1] = t[1];
            bl[2*bp+1][0] = t[2]; bl[2*bp+1][1] = t[3];
        }
#pragma unroll
        for (int am = 0; am < 4; am++)
#pragma unroll
            for (int bn = 0; bn < 4; bn++) {
                MMA_BF16(acc[am][bn], ah[am], bh[bn]);
                MMA_BF16(acc[am][bn], ah[am], bl[bn]);
                MMA_BF16(acc[am][bn], al[am], bh[bn]);
            }
    }
}

// D[128,128] fp32 = A[128,K] * B[128,K]^T, 3-stage cp.async pipeline
__device__ __forceinline__ void mma_mainloop(
        const bf16* __restrict__ Ahi, const bf16* __restrict__ Alo, size_t lda,
        const bf16* __restrict__ Bhi, const bf16* __restrict__ Blo, size_t ldb,
        int kIters, float acc[4][4][4]) {
    extern __shared__ __align__(16) char smem[];
    uint32_t sb = smem_u32(smem);
    int tid = threadIdx.x, lane = tid & 31, wid = tid >> 5;
    int wm = wid >> 2, wn = wid & 3;
    load_stage(sb,          Ahi, Alo, Bhi, Blo, lda, ldb, 0);
    load_stage(sb + STAGEB, Ahi, Alo, Bhi, Blo, lda, ldb, 1);
    for (int kt = 0; kt < kIters; kt++) {
        if (kt + 1 < kIters) asm volatile("cp.async.wait_group 1;" ::: "memory");
        else                 asm volatile("cp.async.wait_group 0;" ::: "memory");
        __syncthreads();
        if (kt + 2 < kIters)
            load_stage(sb + (uint32_t)((kt+2) % NSTAGE) * STAGEB,
                       Ahi, Alo, Bhi, Blo, lda, ldb, kt + 2);
        compute_stage(sb + (uint32_t)(kt % NSTAGE) * STAGEB, wm, wn, lane, acc);
    }
}

__device__ __forceinline__ uint32_t packbf(bf16 a, bf16 b) {
    union { __nv_bfloat162 h; uint32_t u; } c;
    c.h = __halves2bfloat162(a, b);
    return c.u;
}
__device__ __forceinline__ void split1(float v, bf16& h, bf16& l) {
    h = __float2bfloat16(v);
    l = __float2bfloat16(v - __bfloat162float(h));
}

// ---------------- conversion kernel -----------------------------------------
__global__ void __launch_bounds__(256) cvt_kernel(const float* __restrict__ src,
                                                  bf16* __restrict__ hi,
                                                  bf16* __restrict__ lo, int n4) {
    int i = blockIdx.x * 256 + threadIdx.x;
    if (i >= n4) return;
    float4 v = ((const float4*)src)[i];
    bf16 h0,l0,h1,l1,h2,l2,h3,l3;
    split1(v.x,h0,l0); split1(v.y,h1,l1); split1(v.z,h2,l2); split1(v.w,h3,l3);
    *(uint2*)(hi + 4*(size_t)i) = make_uint2(packbf(h0,h1), packbf(h2,h3));
    *(uint2*)(lo + 4*(size_t)i) = make_uint2(packbf(l0,l1), packbf(l2,l3));
}

// ---------------- small SIMT kernels ----------------------------------------
__global__ void zero_stats_kernel() {
    if (threadIdx.x < Bb) { g_s1[threadIdx.x] = 0.0; g_s2[threadIdx.x] = 0.0; }
}
__global__ void __launch_bounds__(256) qp_kernel(const float* __restrict__ X,
                                                 const float* __restrict__ Wtq,
                                                 const float* __restrict__ btq) {
    int warp = threadIdx.x >> 5, lane = threadIdx.x & 31;
    int row = blockIdx.x * 8 + warp;
    const float* x = X + (size_t)row * Dd;
    float s0 = 0.f, s1 = 0.f;
    for (int k = lane * 4; k < Dd; k += 128) {
        float4 xv = *(const float4*)(x + k);
        float4 w0 = *(const float4*)(Wtq + k);
        float4 w1 = *(const float4*)(Wtq + Dd + k);
        s0 += xv.x*w0.x + xv.y*w0.y + xv.z*w0.z + xv.w*w0.w;
        s1 += xv.x*w1.x + xv.y*w1.y + xv.z*w1.z + xv.w*w1.w;
    }
#pragma unroll
    for (int o = 16; o; o >>= 1) {
        s0 += __shfl_xor_sync(0xffffffffu, s0, o);
        s1 += __shfl_xor_sync(0xffffffffu, s1, o);
    }
    if (lane == 0) { g_qp[row*2+0] = s0 + btq[0]; g_qp[row*2+1] = s1 + btq[1]; }
}
__global__ void __launch_bounds__(256) stats_kernel() {
    __shared__ float r1[256], r2[256];
    int b = blockIdx.y, i = blockIdx.x, tid = threadIdx.x;
    const float2* qp2 = (const float2*)g_qp + (size_t)b * Nn;
    float2 qi = qp2[i];
    float s1 = 0.f, s2 = 0.f;
    for (int j = tid; j < Nn; j += 256) {
        float2 qj = qp2[j];
        float dx = qi.x - qj.x, dy = qi.y - qj.y;
        float d = dx*dx + dy*dy;
        s1 += d; s2 += d*d;
    }
    r1[tid] = s1; r2[tid] = s2; __syncthreads();
    for (int o = 128; o; o >>= 1) {
        if (tid < o) { r1[tid] += r1[tid+o]; r2[tid] += r2[tid+o]; }
        __syncthreads();
    }
    if (tid == 0) { atomicAdd(&g_s1[b], (double)r1[0]); atomicAdd(&g_s2[b], (double)r2[0]); }
}
__global__ void thr_kernel() {
    int b = threadIdx.x;
    if (b < Bb) {
        double M = (double)Nn * (double)Nn;
        double mean = g_s1[b] / M;
        double var = (g_s2[b] - g_s1[b]*g_s1[b]/M) / (M - 1.0);
        if (var < 0.0) var = 0.0;
        g_thr[b] = (float)(mean + 1.25 * sqrt(var));
    }
}

// ---------------- GEMM kernels (warp MMA) ------------------------------------
__global__ void __launch_bounds__(256) mma_qkv_kernel(const float* __restrict__ bq,
                                                      const float* __restrict__ bk,
                                                      const float* __restrict__ bv) {
    int z = blockIdx.z;
    const bf16 *Whi, *Wlo; const float* bias;
    if (z == 0)      { Whi = g_wqhi; Wlo = g_wqlo; bias = bq; }
    else if (z == 1) { Whi = g_wkhi; Wlo = g_wklo; bias = bk; }
    else             { Whi = g_wvhi; Wlo = g_wvlo; bias = bv; }
    int m0 = blockIdx.y * 128, n0 = blockIdx.x * 128;
    float acc[4][4][4] = {};
    mma_mainloop(g_xhi + (size_t)m0*Dd, g_xlo + (size_t)m0*Dd, Dd,
                 Whi + (size_t)n0*Dd,  Wlo + (size_t)n0*Dd,  Dd, Dd/KS, acc);
    int tid = threadIdx.x, lane = tid & 31, wid = tid >> 5;
    int rb = (wid >> 2)*64 + (lane >> 2);
    int cb = (wid & 3)*32 + (lane & 3)*2;
    float2 b2[4];
#pragma unroll
    for (int bn = 0; bn < 4; bn++) b2[bn] = *(const float2*)(bias + n0 + cb + bn*8);
#pragma unroll
    for (int am = 0; am < 4; am++)
#pragma unroll
    for (int h = 0; h < 2; h++) {
        int row = m0 + rb + am*16 + h*8;
        if (z < 2) {
            bf16* oh = (z ? g_khi : g_qhi) + (size_t)row*Dd + n0 + cb;
            bf16* ol = (z ? g_klo : g_qlo) + (size_t)row*Dd + n0 + cb;
#pragma unroll
            for (int bn = 0; bn < 4; bn++) {
                bf16 h0,l0,h1,l1;
                split1(acc[am][bn][2*h]   + b2[bn].x, h0, l0);
                split1(acc[am][bn][2*h+1] + b2[bn].y, h1, l1);
                *(uint32_t*)(oh + bn*8) = packbf(h0, h1);
                *(uint32_t*)(ol + bn*8) = packbf(l0, l1);
            }
        } else {
            int bb = row >> 11, tok = row & (Nn - 1);
            size_t base = (size_t)bb * Dd * Nn;
#pragma unroll
            for (int bn = 0; bn < 4; bn++) {
                int col = n0 + cb + bn*8;
                bf16 h0,l0,h1,l1;
                split1(acc[am][bn][2*h]   + b2[bn].x, h0, l0);
                split1(acc[am][bn][2*h+1] + b2[bn].y, h1, l1);
                g_vThi[base + (size_t)col*Nn + tok] = h0;
                g_vTlo[base + (size_t)col*Nn + tok] = l0;
                g_vThi[base + (size_t)(col+1)*Nn + tok] = h1;
                g_vTlo[base + (size_t)(col+1)*Nn + tok] = l1;
            }
        }
    }
}

__global__ void __launch_bounds__(256) mma_scores_kernel() {
    int b = blockIdx.z;
    int i0 = blockIdx.y * 128, j0 = blockIdx.x * 128;
    if (j0 > i0) return;
    float acc[4][4][4] = {};
    mma_mainloop(g_qhi + ((size_t)b*Nn + i0)*Dd, g_qlo + ((size_t)b*Nn + i0)*Dd, Dd,
                 g_khi + ((size_t)b*Nn + j0)*Dd, g_klo + ((size_t)b*Nn + j0)*Dd, Dd,
                 Dd/KS, acc);
    int tid = threadIdx.x, lane = tid & 31, wid = tid >> 5;
    int rb = (wid >> 2)*64 + (lane >> 2);
    int cb = (wid & 3)*32 + (lane & 3)*2;
    float thr = g_thr[b];
    const float2* qp2 = (const float2*)g_qp + (size_t)b * Nn;
    const float NEG = __int_as_float(0xff800000);
    float2 qj0[4], qj1[4];
#pragma unroll
    for (int bn = 0; bn < 4; bn++) {
        qj0[bn] = qp2[j0 + cb + bn*8];
        qj1[bn] = qp2[j0 + cb + bn*8 + 1];
    }
#pragma unroll
    for (int am = 0; am < 4; am++)
#pragma unroll
    for (int h = 0; h < 2; h++) {
        int gi = i0 + rb + am*16 + h*8;
        float2 qi = qp2[gi];
        float* o = g_w + (size_t)b*Nn*Nn + (size_t)gi*Nn + j0 + cb;
#pragma unroll
        for (int bn = 0; bn < 4; bn++) {
            float r[2];
#pragma unroll
            for (int q = 0; q < 2; q++) {
                int gj = j0 + cb + bn*8 + q;
                float2 qj = q ? qj1[bn] : qj0[bn];
                float dx = qi.x - qj.x, dy = qi.y - qj.y;
                float ds = dx*dx + dy*dy;
                bool ok = (gj <= gi) && (ds <= thr);
                if (ok && dx < 0.f && fabsf(dy) < 1e-3f * (-dx)) {
                    float bias = 0.5f * (1.f + cosf(atan2f(dy, dx)));
                    ok = (bias != 0.f);
                }
                r[q] = ok ? acc[am][bn][2*h+q] * 0.03125f : NEG;
            }
            *(float2*)(o + bn*8) = make_float2(r[0], r[1]);
        }
    }
}

__global__ void __launch_bounds__(256) softmax_kernel() {
    __shared__ float red[256];
    int row = blockIdx.x;
    int b = row >> 11, i = row & (Nn - 1);
    float* s = g_w + (size_t)b*Nn*Nn + (size_t)i*Nn;
    bf16* oh = g_whi + (size_t)b*Nn*Nn + (size_t)i*Nn;
    bf16* ol = g_wlo + (size_t)b*Nn*Nn + (size_t)i*Nn;
    int tid = threadIdx.x;
    float mx = __int_as_float(0xff800000);
    for (int j = tid; j <= i; j += 256) mx = fmaxf(mx, s[j]);
    red[tid] = mx; __syncthreads();
    for (int o = 128; o; o >>= 1) {
        if (tid < o) red[tid] = fmaxf(red[tid], red[tid+o]);
        __syncthreads();
    }
    mx = red[0]; __syncthreads();
    float sum = 0.f;
    for (int j = tid; j <= i; j += 256) {
        float e = expf(s[j] - mx);
        s[j] = e; sum += e;
    }
    red[tid] = sum; __syncthreads();
    for (int o = 128; o; o >>= 1) {
        if (tid < o) red[tid] += red[tid+o];
        __syncthreads();
    }
    float inv = 1.f / red[0];
    for (int j = tid; j < Nn; j += 256) {
        float v = (j <= i) ? s[j] * inv : 0.f;
        bf16 h, l; split1(v, h, l);
        oh[j] = h; ol[j] = l;
    }
}

__global__ void __launch_bounds__(256) mma_context_kernel() {
    int b = blockIdx.z, m0 = blockIdx.y * 128, n0 = blockIdx.x * 128;
    float acc[4][4][4] = {};
    mma_mainloop(g_whi + ((size_t)b*Nn + m0)*Nn, g_wlo + ((size_t)b*Nn + m0)*Nn, Nn,
                 g_vThi + ((size_t)b*Dd + n0)*Nn, g_vTlo + ((size_t)b*Dd + n0)*Nn, Nn,
                 (m0 + 128)/KS, acc);
    int tid = threadIdx.x, lane = tid & 31, wid = tid >> 5;
    int rb = (wid >> 2)*64 + (lane >> 2);
    int cb = (wid & 3)*32 + (lane & 3)*2;
#pragma unroll
    for (int am = 0; am < 4; am++)
#pragma unroll
    for (int h = 0; h < 2; h++) {
        int row = b*Nn + m0 + rb + am*16 + h*8;
        bf16* oh = g_ctxhi + (size_t)row*Dd + n0 + cb;
        bf16* ol = g_ctxlo + (size_t)row*Dd + n0 + cb;
#pragma unroll
        for (int bn = 0; bn < 4; bn++) {
            bf16 h0,l0,h1,l1;
            split1(acc[am][bn][2*h],   h0, l0);
            split1(acc[am][bn][2*h+1], h1, l1);
            *(uint32_t*)(oh + bn*8) = packbf(h0, h1);
            *(uint32_t*)(ol + bn*8) = packbf(l0, l1);
        }
    }
}

__global__ void __launch_bounds__(256) mma_final_kernel(const float* __restrict__ X,
                                                        const float* __restrict__ bo,
                                                        const float* __restrict__ Wfq,
                                                        const float* __restrict__ bfq,
                                                        float* __restrict__ out) {
    int m0 = blockIdx.y * 128, n0 = blockIdx.x * 128;
    float acc[4][4][4] = {};
    mma_mainloop(g_ctxhi + (size_t)m0*Dd, g_ctxlo + (size_t)m0*Dd, Dd,
                 g_wohi + (size_t)n0*Dd,  g_wolo + (size_t)n0*Dd,  Dd, Dd/KS, acc);
    int tid = threadIdx.x, lane = tid & 31, wid = tid >> 5;
    int rb = (wid >> 2)*64 + (lane >> 2);
    int cb = (wid & 3)*32 + (lane & 3)*2;
    float2 bo2[4], bfq2[4]; float4 wf[4];
#pragma unroll
    for (int bn = 0; bn < 4; bn++) {
        int c = n0 + cb + bn*8;
        bo2[bn]  = *(const float2*)(bo  + c);
        bfq2[bn] = *(const float2*)(bfq + c);
        wf[bn]   = *(const float4*)(Wfq + 2*c);
    }
#pragma unroll
    for (int am = 0; am < 4; am++)
#pragma unroll
    for (int h = 0; h < 2; h++) {
        int row = m0 + rb + am*16 + h*8;
        float2 qp = ((const float2*)g_qp)[row];
        float nrm = fmaxf(sqrtf(qp.x*qp.x + qp.y*qp.y), 1e-12f);
        float r0 = qp.x / nrm, r1 = qp.y / nrm;
        const float* hx = X + (size_t)row*Dd + n0 + cb;
        float* o = out + (size_t)row*Dd + n0 + cb;
#pragma unroll
        for (int bn = 0; bn < 4; bn++) {
            float2 hv = *(const float2*)(hx + bn*8);
            float v0 = hv.x + acc[am][bn][2*h]   + bo2[bn].x
                     + 0.1f*(r0*wf[bn].x + r1*wf[bn].y + bfq2[bn].x);
            float v1 = hv.y + acc[am][bn][2*h+1] + bo2[bn].y
                     + 0.1f*(r0*wf[bn].z + r1*wf[bn].w + bfq2[bn].y);
            *(float2*)(o + bn*8) = make_float2(v0, v1);
        }
    }
}

// ---------------- launch ----------------------------------------------------
extern "C" void kernel_launch(void* const* d_in, const int* in_sizes, int n_in,
                              void* d_out, int out_size) {
    const float* X   = (const float*)d_in[0];
    const float* Wq  = (const float*)d_in[1];
    const float* bq  = (const float*)d_in[2];
    const float* Wk  = (const float*)d_in[3];
    const float* bk  = (const float*)d_in[4];
    const float* Wv  = (const float*)d_in[5];
    const float* bv  = (const float*)d_in[6];
    const float* Wo  = (const float*)d_in[7];
    const float* bo  = (const float*)d_in[8];
    const float* Wtq = (const float*)d_in[9];
    const float* btq = (const float*)d_in[10];
    const float* Wfq = (const float*)d_in[11];
    const float* bfq = (const float*)d_in[12];
    float* out = (float*)d_out;

    static bool attr_done = false;
    if (!attr_done) {
        cudaFuncSetAttribute(mma_qkv_kernel,     cudaFuncAttributeMaxDynamicSharedMemorySize, SMEM_BYTES);
        cudaFuncSetAttribute(mma_scores_kernel,  cudaFuncAttributeMaxDynamicSharedMemorySize, SMEM_BYTES);
        cudaFuncSetAttribute(mma_context_kernel, cudaFuncAttributeMaxDynamicSharedMemorySize, SMEM_BYTES);
        cudaFuncSetAttribute(mma_final_kernel,   cudaFuncAttributeMaxDynamicSharedMemorySize, SMEM_BYTES);
        attr_done = true;
    }

    bf16 *xhi, *xlo, *wqh, *wql, *wkh, *wkl, *wvh, *wvl, *woh, *wol;
    cudaGetSymbolAddress((void**)&xhi, g_xhi);  cudaGetSymbolAddress((void**)&xlo, g_xlo);
    cudaGetSymbolAddress((void**)&wqh, g_wqhi); cudaGetSymbolAddress((void**)&wql, g_wqlo);
    cudaGetSymbolAddress((void**)&wkh, g_wkhi); cudaGetSymbolAddress((void**)&wkl, g_wklo);
    cudaGetSymbolAddress((void**)&wvh, g_wvhi); cudaGetSymbolAddress((void**)&wvl, g_wvlo);
    cudaGetSymbolAddress((void**)&woh, g_wohi); cudaGetSymbolAddress((void**)&wol, g_wolo);

    int n4x = (int)((size_t)Mm*Dd/4), n4w = Dd*Dd/4;
    cvt_kernel<<<(n4x + 255)/256, 256>>>(X,  xhi, xlo, n4x);
    cvt_kernel<<<(n4w + 255)/256, 256>>>(Wq, wqh, wql, n4w);
    cvt_kernel<<<(n4w + 255)/256, 256>>>(Wk, wkh, wkl, n4w);
    cvt_kernel<<<(n4w + 255)/256, 256>>>(Wv, wvh, wvl, n4w);
    cvt_kernel<<<(n4w + 255)/256, 256>>>(Wo, woh, wol, n4w);

    zero_stats_kernel<<<1, 32>>>();
    qp_kernel<<<Mm/8, 256>>>(X, Wtq, btq);
    stats_kernel<<<dim3(Nn, Bb), 256>>>();
    thr_kernel<<<1, 32>>>();

    mma_qkv_kernel<<<dim3(Dd/128, Mm/128, 3), 256, SMEM_BYTES>>>(bq, bk, bv);
    mma_scores_kernel<<<dim3(Nn/128, Nn/128, Bb), 256, SMEM_BYTES>>>();
    softmax_kernel<<<Mm, 256>>>();
    mma_context_kernel<<<dim3(Dd/128, Nn/128, Bb), 256, SMEM_BYTES>>>();
    mma_final_kernel<<<dim3(Dd/128, Mm/128), 256, SMEM_BYTES>>>(X, bo, Wfq, bfq, out);
}

// round 5
// speedup vs baseline: 2.2611x; 1.0017x over previous
#include <cuda_runtime.h>
#include <cuda_bf16.h>
#include <math.h>
#include <stdint.h>

#define Bb 4
#define Nn 2048
#define Dd 1024
#define Mm (Bb*Nn)

typedef __nv_bfloat16 bf16;

// ---------------- scratch (static device globals) ---------------------------
__device__ bf16 g_xhi[(size_t)Mm*Dd], g_xlo[(size_t)Mm*Dd];
__device__ bf16 g_wqhi[Dd*Dd], g_wqlo[Dd*Dd];
__device__ bf16 g_wkhi[Dd*Dd], g_wklo[Dd*Dd];
__device__ bf16 g_wvhi[Dd*Dd], g_wvlo[Dd*Dd];
__device__ bf16 g_wohi[Dd*Dd], g_wolo[Dd*Dd];
__device__ bf16 g_qhi[(size_t)Mm*Dd], g_qlo[(size_t)Mm*Dd];
__device__ bf16 g_khi[(size_t)Mm*Dd], g_klo[(size_t)Mm*Dd];
__device__ bf16 g_vhi[(size_t)Mm*Dd], g_vlo[(size_t)Mm*Dd];
__device__ bf16 g_vThi[(size_t)Bb*Dd*Nn], g_vTlo[(size_t)Bb*Dd*Nn];
__device__ bf16 g_ctxhi[(size_t)Mm*Dd], g_ctxlo[(size_t)Mm*Dd];
__device__ bf16 g_whi[(size_t)Bb*Nn*Nn], g_wlo[(size_t)Bb*Nn*Nn];
__device__ float  g_w [(size_t)Bb*Nn*Nn];
__device__ float  g_qp[Mm*2];
__device__ double g_s1[Bb], g_s2[Bb];
__device__ float  g_thr[Bb];

// ---------------- PTX helpers (sm_80-class only) ----------------------------
__device__ __forceinline__ uint32_t smem_u32(const void* p) {
    uint32_t a;
    asm("{ .reg .u64 t; cvta.to.shared.u64 t, %1; cvt.u32.u64 %0, t; }" : "=r"(a) : "l"(p));
    return a;
}
#define CP16(dst, src) \
    asm volatile("cp.async.cg.shared.global [%0], [%1], 16;" :: "r"(dst), "l"(src) : "memory")
#define CP_COMMIT() asm volatile("cp.async.commit_group;" ::: "memory")

#define LDM_X4(r, addr) \
    asm volatile("ldmatrix.sync.aligned.m8n8.x4.shared.b16 {%0,%1,%2,%3}, [%4];" \
        : "=r"((r)[0]), "=r"((r)[1]), "=r"((r)[2]), "=r"((r)[3]) : "r"(addr))

#define MMA_BF16(d, a, b) \
    asm volatile("mma.sync.aligned.m16n8k16.row.col.f32.bf16.bf16.f32 " \
        "{%0,%1,%2,%3}, {%4,%5,%6,%7}, {%8,%9}, {%0,%1,%2,%3};" \
        : "+f"((d)[0]), "+f"((d)[1]), "+f"((d)[2]), "+f"((d)[3]) \
        : "r"((a)[0]), "r"((a)[1]), "r"((a)[2]), "r"((a)[3]), "r"((b)[0]), "r"((b)[1]))

// ---------------- tiling constants ------------------------------------------
#define KS 32                 // k elements per stage
#define LDSB 80               // smem row stride in bytes
#define TILEB (128*LDSB)
#define STAGEB (4*TILEB)      // Ahi, Alo, Bhi, Blo
#define NSTAGE 4
#define SMEM_BYTES (NSTAGE*STAGEB)

// ---------------- stage load via cp.async -----------------------------------
__device__ __forceinline__ void load_stage(uint32_t sb,
        const bf16* __restrict__ Ahi, const bf16* __restrict__ Alo,
        const bf16* __restrict__ Bhi, const bf16* __restrict__ Blo,
        size_t lda, size_t ldb, int kt) {
    int tid = threadIdx.x;
    int r0 = tid >> 2, seg = tid & 3;
    size_t koff = (size_t)kt * KS + seg * 8;
#pragma unroll
    for (int p = 0; p < 2; p++) {
        int row = r0 + p * 64;
        uint32_t ds = sb + (uint32_t)row * LDSB + seg * 16;
        CP16(ds,           Ahi + (size_t)row * lda + koff);
        CP16(ds +   TILEB, Alo + (size_t)row * lda + koff);
        CP16(ds + 2*TILEB, Bhi + (size_t)row * ldb + koff);
        CP16(ds + 3*TILEB, Blo + (size_t)row * ldb + koff);
    }
    CP_COMMIT();
}

// ---------------- per-stage compute -----------------------------------------
__device__ __forceinline__ void compute_stage(uint32_t sb, int wm, int wn, int lane,
                                              float acc[4][4][4]) {
    int arow = lane & 15;
    int acol = (lane >> 4) << 3;
    int brow = (lane & 7) + ((lane >> 4) << 3);
    int bcol = ((lane >> 3) & 1) << 3;
#pragma unroll
    for (int ks = 0; ks < 2; ks++) {
        uint32_t ah[4][4], al[4][4];
#pragma unroll
        for (int am = 0; am < 4; am++) {
            uint32_t ad = sb + (uint32_t)(wm*64 + am*16 + arow) * LDSB + (ks*16 + acol) * 2;
            LDM_X4(ah[am], ad);
            LDM_X4(al[am], ad + TILEB);
        }
        uint32_t bh[4][2], bl[4][2];
#pragma unroll
        for (int bp = 0; bp < 2; bp++) {
            uint32_t bd = sb + 2*TILEB + (uint32_t)(wn*32 + bp*16 + brow) * LDSB
                        + (ks*16 + bcol) * 2;
            uint32_t t[4];
            LDM_X4(t, bd);
            bh[2*bp][0] = t[0]; bh[2*bp][1] = t[1];
            bh[2*bp+1][0] = t[2]; bh[2*bp+1][1] = t[3];
            LDM_X4(t, bd + TILEB);
            bl[2*bp][0] = t[0]; bl[2*bp][1] = t[1];
            bl[2*bp+1][0] = t[2]; bl[2*bp+1][1] = t[3];
        }
#pragma unroll
        for (int am = 0; am < 4; am++)
#pragma unroll
            for (int bn = 0; bn < 4; bn++) {
                MMA_BF16(acc[am][bn], ah[am], bh[bn]);
                MMA_BF16(acc[am][bn], ah[am], bl[bn]);
                MMA_BF16(acc[am][bn], al[am], bh[bn]);
            }
    }
}

// D[128,128] fp32 = A[128,K] * B[128,K]^T, 4-stage cp.async pipeline
__device__ __forceinline__ void mma_mainloop(
        const bf16* __restrict__ Ahi, const bf16* __restrict__ Alo, size_t lda,
        const bf16* __restrict__ Bhi, const bf16* __restrict__ Blo, size_t ldb,
        int kIters, float acc[4][4][4]) {
    extern __shared__ __align__(16) char smem[];
    uint32_t sb = smem_u32(smem);
    int tid = threadIdx.x, lane = tid & 31, wid = tid >> 5;
    int wm = wid >> 2, wn = wid & 3;
    load_stage(sb, Ahi, Alo, Bhi, Blo, lda, ldb, 0);
    if (kIters > 1) load_stage(sb + STAGEB,   Ahi, Alo, Bhi, Blo, lda, ldb, 1);
    if (kIters > 2) load_stage(sb + 2*STAGEB, Ahi, Alo, Bhi, Blo, lda, ldb, 2);
    for (int kt = 0; kt < kIters; kt++) {
        if (kt + 2 < kIters)      asm volatile("cp.async.wait_group 2;" ::: "memory");
        else if (kt + 1 < kIters) asm volatile("cp.async.wait_group 1;" ::: "memory");
        else                      asm volatile("cp.async.wait_group 0;" ::: "memory");
        __syncthreads();
        if (kt + 3 < kIters)
            load_stage(sb + (uint32_t)((kt+3) & 3) * STAGEB,
                       Ahi, Alo, Bhi, Blo, lda, ldb, kt + 3);
        compute_stage(sb + (uint32_t)(kt & 3) * STAGEB, wm, wn, lane, acc);
    }
}

__device__ __forceinline__ uint32_t packbf(bf16 a, bf16 b) {
    union { __nv_bfloat162 h; uint32_t u; } c;
    c.h = __halves2bfloat162(a, b);
    return c.u;
}
__device__ __forceinline__ void split1(float v, bf16& h, bf16& l) {
    h = __float2bfloat16(v);
    l = __float2bfloat16(v - __bfloat162float(h));
}

// ---------------- conversion kernel -----------------------------------------
__global__ void __launch_bounds__(256) cvt_kernel(const float* __restrict__ src,
                                                  bf16* __restrict__ hi,
                                                  bf16* __restrict__ lo, int n4) {
    int i = blockIdx.x * 256 + threadIdx.x;
    if (i >= n4) return;
    float4 v = ((const float4*)src)[i];
    bf16 h0,l0,h1,l1,h2,l2,h3,l3;
    split1(v.x,h0,l0); split1(v.y,h1,l1); split1(v.z,h2,l2); split1(v.w,h3,l3);
    *(uint2*)(hi + 4*(size_t)i) = make_uint2(packbf(h0,h1), packbf(h2,h3));
    *(uint2*)(lo + 4*(size_t)i) = make_uint2(packbf(l0,l1), packbf(l2,l3));
}

// ---------------- small SIMT kernels ----------------------------------------
__global__ void zero_stats_kernel() {
    if (threadIdx.x < Bb) { g_s1[threadIdx.x] = 0.0; g_s2[threadIdx.x] = 0.0; }
}
__global__ void __launch_bounds__(256) qp_kernel(const float* __restrict__ X,
                                                 const float* __restrict__ Wtq,
                                                 const float* __restrict__ btq) {
    int warp = threadIdx.x >> 5, lane = threadIdx.x & 31;
    int row = blockIdx.x * 8 + warp;
    const float* x = X + (size_t)row * Dd;
    float s0 = 0.f, s1 = 0.f;
    for (int k = lane * 4; k < Dd; k += 128) {
        float4 xv = *(const float4*)(x + k);
        float4 w0 = *(const float4*)(Wtq + k);
        float4 w1 = *(const float4*)(Wtq + Dd + k);
        s0 += xv.x*w0.x + xv.y*w0.y + xv.z*w0.z + xv.w*w0.w;
        s1 += xv.x*w1.x + xv.y*w1.y + xv.z*w1.z + xv.w*w1.w;
    }
#pragma unroll
    for (int o = 16; o; o >>= 1) {
        s0 += __shfl_xor_sync(0xffffffffu, s0, o);
        s1 += __shfl_xor_sync(0xffffffffu, s1, o);
    }
    if (lane == 0) { g_qp[row*2+0] = s0 + btq[0]; g_qp[row*2+1] = s1 + btq[1]; }
}
__global__ void __launch_bounds__(256) stats_kernel() {
    __shared__ float r1[256], r2[256];
    int b = blockIdx.y, i = blockIdx.x, tid = threadIdx.x;
    const float2* qp2 = (const float2*)g_qp + (size_t)b * Nn;
    float2 qi = qp2[i];
    float s1 = 0.f, s2 = 0.f;
    for (int j = tid; j < Nn; j += 256) {
        float2 qj = qp2[j];
        float dx = qi.x - qj.x, dy = qi.y - qj.y;
        float d = dx*dx + dy*dy;
        s1 += d; s2 += d*d;
    }
    r1[tid] = s1; r2[tid] = s2; __syncthreads();
    for (int o = 128; o; o >>= 1) {
        if (tid < o) { r1[tid] += r1[tid+o]; r2[tid] += r2[tid+o]; }
        __syncthreads();
    }
    if (tid == 0) { atomicAdd(&g_s1[b], (double)r1[0]); atomicAdd(&g_s2[b], (double)r2[0]); }
}
__global__ void thr_kernel() {
    int b = threadIdx.x;
    if (b < Bb) {
        double M = (double)Nn * (double)Nn;
        double mean = g_s1[b] / M;
        double var = (g_s2[b] - g_s1[b]*g_s1[b]/M) / (M - 1.0);
        if (var < 0.0) var = 0.0;
        g_thr[b] = (float)(mean + 1.25 * sqrt(var));
    }
}

// ---------------- v transpose: [b, tok, d] -> [b, d, tok], hi & lo ----------
__global__ void __launch_bounds__(256) vtrans_kernel() {
    __shared__ bf16 t[64][66];
    int b = blockIdx.z >> 1;
    const bf16* src = (blockIdx.z & 1) ? g_vlo : g_vhi;
    bf16* dst       = (blockIdx.z & 1) ? g_vTlo : g_vThi;
    int tok0 = blockIdx.x * 64, d0 = blockIdx.y * 64;
    int tid = threadIdx.x, r = tid >> 2, seg = tid & 3;
    const bf16* sp = src + ((size_t)(b*Nn + tok0 + r)) * Dd + d0;
#pragma unroll
    for (int p = 0; p < 2; p++) {
        int c0 = (seg + 4*p) * 8;
        union { uint4 u; bf16 h[8]; } v;
        v.u = *(const uint4*)(sp + c0);
#pragma unroll
        for (int e = 0; e < 8; e++) t[r][c0 + e] = v.h[e];
    }
    __syncthreads();
    bf16* dp = dst + (size_t)b*Dd*Nn + (size_t)(d0 + r)*Nn + tok0;
#pragma unroll
    for (int p = 0; p < 2; p++) {
        int c0 = (seg + 4*p) * 8;
        union { uint4 u; bf16 h[8]; } v;
#pragma unroll
        for (int e = 0; e < 8; e++) v.h[e] = t[c0 + e][r];
        *(uint4*)(dp + c0) = v.u;
    }
}

// ---------------- GEMM kernels (warp MMA) ------------------------------------
__global__ void __launch_bounds__(256) mma_qkv_kernel(const float* __restrict__ bq,
                                                      const float* __restrict__ bk,
                                                      const float* __restrict__ bv) {
    int z = blockIdx.z;
    const bf16 *Whi, *Wlo; const float* bias; bf16 *OH, *OL;
    if (z == 0)      { Whi = g_wqhi; Wlo = g_wqlo; bias = bq; OH = g_qhi; OL = g_qlo; }
    else if (z == 1) { Whi = g_wkhi; Wlo = g_wklo; bias = bk; OH = g_khi; OL = g_klo; }
    else             { Whi = g_wvhi; Wlo = g_wvlo; bias = bv; OH = g_vhi; OL = g_vlo; }
    int m0 = blockIdx.y * 128, n0 = blockIdx.x * 128;
    float acc[4][4][4] = {};
    mma_mainloop(g_xhi + (size_t)m0*Dd, g_xlo + (size_t)m0*Dd, Dd,
                 Whi + (size_t)n0*Dd,  Wlo + (size_t)n0*Dd,  Dd, Dd/KS, acc);
    int tid = threadIdx.x, lane = tid & 31, wid = tid >> 5;
    int rb = (wid >> 2)*64 + (lane >> 2);
    int cb = (wid & 3)*32 + (lane & 3)*2;
    float2 b2[4];
#pragma unroll
    for (int bn = 0; bn < 4; bn++) b2[bn] = *(const float2*)(bias + n0 + cb + bn*8);
#pragma unroll
    for (int am = 0; am < 4; am++)
#pragma unroll
    for (int h = 0; h < 2; h++) {
        int row = m0 + rb + am*16 + h*8;
        bf16* oh = OH + (size_t)row*Dd + n0 + cb;
        bf16* ol = OL + (size_t)row*Dd + n0 + cb;
#pragma unroll
        for (int bn = 0; bn < 4; bn++) {
            bf16 h0,l0,h1,l1;
            split1(acc[am][bn][2*h]   + b2[bn].x, h0, l0);
            split1(acc[am][bn][2*h+1] + b2[bn].y, h1, l1);
            *(uint32_t*)(oh + bn*8) = packbf(h0, h1);
            *(uint32_t*)(ol + bn*8) = packbf(l0, l1);
        }
    }
}

__global__ void __launch_bounds__(256) mma_scores_kernel() {
    int b = blockIdx.z;
    // triangular decode: blockIdx.x in [0, 136) -> (it >= jt)
    int t = blockIdx.x;
    int it = (int)((sqrtf(8.f*t + 1.f) - 1.f) * 0.5f);
    while ((it + 1)*(it + 2)/2 <= t) it++;
    while (it*(it + 1)/2 > t) it--;
    int jt = t - it*(it + 1)/2;
    int i0 = it * 128, j0 = jt * 128;
    float acc[4][4][4] = {};
    mma_mainloop(g_qhi + ((size_t)b*Nn + i0)*Dd, g_qlo + ((size_t)b*Nn + i0)*Dd, Dd,
                 g_khi + ((size_t)b*Nn + j0)*Dd, g_klo + ((size_t)b*Nn + j0)*Dd, Dd,
                 Dd/KS, acc);
    int tid = threadIdx.x, lane = tid & 31, wid = tid >> 5;
    int rb = (wid >> 2)*64 + (lane >> 2);
    int cb = (wid & 3)*32 + (lane & 3)*2;
    float thr = g_thr[b];
    const float2* qp2 = (const float2*)g_qp + (size_t)b * Nn;
    const float NEG = __int_as_float(0xff800000);
    float2 qj0[4], qj1[4];
#pragma unroll
    for (int bn = 0; bn < 4; bn++) {
        qj0[bn] = qp2[j0 + cb + bn*8];
        qj1[bn] = qp2[j0 + cb + bn*8 + 1];
    }
#pragma unroll
    for (int am = 0; am < 4; am++)
#pragma unroll
    for (int h = 0; h < 2; h++) {
        int gi = i0 + rb + am*16 + h*8;
        float2 qi = qp2[gi];
        float* o = g_w + (size_t)b*Nn*Nn + (size_t)gi*Nn + j0 + cb;
#pragma unroll
        for (int bn = 0; bn < 4; bn++) {
            float r[2];
#pragma unroll
            for (int q = 0; q < 2; q++) {
                int gj = j0 + cb + bn*8 + q;
                float2 qj = q ? qj1[bn] : qj0[bn];
                float dx = qi.x - qj.x, dy = qi.y - qj.y;
                float ds = dx*dx + dy*dy;
                bool ok = (gj <= gi) && (ds <= thr);
                if (ok && dx < 0.f && fabsf(dy) < 1e-3f * (-dx)) {
                    float bias = 0.5f * (1.f + cosf(atan2f(dy, dx)));
                    ok = (bias != 0.f);
                }
                r[q] = ok ? acc[am][bn][2*h+q] * 0.03125f : NEG;
            }
            *(float2*)(o + bn*8) = make_float2(r[0], r[1]);
        }
    }
}

// single-pass register softmax; emits hi/lo bf16 only
__global__ void __launch_bounds__(256) softmax_kernel() {
    __shared__ float red[256];
    int row = blockIdx.x;
    int b = row >> 11, i = row & (Nn - 1);
    const float* s = g_w + (size_t)b*Nn*Nn + (size_t)i*Nn;
    bf16* oh = g_whi + (size_t)b*Nn*Nn + (size_t)i*Nn;
    bf16* ol = g_wlo + (size_t)b*Nn*Nn + (size_t)i*Nn;
    int tid = threadIdx.x;
    int jb = tid * 8;
    const float NEG = __int_as_float(0xff800000);
    float v[8];
#pragma unroll
    for (int k = 0; k < 8; k++) {
        int j = jb + k;
        v[k] = (j <= i) ? s[j] : NEG;
    }
    float mx = v[0];
#pragma unroll
    for (int k = 1; k < 8; k++) mx = fmaxf(mx, v[k]);
    red[tid] = mx; __syncthreads();
    for (int o = 128; o; o >>= 1) {
        if (tid < o) red[tid] = fmaxf(red[tid], red[tid+o]);
        __syncthreads();
    }
    mx = red[0]; __syncthreads();
    float sum = 0.f;
#pragma unroll
    for (int k = 0; k < 8; k++) {
        int j = jb + k;
        float e = (j <= i) ? expf(v[k] - mx) : 0.f;
        v[k] = e; sum += e;
    }
    red[tid] = sum; __syncthreads();
    for (int o = 128; o; o >>= 1) {
        if (tid < o) red[tid] += red[tid+o];
        __syncthreads();
    }
    float inv = 1.f / red[0];
    union { uint4 u; bf16 hh[8]; } ph, pl;
#pragma unroll
    for (int k = 0; k < 8; k++) {
        bf16 h, l; split1(v[k] * inv, h, l);
        ph.hh[k] = h; pl.hh[k] = l;
    }
    *(uint4*)(oh + jb) = ph.u;
    *(uint4*)(ol + jb) = pl.u;
}

__global__ void __launch_bounds__(256) mma_context_kernel() {
    int b = blockIdx.z, m0 = blockIdx.y * 128, n0 = blockIdx.x * 128;
    float acc[4][4][4] = {};
    mma_mainloop(g_whi + ((size_t)b*Nn + m0)*Nn, g_wlo + ((size_t)b*Nn + m0)*Nn, Nn,
                 g_vThi + ((size_t)b*Dd + n0)*Nn, g_vTlo + ((size_t)b*Dd + n0)*Nn, Nn,
                 (m0 + 128)/KS, acc);
    int tid = threadIdx.x, lane = tid & 31, wid = tid >> 5;
    int rb = (wid >> 2)*64 + (lane >> 2);
    int cb = (wid & 3)*32 + (lane & 3)*2;
#pragma unroll
    for (int am = 0; am < 4; am++)
#pragma unroll
    for (int h = 0; h < 2; h++) {
        int row = b*Nn + m0 + rb + am*16 + h*8;
        bf16* oh = g_ctxhi + (size_t)row*Dd + n0 + cb;
        bf16* ol = g_ctxlo + (size_t)row*Dd + n0 + cb;
#pragma unroll
        for (int bn = 0; bn < 4; bn++) {
            bf16 h0,l0,h1,l1;
            split1(acc[am][bn][2*h],   h0, l0);
            split1(acc[am][bn][2*h+1], h1, l1);
            *(uint32_t*)(oh + bn*8) = packbf(h0, h1);
            *(uint32_t*)(ol + bn*8) = packbf(l0, l1);
        }
    }
}

__global__ void __launch_bounds__(256) mma_final_kernel(const float* __restrict__ X,
                                                        const float* __restrict__ bo,
                                                        const float* __restrict__ Wfq,
                                                        const float* __restrict__ bfq,
                                                        float* __restrict__ out) {
    int m0 = blockIdx.y * 128, n0 = blockIdx.x * 128;
    float acc[4][4][4] = {};
    mma_mainloop(g_ctxhi + (size_t)m0*Dd, g_ctxlo + (size_t)m0*Dd, Dd,
                 g_wohi + (size_t)n0*Dd,  g_wolo + (size_t)n0*Dd,  Dd, Dd/KS, acc);
    int tid = threadIdx.x, lane = tid & 31, wid = tid >> 5;
    int rb = (wid >> 2)*64 + (lane >> 2);
    int cb = (wid & 3)*32 + (lane & 3)*2;
    float2 bo2[4], bfq2[4]; float4 wf[4];
#pragma unroll
    for (int bn = 0; bn < 4; bn++) {
        int c = n0 + cb + bn*8;
        bo2[bn]  = *(const float2*)(bo  + c);
        bfq2[bn] = *(const float2*)(bfq + c);
        wf[bn]   = *(const float4*)(Wfq + 2*c);
    }
#pragma unroll
    for (int am = 0; am < 4; am++)
#pragma unroll
    for (int h = 0; h < 2; h++) {
        int row = m0 + rb + am*16 + h*8;
        float2 qp = ((const float2*)g_qp)[row];
        float nrm = fmaxf(sqrtf(qp.x*qp.x + qp.y*qp.y), 1e-12f);
        float r0 = qp.x / nrm, r1 = qp.y / nrm;
        const float* hx = X + (size_t)row*Dd + n0 + cb;
        float* o = out + (size_t)row*Dd + n0 + cb;
#pragma unroll
        for (int bn = 0; bn < 4; bn++) {
            float2 hv = *(const float2*)(hx + bn*8);
            float v0 = hv.x + acc[am][bn][2*h]   + bo2[bn].x
                     + 0.1f*(r0*wf[bn].x + r1*wf[bn].y + bfq2[bn].x);
            float v1 = hv.y + acc[am][bn][2*h+1] + bo2[bn].y
                     + 0.1f*(r0*wf[bn].z + r1*wf[bn].w + bfq2[bn].y);
            *(float2*)(o + bn*8) = make_float2(v0, v1);
        }
    }
}

// ---------------- launch ----------------------------------------------------
extern "C" void kernel_launch(void* const* d_in, const int* in_sizes, int n_in,
                              void* d_out, int out_size) {
    const float* X   = (const float*)d_in[0];
    const float* Wq  = (const float*)d_in[1];
    const float* bq  = (const float*)d_in[2];
    const float* Wk  = (const float*)d_in[3];
    const float* bk  = (const float*)d_in[4];
    const float* Wv  = (const float*)d_in[5];
    const float* bv  = (const float*)d_in[6];
    const float* Wo  = (const float*)d_in[7];
    const float* bo  = (const float*)d_in[8];
    const float* Wtq = (const float*)d_in[9];
    const float* btq = (const float*)d_in[10];
    const float* Wfq = (const float*)d_in[11];
    const float* bfq = (const float*)d_in[12];
    float* out = (float*)d_out;

    static bool attr_done = false;
    if (!attr_done) {
        cudaFuncSetAttribute(mma_qkv_kernel,     cudaFuncAttributeMaxDynamicSharedMemorySize, SMEM_BYTES);
        cudaFuncSetAttribute(mma_scores_kernel,  cudaFuncAttributeMaxDynamicSharedMemorySize, SMEM_BYTES);
        cudaFuncSetAttribute(mma_context_kernel, cudaFuncAttributeMaxDynamicSharedMemorySize, SMEM_BYTES);
        cudaFuncSetAttribute(mma_final_kernel,   cudaFuncAttributeMaxDynamicSharedMemorySize, SMEM_BYTES);
        attr_done = true;
    }

    bf16 *xhi, *xlo, *wqh, *wql, *wkh, *wkl, *wvh, *wvl, *woh, *wol;
    cudaGetSymbolAddress((void**)&xhi, g_xhi);  cudaGetSymbolAddress((void**)&xlo, g_xlo);
    cudaGetSymbolAddress((void**)&wqh, g_wqhi); cudaGetSymbolAddress((void**)&wql, g_wqlo);
    cudaGetSymbolAddress((void**)&wkh, g_wkhi); cudaGetSymbolAddress((void**)&wkl, g_wklo);
    cudaGetSymbolAddress((void**)&wvh, g_wvhi); cudaGetSymbolAddress((void**)&wvl, g_wvlo);
    cudaGetSymbolAddress((void**)&woh, g_wohi); cudaGetSymbolAddress((void**)&wol, g_wolo);

    int n4x = (int)((size_t)Mm*Dd/4), n4w = Dd*Dd/4;
    cvt_kernel<<<(n4x + 255)/256, 256>>>(X,  xhi, xlo, n4x);
    cvt_kernel<<<(n4w + 255)/256, 256>>>(Wq, wqh, wql, n4w);
    cvt_kernel<<<(n4w + 255)/256, 256>>>(Wk, wkh, wkl, n4w);
    cvt_kernel<<<(n4w + 255)/256, 256>>>(Wv, wvh, wvl, n4w);
    cvt_kernel<<<(n4w + 255)/256, 256>>>(Wo, woh, wol, n4w);

    zero_stats_kernel<<<1, 32>>>();
    qp_kernel<<<Mm/8, 256>>>(X, Wtq, btq);
    stats_kernel<<<dim3(Nn, Bb), 256>>>();
    thr_kernel<<<1, 32>>>();

    mma_qkv_kernel<<<dim3(Dd/128, Mm/128, 3), 256, SMEM_BYTES>>>(bq, bk, bv);
    vtrans_kernel<<<dim3(Nn/64, Dd/64, Bb*2), 256>>>();
    mma_scores_kernel<<<dim3(136, 1, Bb), 256, SMEM_BYTES>>>();
    softmax_kernel<<<Mm, 256>>>();
    mma_context_kernel<<<dim3(Dd/128, Nn/128, Bb), 256, SMEM_BYTES>>>();
    mma_final_kernel<<<dim3(Dd/128, Mm/128), 256, SMEM_BYTES>>>(X, bo, Wfq, bfq, out);
}

// round 6
// speedup vs baseline: 3.0421x; 1.3454x over previous
#include <cuda_runtime.h>
#include <cuda_bf16.h>
#include <math.h>
#include <stdint.h>

#define Bb 4
#define Nn 2048
#define Dd 1024
#define Mm (Bb*Nn)

typedef __nv_bfloat16 bf16;

// ---------------- scratch (static device globals) ---------------------------
__device__ bf16 g_xhi[(size_t)Mm*Dd], g_xlo[(size_t)Mm*Dd];
__device__ bf16 g_wqhi[Dd*Dd], g_wqlo[Dd*Dd];
__device__ bf16 g_wkhi[Dd*Dd], g_wklo[Dd*Dd];
__device__ bf16 g_wvhi[Dd*Dd], g_wvlo[Dd*Dd];
__device__ bf16 g_wohi[Dd*Dd], g_wolo[Dd*Dd];
__device__ bf16 g_qhi[(size_t)Mm*Dd], g_qlo[(size_t)Mm*Dd];
__device__ bf16 g_khi[(size_t)Mm*Dd], g_klo[(size_t)Mm*Dd];
__device__ bf16 g_vhi[(size_t)Mm*Dd], g_vlo[(size_t)Mm*Dd];
__device__ bf16 g_vThi[(size_t)Bb*Dd*Nn], g_vTlo[(size_t)Bb*Dd*Nn];
__device__ bf16 g_ctxhi[(size_t)Mm*Dd], g_ctxlo[(size_t)Mm*Dd];
__device__ bf16 g_whi[(size_t)Bb*Nn*Nn], g_wlo[(size_t)Bb*Nn*Nn];
__device__ float  g_w [(size_t)Bb*Nn*Nn];
__device__ float  g_qp[Mm*2];
__device__ double g_s1[Bb], g_s2[Bb];
__device__ float  g_thr[Bb];

// ---------------- PTX helpers (sm_80-class only) ----------------------------
__device__ __forceinline__ uint32_t smem_u32(const void* p) {
    uint32_t a;
    asm("{ .reg .u64 t; cvta.to.shared.u64 t, %1; cvt.u32.u64 %0, t; }" : "=r"(a) : "l"(p));
    return a;
}
#define CP16(dst, src) \
    asm volatile("cp.async.cg.shared.global [%0], [%1], 16;" :: "r"(dst), "l"(src) : "memory")
#define CP_COMMIT() asm volatile("cp.async.commit_group;" ::: "memory")

#define LDM_X4(r, addr) \
    asm volatile("ldmatrix.sync.aligned.m8n8.x4.shared.b16 {%0,%1,%2,%3}, [%4];" \
        : "=r"((r)[0]), "=r"((r)[1]), "=r"((r)[2]), "=r"((r)[3]) : "r"(addr))

#define MMA_BF16(d, a, b) \
    asm volatile("mma.sync.aligned.m16n8k16.row.col.f32.bf16.bf16.f32 " \
        "{%0,%1,%2,%3}, {%4,%5,%6,%7}, {%8,%9}, {%0,%1,%2,%3};" \
        : "+f"((d)[0]), "+f"((d)[1]), "+f"((d)[2]), "+f"((d)[3]) \
        : "r"((a)[0]), "r"((a)[1]), "r"((a)[2]), "r"((a)[3]), "r"((b)[0]), "r"((b)[1]))

// ---------------- tiling constants ------------------------------------------
#define KS 32                 // k elements per stage
#define LDSB 64               // smem row stride (64 B, XOR-swizzled chunks)
#define TILEB (128*LDSB)      // 8192 B
#define STAGEB (4*TILEB)      // 32768 B: Ahi, Alo, Bhi, Blo
#define NSTAGE 3
#define SMEM_BYTES (NSTAGE*STAGEB)   // 98304 -> 2 CTAs/SM

// swizzle: 16B-chunk c within 64B row r
__device__ __forceinline__ uint32_t swz(uint32_t r, uint32_t c) {
    return (uint32_t)r * LDSB + ((c ^ ((r + (r >> 2)) & 3)) << 4);
}

// ---------------- stage load via cp.async -----------------------------------
__device__ __forceinline__ void load_stage(uint32_t sb,
        const bf16* __restrict__ Ahi, const bf16* __restrict__ Alo,
        const bf16* __restrict__ Bhi, const bf16* __restrict__ Blo,
        size_t lda, size_t ldb, int kt) {
    int tid = threadIdx.x;
    int r0 = tid >> 2, seg = tid & 3;
    size_t koff = (size_t)kt * KS + seg * 8;
#pragma unroll
    for (int p = 0; p < 2; p++) {
        int row = r0 + p * 64;
        uint32_t ds = sb + swz((uint32_t)row, (uint32_t)seg);
        CP16(ds,           Ahi + (size_t)row * lda + koff);
        CP16(ds +   TILEB, Alo + (size_t)row * lda + koff);
        CP16(ds + 2*TILEB, Bhi + (size_t)row * ldb + koff);
        CP16(ds + 3*TILEB, Blo + (size_t)row * ldb + koff);
    }
    CP_COMMIT();
}

// ---------------- per-stage compute -----------------------------------------
__device__ __forceinline__ void compute_stage(uint32_t sb, int wm, int wn, int lane,
                                              float acc[4][4][4]) {
    int arow = lane & 15;
    int acol = (lane >> 4) << 3;                  // 0 or 8 (bf16 cols)
    int brow = (lane & 7) + ((lane >> 4) << 3);
    int bcol = ((lane >> 3) & 1) << 3;
#pragma unroll
    for (int ks = 0; ks < 2; ks++) {
        uint32_t ah[4][4], al[4][4];
        uint32_t ca = (uint32_t)(2*ks + (acol >> 3));
#pragma unroll
        for (int am = 0; am < 4; am++) {
            uint32_t ad = sb + swz((uint32_t)(wm*64 + am*16 + arow), ca);
            LDM_X4(ah[am], ad);
            LDM_X4(al[am], ad + TILEB);
        }
        uint32_t bh[4][2], bl[4][2];
        uint32_t cbk = (uint32_t)(2*ks + (bcol >> 3));
#pragma unroll
        for (int bp = 0; bp < 2; bp++) {
            uint32_t bd = sb + 2*TILEB + swz((uint32_t)(wn*32 + bp*16 + brow), cbk);
            uint32_t t[4];
            LDM_X4(t, bd);
            bh[2*bp][0] = t[0]; bh[2*bp][1] = t[1];
            bh[2*bp+1][0] = t[2]; bh[2*bp+1][1] = t[3];
            LDM_X4(t, bd + TILEB);
            bl[2*bp][0] = t[0]; bl[2*bp][1] = t[1];
            bl[2*bp+1][0] = t[2]; bl[2*bp+1][1] = t[3];
        }
#pragma unroll
        for (int am = 0; am < 4; am++)
#pragma unroll
            for (int bn = 0; bn < 4; bn++) {
                MMA_BF16(acc[am][bn], ah[am], bh[bn]);
                MMA_BF16(acc[am][bn], ah[am], bl[bn]);
                MMA_BF16(acc[am][bn], al[am], bh[bn]);
            }
    }
}

// D[128,128] fp32 = A[128,K] * B[128,K]^T, 3-stage cp.async pipeline
__device__ __forceinline__ void mma_mainloop(
        const bf16* __restrict__ Ahi, const bf16* __restrict__ Alo, size_t lda,
        const bf16* __restrict__ Bhi, const bf16* __restrict__ Blo, size_t ldb,
        int kIters, float acc[4][4][4]) {
    extern __shared__ __align__(16) char smem[];
    uint32_t sb = smem_u32(smem);
    int tid = threadIdx.x, lane = tid & 31, wid = tid >> 5;
    int wm = wid >> 2, wn = wid & 3;
    load_stage(sb, Ahi, Alo, Bhi, Blo, lda, ldb, 0);
    if (kIters > 1) load_stage(sb + STAGEB, Ahi, Alo, Bhi, Blo, lda, ldb, 1);
    int slot = 0;
    for (int kt = 0; kt < kIters; kt++) {
        if (kt + 1 < kIters) asm volatile("cp.async.wait_group 1;" ::: "memory");
        else                 asm volatile("cp.async.wait_group 0;" ::: "memory");
        __syncthreads();
        if (kt + 2 < kIters) {
            int ns = slot + 2; if (ns >= NSTAGE) ns -= NSTAGE;
            load_stage(sb + (uint32_t)ns * STAGEB, Ahi, Alo, Bhi, Blo, lda, ldb, kt + 2);
        }
        compute_stage(sb + (uint32_t)slot * STAGEB, wm, wn, lane, acc);
        if (++slot == NSTAGE) slot = 0;
    }
}

__device__ __forceinline__ uint32_t packbf(bf16 a, bf16 b) {
    union { __nv_bfloat162 h; uint32_t u; } c;
    c.h = __halves2bfloat162(a, b);
    return c.u;
}
__device__ __forceinline__ void split1(float v, bf16& h, bf16& l) {
    h = __float2bfloat16(v);
    l = __float2bfloat16(v - __bfloat162float(h));
}

// ---------------- conversion kernel -----------------------------------------
__global__ void __launch_bounds__(256) cvt_kernel(const float* __restrict__ src,
                                                  bf16* __restrict__ hi,
                                                  bf16* __restrict__ lo, int n4) {
    int i = blockIdx.x * 256 + threadIdx.x;
    if (i >= n4) return;
    float4 v = ((const float4*)src)[i];
    bf16 h0,l0,h1,l1,h2,l2,h3,l3;
    split1(v.x,h0,l0); split1(v.y,h1,l1); split1(v.z,h2,l2); split1(v.w,h3,l3);
    *(uint2*)(hi + 4*(size_t)i) = make_uint2(packbf(h0,h1), packbf(h2,h3));
    *(uint2*)(lo + 4*(size_t)i) = make_uint2(packbf(l0,l1), packbf(l2,l3));
}

// ---------------- small SIMT kernels ----------------------------------------
__global__ void zero_stats_kernel() {
    if (threadIdx.x < Bb) { g_s1[threadIdx.x] = 0.0; g_s2[threadIdx.x] = 0.0; }
}
__global__ void __launch_bounds__(256) qp_kernel(const float* __restrict__ X,
                                                 const float* __restrict__ Wtq,
                                                 const float* __restrict__ btq) {
    int warp = threadIdx.x >> 5, lane = threadIdx.x & 31;
    int row = blockIdx.x * 8 + warp;
    const float* x = X + (size_t)row * Dd;
    float s0 = 0.f, s1 = 0.f;
    for (int k = lane * 4; k < Dd; k += 128) {
        float4 xv = *(const float4*)(x + k);
        float4 w0 = *(const float4*)(Wtq + k);
        float4 w1 = *(const float4*)(Wtq + Dd + k);
        s0 += xv.x*w0.x + xv.y*w0.y + xv.z*w0.z + xv.w*w0.w;
        s1 += xv.x*w1.x + xv.y*w1.y + xv.z*w1.z + xv.w*w1.w;
    }
#pragma unroll
    for (int o = 16; o; o >>= 1) {
        s0 += __shfl_xor_sync(0xffffffffu, s0, o);
        s1 += __shfl_xor_sync(0xffffffffu, s1, o);
    }
    if (lane == 0) { g_qp[row*2+0] = s0 + btq[0]; g_qp[row*2+1] = s1 + btq[1]; }
}
__global__ void __launch_bounds__(256) stats_kernel() {
    __shared__ float r1[256], r2[256];
    int b = blockIdx.y, i = blockIdx.x, tid = threadIdx.x;
    const float2* qp2 = (const float2*)g_qp + (size_t)b * Nn;
    float2 qi = qp2[i];
    float s1 = 0.f, s2 = 0.f;
    for (int j = tid; j < Nn; j += 256) {
        float2 qj = qp2[j];
        float dx = qi.x - qj.x, dy = qi.y - qj.y;
        float d = dx*dx + dy*dy;
        s1 += d; s2 += d*d;
    }
    r1[tid] = s1; r2[tid] = s2; __syncthreads();
    for (int o = 128; o; o >>= 1) {
        if (tid < o) { r1[tid] += r1[tid+o]; r2[tid] += r2[tid+o]; }
        __syncthreads();
    }
    if (tid == 0) { atomicAdd(&g_s1[b], (double)r1[0]); atomicAdd(&g_s2[b], (double)r2[0]); }
}
__global__ void thr_kernel() {
    int b = threadIdx.x;
    if (b < Bb) {
        double M = (double)Nn * (double)Nn;
        double mean = g_s1[b] / M;
        double var = (g_s2[b] - g_s1[b]*g_s1[b]/M) / (M - 1.0);
        if (var < 0.0) var = 0.0;
        g_thr[b] = (float)(mean + 1.25 * sqrt(var));
    }
}

// ---------------- v transpose: [b, tok, d] -> [b, d, tok], hi & lo ----------
__global__ void __launch_bounds__(256) vtrans_kernel() {
    __shared__ bf16 t[64][66];
    int b = blockIdx.z >> 1;
    const bf16* src = (blockIdx.z & 1) ? g_vlo : g_vhi;
    bf16* dst       = (blockIdx.z & 1) ? g_vTlo : g_vThi;
    int tok0 = blockIdx.x * 64, d0 = blockIdx.y * 64;
    int tid = threadIdx.x, r = tid >> 2, seg = tid & 3;
    const bf16* sp = src + ((size_t)(b*Nn + tok0 + r)) * Dd + d0;
#pragma unroll
    for (int p = 0; p < 2; p++) {
        int c0 = (seg + 4*p) * 8;
        union { uint4 u; bf16 h[8]; } v;
        v.u = *(const uint4*)(sp + c0);
#pragma unroll
        for (int e = 0; e < 8; e++) t[r][c0 + e] = v.h[e];
    }
    __syncthreads();
    bf16* dp = dst + (size_t)b*Dd*Nn + (size_t)(d0 + r)*Nn + tok0;
#pragma unroll
    for (int p = 0; p < 2; p++) {
        int c0 = (seg + 4*p) * 8;
        union { uint4 u; bf16 h[8]; } v;
#pragma unroll
        for (int e = 0; e < 8; e++) v.h[e] = t[c0 + e][r];
        *(uint4*)(dp + c0) = v.u;
    }
}

// ---------------- GEMM kernels (warp MMA) ------------------------------------
__global__ void __launch_bounds__(256, 2) mma_qkv_kernel(const float* __restrict__ bq,
                                                         const float* __restrict__ bk,
                                                         const float* __restrict__ bv) {
    int z = blockIdx.z;
    const bf16 *Whi, *Wlo; const float* bias; bf16 *OH, *OL;
    if (z == 0)      { Whi = g_wqhi; Wlo = g_wqlo; bias = bq; OH = g_qhi; OL = g_qlo; }
    else if (z == 1) { Whi = g_wkhi; Wlo = g_wklo; bias = bk; OH = g_khi; OL = g_klo; }
    else             { Whi = g_wvhi; Wlo = g_wvlo; bias = bv; OH = g_vhi; OL = g_vlo; }
    int m0 = blockIdx.y * 128, n0 = blockIdx.x * 128;
    float acc[4][4][4] = {};
    mma_mainloop(g_xhi + (size_t)m0*Dd, g_xlo + (size_t)m0*Dd, Dd,
                 Whi + (size_t)n0*Dd,  Wlo + (size_t)n0*Dd,  Dd, Dd/KS, acc);
    int tid = threadIdx.x, lane = tid & 31, wid = tid >> 5;
    int rb = (wid >> 2)*64 + (lane >> 2);
    int cb = (wid & 3)*32 + (lane & 3)*2;
    float2 b2[4];
#pragma unroll
    for (int bn = 0; bn < 4; bn++) b2[bn] = *(const float2*)(bias + n0 + cb + bn*8);
#pragma unroll
    for (int am = 0; am < 4; am++)
#pragma unroll
    for (int h = 0; h < 2; h++) {
        int row = m0 + rb + am*16 + h*8;
        bf16* oh = OH + (size_t)row*Dd + n0 + cb;
        bf16* ol = OL + (size_t)row*Dd + n0 + cb;
#pragma unroll
        for (int bn = 0; bn < 4; bn++) {
            bf16 h0,l0,h1,l1;
            split1(acc[am][bn][2*h]   + b2[bn].x, h0, l0);
            split1(acc[am][bn][2*h+1] + b2[bn].y, h1, l1);
            *(uint32_t*)(oh + bn*8) = packbf(h0, h1);
            *(uint32_t*)(ol + bn*8) = packbf(l0, l1);
        }
    }
}

__global__ void __launch_bounds__(256, 2) mma_scores_kernel() {
    int b = blockIdx.z;
    int t = blockIdx.x;
    int it = (int)((sqrtf(8.f*t + 1.f) - 1.f) * 0.5f);
    while ((it + 1)*(it + 2)/2 <= t) it++;
    while (it*(it + 1)/2 > t) it--;
    int jt = t - it*(it + 1)/2;
    int i0 = it * 128, j0 = jt * 128;
    float acc[4][4][4] = {};
    mma_mainloop(g_qhi + ((size_t)b*Nn + i0)*Dd, g_qlo + ((size_t)b*Nn + i0)*Dd, Dd,
                 g_khi + ((size_t)b*Nn + j0)*Dd, g_klo + ((size_t)b*Nn + j0)*Dd, Dd,
                 Dd/KS, acc);
    int tid = threadIdx.x, lane = tid & 31, wid = tid >> 5;
    int rb = (wid >> 2)*64 + (lane >> 2);
    int cb = (wid & 3)*32 + (lane & 3)*2;
    float thr = g_thr[b];
    const float2* qp2 = (const float2*)g_qp + (size_t)b * Nn;
    const float NEG = __int_as_float(0xff800000);
    float2 qj0[4], qj1[4];
#pragma unroll
    for (int bn = 0; bn < 4; bn++) {
        qj0[bn] = qp2[j0 + cb + bn*8];
        qj1[bn] = qp2[j0 + cb + bn*8 + 1];
    }
#pragma unroll
    for (int am = 0; am < 4; am++)
#pragma unroll
    for (int h = 0; h < 2; h++) {
        int gi = i0 + rb + am*16 + h*8;
        float2 qi = qp2[gi];
        float* o = g_w + (size_t)b*Nn*Nn + (size_t)gi*Nn + j0 + cb;
#pragma unroll
        for (int bn = 0; bn < 4; bn++) {
            float r[2];
#pragma unroll
            for (int q = 0; q < 2; q++) {
                int gj = j0 + cb + bn*8 + q;
                float2 qj = q ? qj1[bn] : qj0[bn];
                float dx = qi.x - qj.x, dy = qi.y - qj.y;
                float ds = dx*dx + dy*dy;
                bool ok = (gj <= gi) && (ds <= thr);
                if (ok && dx < 0.f && fabsf(dy) < 1e-3f * (-dx)) {
                    float bias = 0.5f * (1.f + cosf(atan2f(dy, dx)));
                    ok = (bias != 0.f);
                }
                r[q] = ok ? acc[am][bn][2*h+q] * 0.03125f : NEG;
            }
            *(float2*)(o + bn*8) = make_float2(r[0], r[1]);
        }
    }
}

// single-pass register softmax; emits hi/lo bf16 only
__global__ void __launch_bounds__(256) softmax_kernel() {
    __shared__ float red[256];
    int row = blockIdx.x;
    int b = row >> 11, i = row & (Nn - 1);
    const float* s = g_w + (size_t)b*Nn*Nn + (size_t)i*Nn;
    bf16* oh = g_whi + (size_t)b*Nn*Nn + (size_t)i*Nn;
    bf16* ol = g_wlo + (size_t)b*Nn*Nn + (size_t)i*Nn;
    int tid = threadIdx.x;
    int jb = tid * 8;
    const float NEG = __int_as_float(0xff800000);
    float v[8];
#pragma unroll
    for (int k = 0; k < 8; k++) {
        int j = jb + k;
        v[k] = (j <= i) ? s[j] : NEG;
    }
    float mx = v[0];
#pragma unroll
    for (int k = 1; k < 8; k++) mx = fmaxf(mx, v[k]);
    red[tid] = mx; __syncthreads();
    for (int o = 128; o; o >>= 1) {
        if (tid < o) red[tid] = fmaxf(red[tid], red[tid+o]);
        __syncthreads();
    }
    mx = red[0]; __syncthreads();
    float sum = 0.f;
#pragma unroll
    for (int k = 0; k < 8; k++) {
        int j = jb + k;
        float e = (j <= i) ? expf(v[k] - mx) : 0.f;
        v[k] = e; sum += e;
    }
    red[tid] = sum; __syncthreads();
    for (int o = 128; o; o >>= 1) {
        if (tid < o) red[tid] += red[tid+o];
        __syncthreads();
    }
    float inv = 1.f / red[0];
    union { uint4 u; bf16 hh[8]; } ph, pl;
#pragma unroll
    for (int k = 0; k < 8; k++) {
        bf16 h, l; split1(v[k] * inv, h, l);
        ph.hh[k] = h; pl.hh[k] = l;
    }
    *(uint4*)(oh + jb) = ph.u;
    *(uint4*)(ol + jb) = pl.u;
}

__global__ void __launch_bounds__(256, 2) mma_context_kernel() {
    int b = blockIdx.z, m0 = blockIdx.y * 128, n0 = blockIdx.x * 128;
    float acc[4][4][4] = {};
    mma_mainloop(g_whi + ((size_t)b*Nn + m0)*Nn, g_wlo + ((size_t)b*Nn + m0)*Nn, Nn,
                 g_vThi + ((size_t)b*Dd + n0)*Nn, g_vTlo + ((size_t)b*Dd + n0)*Nn, Nn,
                 (m0 + 128)/KS, acc);
    int tid = threadIdx.x, lane = tid & 31, wid = tid >> 5;
    int rb = (wid >> 2)*64 + (lane >> 2);
    int cb = (wid & 3)*32 + (lane & 3)*2;
#pragma unroll
    for (int am = 0; am < 4; am++)
#pragma unroll
    for (int h = 0; h < 2; h++) {
        int row = b*Nn + m0 + rb + am*16 + h*8;
        bf16* oh = g_ctxhi + (size_t)row*Dd + n0 + cb;
        bf16* ol = g_ctxlo + (size_t)row*Dd + n0 + cb;
#pragma unroll
        for (int bn = 0; bn < 4; bn++) {
            bf16 h0,l0,h1,l1;
            split1(acc[am][bn][2*h],   h0, l0);
            split1(acc[am][bn][2*h+1], h1, l1);
            *(uint32_t*)(oh + bn*8) = packbf(h0, h1);
            *(uint32_t*)(ol + bn*8) = packbf(l0, l1);
        }
    }
}

__global__ void __launch_bounds__(256, 2) mma_final_kernel(const float* __restrict__ X,
                                                           const float* __restrict__ bo,
                                                           const float* __restrict__ Wfq,
                                                           const float* __restrict__ bfq,
                                                           float* __restrict__ out) {
    int m0 = blockIdx.y * 128, n0 = blockIdx.x * 128;
    float acc[4][4][4] = {};
    mma_mainloop(g_ctxhi + (size_t)m0*Dd, g_ctxlo + (size_t)m0*Dd, Dd,
                 g_wohi + (size_t)n0*Dd,  g_wolo + (size_t)n0*Dd,  Dd, Dd/KS, acc);
    int tid = threadIdx.x, lane = tid & 31, wid = tid >> 5;
    int rb = (wid >> 2)*64 + (lane >> 2);
    int cb = (wid & 3)*32 + (lane & 3)*2;
    float2 bo2[4], bfq2[4]; float4 wf[4];
#pragma unroll
    for (int bn = 0; bn < 4; bn++) {
        int c = n0 + cb + bn*8;
        bo2[bn]  = *(const float2*)(bo  + c);
        bfq2[bn] = *(const float2*)(bfq + c);
        wf[bn]   = *(const float4*)(Wfq + 2*c);
    }
#pragma unroll
    for (int am = 0; am < 4; am++)
#pragma unroll
    for (int h = 0; h < 2; h++) {
        int row = m0 + rb + am*16 + h*8;
        float2 qp = ((const float2*)g_qp)[row];
        float nrm = fmaxf(sqrtf(qp.x*qp.x + qp.y*qp.y), 1e-12f);
        float r0 = qp.x / nrm, r1 = qp.y / nrm;
        const float* hx = X + (size_t)row*Dd + n0 + cb;
        float* o = out + (size_t)row*Dd + n0 + cb;
#pragma unroll
        for (int bn = 0; bn < 4; bn++) {
            float2 hv = *(const float2*)(hx + bn*8);
            float v0 = hv.x + acc[am][bn][2*h]   + bo2[bn].x
                     + 0.1f*(r0*wf[bn].x + r1*wf[bn].y + bfq2[bn].x);
            float v1 = hv.y + acc[am][bn][2*h+1] + bo2[bn].y
                     + 0.1f*(r0*wf[bn].z + r1*wf[bn].w + bfq2[bn].y);
            *(float2*)(o + bn*8) = make_float2(v0, v1);
        }
    }
}

// ---------------- launch ----------------------------------------------------
extern "C" void kernel_launch(void* const* d_in, const int* in_sizes, int n_in,
                              void* d_out, int out_size) {
    const float* X   = (const float*)d_in[0];
    const float* Wq  = (const float*)d_in[1];
    const float* bq  = (const float*)d_in[2];
    const float* Wk  = (const float*)d_in[3];
    const float* bk  = (const float*)d_in[4];
    const float* Wv  = (const float*)d_in[5];
    const float* bv  = (const float*)d_in[6];
    const float* Wo  = (const float*)d_in[7];
    const float* bo  = (const float*)d_in[8];
    const float* Wtq = (const float*)d_in[9];
    const float* btq = (const float*)d_in[10];
    const float* Wfq = (const float*)d_in[11];
    const float* bfq = (const float*)d_in[12];
    float* out = (float*)d_out;

    static bool attr_done = false;
    if (!attr_done) {
        cudaFuncSetAttribute(mma_qkv_kernel,     cudaFuncAttributeMaxDynamicSharedMemorySize, SMEM_BYTES);
        cudaFuncSetAttribute(mma_scores_kernel,  cudaFuncAttributeMaxDynamicSharedMemorySize, SMEM_BYTES);
        cudaFuncSetAttribute(mma_context_kernel, cudaFuncAttributeMaxDynamicSharedMemorySize, SMEM_BYTES);
        cudaFuncSetAttribute(mma_final_kernel,   cudaFuncAttributeMaxDynamicSharedMemorySize, SMEM_BYTES);
        attr_done = true;
    }

    bf16 *xhi, *xlo, *wqh, *wql, *wkh, *wkl, *wvh, *wvl, *woh, *wol;
    cudaGetSymbolAddress((void**)&xhi, g_xhi);  cudaGetSymbolAddress((void**)&xlo, g_xlo);
    cudaGetSymbolAddress((void**)&wqh, g_wqhi); cudaGetSymbolAddress((void**)&wql, g_wqlo);
    cudaGetSymbolAddress((void**)&wkh, g_wkhi); cudaGetSymbolAddress((void**)&wkl, g_wklo);
    cudaGetSymbolAddress((void**)&wvh, g_wvhi); cudaGetSymbolAddress((void**)&wvl, g_wvlo);
    cudaGetSymbolAddress((void**)&woh, g_wohi); cudaGetSymbolAddress((void**)&wol, g_wolo);

    int n4x = (int)((size_t)Mm*Dd/4), n4w = Dd*Dd/4;
    cvt_kernel<<<(n4x + 255)/256, 256>>>(X,  xhi, xlo, n4x);
    cvt_kernel<<<(n4w + 255)/256, 256>>>(Wq, wqh, wql, n4w);
    cvt_kernel<<<(n4w + 255)/256, 256>>>(Wk, wkh, wkl, n4w);
    cvt_kernel<<<(n4w + 255)/256, 256>>>(Wv, wvh, wvl, n4w);
    cvt_kernel<<<(n4w + 255)/256, 256>>>(Wo, woh, wol, n4w);

    zero_stats_kernel<<<1, 32>>>();
    qp_kernel<<<Mm/8, 256>>>(X, Wtq, btq);
    stats_kernel<<<dim3(Nn, Bb), 256>>>();
    thr_kernel<<<1, 32>>>();

    mma_qkv_kernel<<<dim3(Dd/128, Mm/128, 3), 256, SMEM_BYTES>>>(bq, bk, bv);
    vtrans_kernel<<<dim3(Nn/64, Dd/64, Bb*2), 256>>>();
    mma_scores_kernel<<<dim3(136, 1, Bb), 256, SMEM_BYTES>>>();
    softmax_kernel<<<Mm, 256>>>();
    mma_context_kernel<<<dim3(Dd/128, Nn/128, Bb), 256, SMEM_BYTES>>>();
    mma_final_kernel<<<dim3(Dd/128, Mm/128), 256, SMEM_BYTES>>>(X, bo, Wfq, bfq, out);
}

// round 7
// speedup vs baseline: 3.1170x; 1.0246x over previous
#include <cuda_runtime.h>
#include <cuda_bf16.h>
#include <math.h>
#include <stdint.h>

#define Bb 4
#define Nn 2048
#define Dd 1024
#define Mm (Bb*Nn)

typedef __nv_bfloat16 bf16;

// ---------------- scratch (static device globals) ---------------------------
__device__ bf16 g_xhi[(size_t)Mm*Dd], g_xlo[(size_t)Mm*Dd];
__device__ bf16 g_wqhi[Dd*Dd], g_wqlo[Dd*Dd];
__device__ bf16 g_wkhi[Dd*Dd], g_wklo[Dd*Dd];
__device__ bf16 g_wvhi[Dd*Dd], g_wvlo[Dd*Dd];
__device__ bf16 g_wohi[Dd*Dd], g_wolo[Dd*Dd];
__device__ bf16 g_qhi[(size_t)Mm*Dd], g_qlo[(size_t)Mm*Dd];
__device__ bf16 g_khi[(size_t)Mm*Dd], g_klo[(size_t)Mm*Dd];
__device__ bf16 g_vhi[(size_t)Mm*Dd], g_vlo[(size_t)Mm*Dd];
__device__ bf16 g_vThi[(size_t)Bb*Dd*Nn], g_vTlo[(size_t)Bb*Dd*Nn];
__device__ bf16 g_ctxhi[(size_t)Mm*Dd], g_ctxlo[(size_t)Mm*Dd];
__device__ bf16 g_whi[(size_t)Bb*Nn*Nn], g_wlo[(size_t)Bb*Nn*Nn];
__device__ float  g_w [(size_t)Bb*Nn*Nn];
__device__ float  g_qp[Mm*2];
__device__ double g_s1[Bb], g_s2[Bb];
__device__ float  g_thr[Bb];

// ---------------- PTX helpers (sm_80-class only) ----------------------------
__device__ __forceinline__ uint32_t smem_u32(const void* p) {
    uint32_t a;
    asm("{ .reg .u64 t; cvta.to.shared.u64 t, %1; cvt.u32.u64 %0, t; }" : "=r"(a) : "l"(p));
    return a;
}
#define CP16(dst, src) \
    asm volatile("cp.async.cg.shared.global [%0], [%1], 16;" :: "r"(dst), "l"(src) : "memory")
#define CP_COMMIT() asm volatile("cp.async.commit_group;" ::: "memory")

#define LDM_X4(r, addr) \
    asm volatile("ldmatrix.sync.aligned.m8n8.x4.shared.b16 {%0,%1,%2,%3}, [%4];" \
        : "=r"((r)[0]), "=r"((r)[1]), "=r"((r)[2]), "=r"((r)[3]) : "r"(addr))

#define MMA_BF16(d, a, b) \
    asm volatile("mma.sync.aligned.m16n8k16.row.col.f32.bf16.bf16.f32 " \
        "{%0,%1,%2,%3}, {%4,%5,%6,%7}, {%8,%9}, {%0,%1,%2,%3};" \
        : "+f"((d)[0]), "+f"((d)[1]), "+f"((d)[2]), "+f"((d)[3]) \
        : "r"((a)[0]), "r"((a)[1]), "r"((a)[2]), "r"((a)[3]), "r"((b)[0]), "r"((b)[1]))

// ---------------- tiling constants ------------------------------------------
#define KS 32
#define LDSB 64
#define TILEB (128*LDSB)
#define STAGEB (4*TILEB)
#define NSTAGE 3
#define SMEM_BYTES (NSTAGE*STAGEB)   // 98304 -> 2 CTAs/SM

__device__ __forceinline__ uint32_t swz(uint32_t r, uint32_t c) {
    return (uint32_t)r * LDSB + ((c ^ ((r + (r >> 2)) & 3)) << 4);
}

// ---------------- stage load via cp.async -----------------------------------
__device__ __forceinline__ void load_stage(uint32_t sb,
        const bf16* __restrict__ Ahi, const bf16* __restrict__ Alo,
        const bf16* __restrict__ Bhi, const bf16* __restrict__ Blo,
        size_t lda, size_t ldb, int kt) {
    int tid = threadIdx.x;
    int r0 = tid >> 2, seg = tid & 3;
    size_t koff = (size_t)kt * KS + seg * 8;
#pragma unroll
    for (int p = 0; p < 2; p++) {
        int row = r0 + p * 64;
        uint32_t ds = sb + swz((uint32_t)row, (uint32_t)seg);
        CP16(ds,           Ahi + (size_t)row * lda + koff);
        CP16(ds +   TILEB, Alo + (size_t)row * lda + koff);
        CP16(ds + 2*TILEB, Bhi + (size_t)row * ldb + koff);
        CP16(ds + 3*TILEB, Blo + (size_t)row * ldb + koff);
    }
    CP_COMMIT();
}

// ---------------- per-stage compute -----------------------------------------
__device__ __forceinline__ void compute_stage(uint32_t sb, int wm, int wn, int lane,
                                              float acc[4][4][4]) {
    int arow = lane & 15;
    int acol = (lane >> 4) << 3;
    int brow = (lane & 7) + ((lane >> 4) << 3);
    int bcol = ((lane >> 3) & 1) << 3;
#pragma unroll
    for (int ks = 0; ks < 2; ks++) {
        uint32_t ah[4][4], al[4][4];
        uint32_t ca = (uint32_t)(2*ks + (acol >> 3));
#pragma unroll
        for (int am = 0; am < 4; am++) {
            uint32_t ad = sb + swz((uint32_t)(wm*64 + am*16 + arow), ca);
            LDM_X4(ah[am], ad);
            LDM_X4(al[am], ad + TILEB);
        }
        uint32_t bh[4][2], bl[4][2];
        uint32_t cbk = (uint32_t)(2*ks + (bcol >> 3));
#pragma unroll
        for (int bp = 0; bp < 2; bp++) {
            uint32_t bd = sb + 2*TILEB + swz((uint32_t)(wn*32 + bp*16 + brow), cbk);
            uint32_t t[4];
            LDM_X4(t, bd);
            bh[2*bp][0] = t[0]; bh[2*bp][1] = t[1];
            bh[2*bp+1][0] = t[2]; bh[2*bp+1][1] = t[3];
            LDM_X4(t, bd + TILEB);
            bl[2*bp][0] = t[0]; bl[2*bp][1] = t[1];
            bl[2*bp+1][0] = t[2]; bl[2*bp+1][1] = t[3];
        }
#pragma unroll
        for (int am = 0; am < 4; am++)
#pragma unroll
            for (int bn = 0; bn < 4; bn++) {
                MMA_BF16(acc[am][bn], ah[am], bh[bn]);
                MMA_BF16(acc[am][bn], ah[am], bl[bn]);
                MMA_BF16(acc[am][bn], al[am], bh[bn]);
            }
    }
}

__device__ __forceinline__ void mma_mainloop(
        const bf16* __restrict__ Ahi, const bf16* __restrict__ Alo, size_t lda,
        const bf16* __restrict__ Bhi, const bf16* __restrict__ Blo, size_t ldb,
        int kIters, float acc[4][4][4]) {
    extern __shared__ __align__(16) char smem[];
    uint32_t sb = smem_u32(smem);
    int tid = threadIdx.x, lane = tid & 31, wid = tid >> 5;
    int wm = wid >> 2, wn = wid & 3;
    load_stage(sb, Ahi, Alo, Bhi, Blo, lda, ldb, 0);
    if (kIters > 1) load_stage(sb + STAGEB, Ahi, Alo, Bhi, Blo, lda, ldb, 1);
    int slot = 0;
    for (int kt = 0; kt < kIters; kt++) {
        if (kt + 1 < kIters) asm volatile("cp.async.wait_group 1;" ::: "memory");
        else                 asm volatile("cp.async.wait_group 0;" ::: "memory");
        __syncthreads();
        if (kt + 2 < kIters) {
            int ns = slot + 2; if (ns >= NSTAGE) ns -= NSTAGE;
            load_stage(sb + (uint32_t)ns * STAGEB, Ahi, Alo, Bhi, Blo, lda, ldb, kt + 2);
        }
        compute_stage(sb + (uint32_t)slot * STAGEB, wm, wn, lane, acc);
        if (++slot == NSTAGE) slot = 0;
    }
}

__device__ __forceinline__ uint32_t packbf(bf16 a, bf16 b) {
    union { __nv_bfloat162 h; uint32_t u; } c;
    c.h = __halves2bfloat162(a, b);
    return c.u;
}
__device__ __forceinline__ void split1(float v, bf16& h, bf16& l) {
    h = __float2bfloat16(v);
    l = __float2bfloat16(v - __bfloat162float(h));
}

// ---------------- conversion kernel -----------------------------------------
__global__ void __launch_bounds__(256) cvt_kernel(const float* __restrict__ src,
                                                  bf16* __restrict__ hi,
                                                  bf16* __restrict__ lo, int n4) {
    int i = blockIdx.x * 256 + threadIdx.x;
    if (i >= n4) return;
    float4 v = ((const float4*)src)[i];
    bf16 h0,l0,h1,l1,h2,l2,h3,l3;
    split1(v.x,h0,l0); split1(v.y,h1,l1); split1(v.z,h2,l2); split1(v.w,h3,l3);
    *(uint2*)(hi + 4*(size_t)i) = make_uint2(packbf(h0,h1), packbf(h2,h3));
    *(uint2*)(lo + 4*(size_t)i) = make_uint2(packbf(l0,l1), packbf(l2,l3));
}

// ---------------- small SIMT kernels ----------------------------------------
__global__ void __launch_bounds__(256) qp_kernel(const float* __restrict__ X,
                                                 const float* __restrict__ Wtq,
                                                 const float* __restrict__ btq) {
    if (blockIdx.x == 0 && threadIdx.x < Bb) {
        g_s1[threadIdx.x] = 0.0; g_s2[threadIdx.x] = 0.0;
    }
    int warp = threadIdx.x >> 5, lane = threadIdx.x & 31;
    int row = blockIdx.x * 8 + warp;
    const float* x = X + (size_t)row * Dd;
    float s0 = 0.f, s1 = 0.f;
    for (int k = lane * 4; k < Dd; k += 128) {
        float4 xv = *(const float4*)(x + k);
        float4 w0 = *(const float4*)(Wtq + k);
        float4 w1 = *(const float4*)(Wtq + Dd + k);
        s0 += xv.x*w0.x + xv.y*w0.y + xv.z*w0.z + xv.w*w0.w;
        s1 += xv.x*w1.x + xv.y*w1.y + xv.z*w1.z + xv.w*w1.w;
    }
#pragma unroll
    for (int o = 16; o; o >>= 1) {
        s0 += __shfl_xor_sync(0xffffffffu, s0, o);
        s1 += __shfl_xor_sync(0xffffffffu, s1, o);
    }
    if (lane == 0) { g_qp[row*2+0] = s0 + btq[0]; g_qp[row*2+1] = s1 + btq[1]; }
}
__global__ void __launch_bounds__(256) stats_kernel() {
    __shared__ float r1[256], r2[256];
    int b = blockIdx.y, i = blockIdx.x, tid = threadIdx.x;
    const float2* qp2 = (const float2*)g_qp + (size_t)b * Nn;
    float2 qi = qp2[i];
    float s1 = 0.f, s2 = 0.f;
    for (int j = tid; j < Nn; j += 256) {
        float2 qj = qp2[j];
        float dx = qi.x - qj.x, dy = qi.y - qj.y;
        float d = dx*dx + dy*dy;
        s1 += d; s2 += d*d;
    }
    r1[tid] = s1; r2[tid] = s2; __syncthreads();
    for (int o = 128; o; o >>= 1) {
        if (tid < o) { r1[tid] += r1[tid+o]; r2[tid] += r2[tid+o]; }
        __syncthreads();
    }
    if (tid == 0) { atomicAdd(&g_s1[b], (double)r1[0]); atomicAdd(&g_s2[b], (double)r2[0]); }
}
__global__ void thr_kernel() {
    int b = threadIdx.x;
    if (b < Bb) {
        double M = (double)Nn * (double)Nn;
        double mean = g_s1[b] / M;
        double var = (g_s2[b] - g_s1[b]*g_s1[b]/M) / (M - 1.0);
        if (var < 0.0) var = 0.0;
        g_thr[b] = (float)(mean + 1.25 * sqrt(var));
    }
}

// ---------------- v transpose -----------------------------------------------
__global__ void __launch_bounds__(256) vtrans_kernel() {
    __shared__ bf16 t[64][66];
    int b = blockIdx.z >> 1;
    const bf16* src = (blockIdx.z & 1) ? g_vlo : g_vhi;
    bf16* dst       = (blockIdx.z & 1) ? g_vTlo : g_vThi;
    int tok0 = blockIdx.x * 64, d0 = blockIdx.y * 64;
    int tid = threadIdx.x, r = tid >> 2, seg = tid & 3;
    const bf16* sp = src + ((size_t)(b*Nn + tok0 + r)) * Dd + d0;
#pragma unroll
    for (int p = 0; p < 2; p++) {
        int c0 = (seg + 4*p) * 8;
        union { uint4 u; bf16 h[8]; } v;
        v.u = *(const uint4*)(sp + c0);
#pragma unroll
        for (int e = 0; e < 8; e++) t[r][c0 + e] = v.h[e];
    }
    __syncthreads();
    bf16* dp = dst + (size_t)b*Dd*Nn + (size_t)(d0 + r)*Nn + tok0;
#pragma unroll
    for (int p = 0; p < 2; p++) {
        int c0 = (seg + 4*p) * 8;
        union { uint4 u; bf16 h[8]; } v;
#pragma unroll
        for (int e = 0; e < 8; e++) v.h[e] = t[c0 + e][r];
        *(uint4*)(dp + c0) = v.u;
    }
}

// ---------------- GEMM kernels ----------------------------------------------
// projection epilogue shared by qk and v kernels
__device__ __forceinline__ void proj_epilogue(float acc[4][4][4], const float* bias,
                                              bf16* OH, bf16* OL, int m0, int n0) {
    int tid = threadIdx.x, lane = tid & 31, wid = tid >> 5;
    int rb = (wid >> 2)*64 + (lane >> 2);
    int cb = (wid & 3)*32 + (lane & 3)*2;
    float2 b2[4];
#pragma unroll
    for (int bn = 0; bn < 4; bn++) b2[bn] = *(const float2*)(bias + n0 + cb + bn*8);
#pragma unroll
    for (int am = 0; am < 4; am++)
#pragma unroll
    for (int h = 0; h < 2; h++) {
        int row = m0 + rb + am*16 + h*8;
        bf16* oh = OH + (size_t)row*Dd + n0 + cb;
        bf16* ol = OL + (size_t)row*Dd + n0 + cb;
#pragma unroll
        for (int bn = 0; bn < 4; bn++) {
            bf16 h0,l0,h1,l1;
            split1(acc[am][bn][2*h]   + b2[bn].x, h0, l0);
            split1(acc[am][bn][2*h+1] + b2[bn].y, h1, l1);
            *(uint32_t*)(oh + bn*8) = packbf(h0, h1);
            *(uint32_t*)(ol + bn*8) = packbf(l0, l1);
        }
    }
}

__global__ void __launch_bounds__(256, 2) mma_qk_kernel(const float* __restrict__ bq,
                                                        const float* __restrict__ bk) {
    int z = blockIdx.z;
    const bf16 *Whi = z ? g_wkhi : g_wqhi, *Wlo = z ? g_wklo : g_wqlo;
    const float* bias = z ? bk : bq;
    bf16 *OH = z ? g_khi : g_qhi, *OL = z ? g_klo : g_qlo;
    int m0 = blockIdx.y * 128, n0 = blockIdx.x * 128;
    float acc[4][4][4] = {};
    mma_mainloop(g_xhi + (size_t)m0*Dd, g_xlo + (size_t)m0*Dd, Dd,
                 Whi + (size_t)n0*Dd,  Wlo + (size_t)n0*Dd,  Dd, Dd/KS, acc);
    proj_epilogue(acc, bias, OH, OL, m0, n0);
}

__global__ void __launch_bounds__(256, 2) mma_v_kernel(const float* __restrict__ bv) {
    int m0 = blockIdx.y * 128, n0 = blockIdx.x * 128;
    float acc[4][4][4] = {};
    mma_mainloop(g_xhi + (size_t)m0*Dd, g_xlo + (size_t)m0*Dd, Dd,
                 g_wvhi + (size_t)n0*Dd, g_wvlo + (size_t)n0*Dd, Dd, Dd/KS, acc);
    proj_epilogue(acc, bv, g_vhi, g_vlo, m0, n0);
}

__global__ void __launch_bounds__(256, 2) mma_scores_kernel() {
    int b = blockIdx.z;
    int t = blockIdx.x;
    int it = (int)((sqrtf(8.f*t + 1.f) - 1.f) * 0.5f);
    while ((it + 1)*(it + 2)/2 <= t) it++;
    while (it*(it + 1)/2 > t) it--;
    int jt = t - it*(it + 1)/2;
    int i0 = it * 128, j0 = jt * 128;
    float acc[4][4][4] = {};
    mma_mainloop(g_qhi + ((size_t)b*Nn + i0)*Dd, g_qlo + ((size_t)b*Nn + i0)*Dd, Dd,
                 g_khi + ((size_t)b*Nn + j0)*Dd, g_klo + ((size_t)b*Nn + j0)*Dd, Dd,
                 Dd/KS, acc);
    int tid = threadIdx.x, lane = tid & 31, wid = tid >> 5;
    int rb = (wid >> 2)*64 + (lane >> 2);
    int cb = (wid & 3)*32 + (lane & 3)*2;
    float thr = g_thr[b];
    const float2* qp2 = (const float2*)g_qp + (size_t)b * Nn;
    const float NEG = __int_as_float(0xff800000);
    float2 qj0[4], qj1[4];
#pragma unroll
    for (int bn = 0; bn < 4; bn++) {
        qj0[bn] = qp2[j0 + cb + bn*8];
        qj1[bn] = qp2[j0 + cb + bn*8 + 1];
    }
#pragma unroll
    for (int am = 0; am < 4; am++)
#pragma unroll
    for (int h = 0; h < 2; h++) {
        int gi = i0 + rb + am*16 + h*8;
        float2 qi = qp2[gi];
        float* o = g_w + (size_t)b*Nn*Nn + (size_t)gi*Nn + j0 + cb;
#pragma unroll
        for (int bn = 0; bn < 4; bn++) {
            float r[2];
#pragma unroll
            for (int q = 0; q < 2; q++) {
                int gj = j0 + cb + bn*8 + q;
                float2 qj = q ? qj1[bn] : qj0[bn];
                float dx = qi.x - qj.x, dy = qi.y - qj.y;
                float ds = dx*dx + dy*dy;
                bool ok = (gj <= gi) && (ds <= thr);
                if (ok && dx < 0.f && fabsf(dy) < 1e-3f * (-dx)) {
                    float bias = 0.5f * (1.f + cosf(atan2f(dy, dx)));
                    ok = (bias != 0.f);
                }
                r[q] = ok ? acc[am][bn][2*h+q] * 0.03125f : NEG;
            }
            *(float2*)(o + bn*8) = make_float2(r[0], r[1]);
        }
    }
}

__global__ void __launch_bounds__(256) softmax_kernel() {
    __shared__ float red[256];
    int row = blockIdx.x;
    int b = row >> 11, i = row & (Nn - 1);
    const float* s = g_w + (size_t)b*Nn*Nn + (size_t)i*Nn;
    bf16* oh = g_whi + (size_t)b*Nn*Nn + (size_t)i*Nn;
    bf16* ol = g_wlo + (size_t)b*Nn*Nn + (size_t)i*Nn;
    int tid = threadIdx.x;
    int jb = tid * 8;
    const float NEG = __int_as_float(0xff800000);
    float v[8];
#pragma unroll
    for (int k = 0; k < 8; k++) {
        int j = jb + k;
        v[k] = (j <= i) ? s[j] : NEG;
    }
    float mx = v[0];
#pragma unroll
    for (int k = 1; k < 8; k++) mx = fmaxf(mx, v[k]);
    red[tid] = mx; __syncthreads();
    for (int o = 128; o; o >>= 1) {
        if (tid < o) red[tid] = fmaxf(red[tid], red[tid+o]);
        __syncthreads();
    }
    mx = red[0]; __syncthreads();
    float sum = 0.f;
#pragma unroll
    for (int k = 0; k < 8; k++) {
        int j = jb + k;
        float e = (j <= i) ? expf(v[k] - mx) : 0.f;
        v[k] = e; sum += e;
    }
    red[tid] = sum; __syncthreads();
    for (int o = 128; o; o >>= 1) {
        if (tid < o) red[tid] += red[tid+o];
        __syncthreads();
    }
    float inv = 1.f / red[0];
    union { uint4 u; bf16 hh[8]; } ph, pl;
#pragma unroll
    for (int k = 0; k < 8; k++) {
        bf16 h, l; split1(v[k] * inv, h, l);
        ph.hh[k] = h; pl.hh[k] = l;
    }
    *(uint4*)(oh + jb) = ph.u;
    *(uint4*)(ol + jb) = pl.u;
}

__global__ void __launch_bounds__(256, 2) mma_context_kernel() {
    int b = blockIdx.z, m0 = blockIdx.y * 128, n0 = blockIdx.x * 128;
    float acc[4][4][4] = {};
    mma_mainloop(g_whi + ((size_t)b*Nn + m0)*Nn, g_wlo + ((size_t)b*Nn + m0)*Nn, Nn,
                 g_vThi + ((size_t)b*Dd + n0)*Nn, g_vTlo + ((size_t)b*Dd + n0)*Nn, Nn,
                 (m0 + 128)/KS, acc);
    int tid = threadIdx.x, lane = tid & 31, wid = tid >> 5;
    int rb = (wid >> 2)*64 + (lane >> 2);
    int cb = (wid & 3)*32 + (lane & 3)*2;
#pragma unroll
    for (int am = 0; am < 4; am++)
#pragma unroll
    for (int h = 0; h < 2; h++) {
        int row = b*Nn + m0 + rb + am*16 + h*8;
        bf16* oh = g_ctxhi + (size_t)row*Dd + n0 + cb;
        bf16* ol = g_ctxlo + (size_t)row*Dd + n0 + cb;
#pragma unroll
        for (int bn = 0; bn < 4; bn++) {
            bf16 h0,l0,h1,l1;
            split1(acc[am][bn][2*h],   h0, l0);
            split1(acc[am][bn][2*h+1], h1, l1);
            *(uint32_t*)(oh + bn*8) = packbf(h0, h1);
            *(uint32_t*)(ol + bn*8) = packbf(l0, l1);
        }
    }
}

__global__ void __launch_bounds__(256, 2) mma_final_kernel(const float* __restrict__ X,
                                                           const float* __restrict__ bo,
                                                           const float* __restrict__ Wfq,
                                                           const float* __restrict__ bfq,
                                                           float* __restrict__ out) {
    int m0 = blockIdx.y * 128, n0 = blockIdx.x * 128;
    float acc[4][4][4] = {};
    mma_mainloop(g_ctxhi + (size_t)m0*Dd, g_ctxlo + (size_t)m0*Dd, Dd,
                 g_wohi + (size_t)n0*Dd,  g_wolo + (size_t)n0*Dd,  Dd, Dd/KS, acc);
    int tid = threadIdx.x, lane = tid & 31, wid = tid >> 5;
    int rb = (wid >> 2)*64 + (lane >> 2);
    int cb = (wid & 3)*32 + (lane & 3)*2;
    float2 bo2[4], bfq2[4]; float4 wf[4];
#pragma unroll
    for (int bn = 0; bn < 4; bn++) {
        int c = n0 + cb + bn*8;
        bo2[bn]  = *(const float2*)(bo  + c);
        bfq2[bn] = *(const float2*)(bfq + c);
        wf[bn]   = *(const float4*)(Wfq + 2*c);
    }
#pragma unroll
    for (int am = 0; am < 4; am++)
#pragma unroll
    for (int h = 0; h < 2; h++) {
        int row = m0 + rb + am*16 + h*8;
        float2 qp = ((const float2*)g_qp)[row];
        float nrm = fmaxf(sqrtf(qp.x*qp.x + qp.y*qp.y), 1e-12f);
        float r0 = qp.x / nrm, r1 = qp.y / nrm;
        const float* hx = X + (size_t)row*Dd + n0 + cb;
        float* o = out + (size_t)row*Dd + n0 + cb;
#pragma unroll
        for (int bn = 0; bn < 4; bn++) {
            float2 hv = *(const float2*)(hx + bn*8);
            float v0 = hv.x + acc[am][bn][2*h]   + bo2[bn].x
                     + 0.1f*(r0*wf[bn].x + r1*wf[bn].y + bfq2[bn].x);
            float v1 = hv.y + acc[am][bn][2*h+1] + bo2[bn].y
                     + 0.1f*(r0*wf[bn].z + r1*wf[bn].w + bfq2[bn].y);
            *(float2*)(o + bn*8) = make_float2(v0, v1);
        }
    }
}

// ---------------- launch ----------------------------------------------------
extern "C" void kernel_launch(void* const* d_in, const int* in_sizes, int n_in,
                              void* d_out, int out_size) {
    const float* X   = (const float*)d_in[0];
    const float* Wq  = (const float*)d_in[1];
    const float* bq  = (const float*)d_in[2];
    const float* Wk  = (const float*)d_in[3];
    const float* bk  = (const float*)d_in[4];
    const float* Wv  = (const float*)d_in[5];
    const float* bv  = (const float*)d_in[6];
    const float* Wo  = (const float*)d_in[7];
    const float* bo  = (const float*)d_in[8];
    const float* Wtq = (const float*)d_in[9];
    const float* btq = (const float*)d_in[10];
    const float* Wfq = (const float*)d_in[11];
    const float* bfq = (const float*)d_in[12];
    float* out = (float*)d_out;

    static bool init_done = false;
    static bool use_streams = false;
    static cudaStream_t sA, sB, sC;
    static cudaEvent_t evRoot, evX, evA, evB, evC;
    if (!init_done) {
        cudaFuncSetAttribute(mma_qk_kernel,      cudaFuncAttributeMaxDynamicSharedMemorySize, SMEM_BYTES);
        cudaFuncSetAttribute(mma_v_kernel,       cudaFuncAttributeMaxDynamicSharedMemorySize, SMEM_BYTES);
        cudaFuncSetAttribute(mma_scores_kernel,  cudaFuncAttributeMaxDynamicSharedMemorySize, SMEM_BYTES);
        cudaFuncSetAttribute(mma_context_kernel, cudaFuncAttributeMaxDynamicSharedMemorySize, SMEM_BYTES);
        cudaFuncSetAttribute(mma_final_kernel,   cudaFuncAttributeMaxDynamicSharedMemorySize, SMEM_BYTES);
        bool ok = true;
        ok &= (cudaStreamCreateWithFlags(&sA, cudaStreamNonBlocking) == cudaSuccess);
        ok &= (cudaStreamCreateWithFlags(&sB, cudaStreamNonBlocking) == cudaSuccess);
        ok &= (cudaStreamCreateWithFlags(&sC, cudaStreamNonBlocking) == cudaSuccess);
        ok &= (cudaEventCreateWithFlags(&evRoot, cudaEventDisableTiming) == cudaSuccess);
        ok &= (cudaEventCreateWithFlags(&evX,    cudaEventDisableTiming) == cudaSuccess);
        ok &= (cudaEventCreateWithFlags(&evA,    cudaEventDisableTiming) == cudaSuccess);
        ok &= (cudaEventCreateWithFlags(&evB,    cudaEventDisableTiming) == cudaSuccess);
        ok &= (cudaEventCreateWithFlags(&evC,    cudaEventDisableTiming) == cudaSuccess);
        use_streams = ok;
        init_done = true;
    }

    bf16 *xhi, *xlo, *wqh, *wql, *wkh, *wkl, *wvh, *wvl, *woh, *wol;
    cudaGetSymbolAddress((void**)&xhi, g_xhi);  cudaGetSymbolAddress((void**)&xlo, g_xlo);
    cudaGetSymbolAddress((void**)&wqh, g_wqhi); cudaGetSymbolAddress((void**)&wql, g_wqlo);
    cudaGetSymbolAddress((void**)&wkh, g_wkhi); cudaGetSymbolAddress((void**)&wkl, g_wklo);
    cudaGetSymbolAddress((void**)&wvh, g_wvhi); cudaGetSymbolAddress((void**)&wvl, g_wvlo);
    cudaGetSymbolAddress((void**)&woh, g_wohi); cudaGetSymbolAddress((void**)&wol, g_wolo);

    int n4x = (int)((size_t)Mm*Dd/4), n4w = Dd*Dd/4;

    if (use_streams) {
        cudaEventRecord(evRoot, 0);
        // side A: mask-threshold chain (depends only on inputs)
        cudaStreamWaitEvent(sA, evRoot, 0);
        qp_kernel<<<Mm/8, 256, 0, sA>>>(X, Wtq, btq);
        stats_kernel<<<dim3(Nn, Bb), 256, 0, sA>>>();
        thr_kernel<<<1, 32, 0, sA>>>();
        cudaEventRecord(evA, sA);
        // side B: Wo conversion (needed only by final)
        cudaStreamWaitEvent(sB, evRoot, 0);
        cvt_kernel<<<(n4w + 255)/256, 256, 0, sB>>>(Wo, woh, wol, n4w);
        cudaEventRecord(evB, sB);
        // main: X + Wq/Wk conversions, then q/k projections
        cvt_kernel<<<(n4x + 255)/256, 256>>>(X,  xhi, xlo, n4x);
        cudaEventRecord(evX, 0);
        cvt_kernel<<<(n4w + 255)/256, 256>>>(Wq, wqh, wql, n4w);
        cvt_kernel<<<(n4w + 255)/256, 256>>>(Wk, wkh, wkl, n4w);
        // side C: v projection + transpose, concurrent with qk/scores/softmax
        cudaStreamWaitEvent(sC, evX, 0);
        cvt_kernel<<<(n4w + 255)/256, 256, 0, sC>>>(Wv, wvh, wvl, n4w);
        mma_v_kernel<<<dim3(Dd/128, Mm/128), 256, SMEM_BYTES, sC>>>(bv);
        vtrans_kernel<<<dim3(Nn/64, Dd/64, Bb*2), 256, 0, sC>>>();
        cudaEventRecord(evC, sC);
        // main chain
        mma_qk_kernel<<<dim3(Dd/128, Mm/128, 2), 256, SMEM_BYTES>>>(bq, bk);
        cudaStreamWaitEvent(0, evA, 0);
        mma_scores_kernel<<<dim3(136, 1, Bb), 256, SMEM_BYTES>>>();
        softmax_kernel<<<Mm, 256>>>();
        cudaStreamWaitEvent(0, evC, 0);
        mma_context_kernel<<<dim3(Dd/128, Nn/128, Bb), 256, SMEM_BYTES>>>();
        cudaStreamWaitEvent(0, evB, 0);
        mma_final_kernel<<<dim3(Dd/128, Mm/128), 256, SMEM_BYTES>>>(X, bo, Wfq, bfq, out);
    } else {
        // sequential fallback (identical work)
        qp_kernel<<<Mm/8, 256>>>(X, Wtq, btq);
        stats_kernel<<<dim3(Nn, Bb), 256>>>();
        thr_kernel<<<1, 32>>>();
        cvt_kernel<<<(n4x + 255)/256, 256>>>(X,  xhi, xlo, n4x);
        cvt_kernel<<<(n4w + 255)/256, 256>>>(Wq, wqh, wql, n4w);
        cvt_kernel<<<(n4w + 255)/256, 256>>>(Wk, wkh, wkl, n4w);
        cvt_kernel<<<(n4w + 255)/256, 256>>>(Wv, wvh, wvl, n4w);
        cvt_kernel<<<(n4w + 255)/256, 256>>>(Wo, woh, wol, n4w);
        mma_qk_kernel<<<dim3(Dd/128, Mm/128, 2), 256, SMEM_BYTES>>>(bq, bk);
        mma_v_kernel<<<dim3(Dd/128, Mm/128), 256, SMEM_BYTES>>>(bv);
        vtrans_kernel<<<dim3(Nn/64, Dd/64, Bb*2), 256>>>();
        mma_scores_kernel<<<dim3(136, 1, Bb), 256, SMEM_BYTES>>>();
        softmax_kernel<<<Mm, 256>>>();
        mma_context_kernel<<<dim3(Dd/128, Nn/128, Bb), 256, SMEM_BYTES>>>();
        mma_final_kernel<<<dim3(Dd/128, Mm/128), 256, SMEM_BYTES>>>(X, bo, Wfq, bfq, out);
    }
}

// round 8
// speedup vs baseline: 4.2613x; 1.3671x over previous
#include <cuda_runtime.h>
#include <cuda_fp16.h>
#include <math.h>
#include <stdint.h>

#define Bb 4
#define Nn 2048
#define Dd 1024
#define Mm (Bb*Nn)

typedef __half h16;

// ---------------- scratch (static device globals) ---------------------------
__device__ h16 g_xhi[(size_t)Mm*Dd];                       // A operands: hi only
__device__ h16 g_wqhi[Dd*Dd], g_wqlo[Dd*Dd];               // weights: hi+lo (x32 scaled)
__device__ h16 g_wkhi[Dd*Dd], g_wklo[Dd*Dd];
__device__ h16 g_wvhi[Dd*Dd], g_wvlo[Dd*Dd];
__device__ h16 g_wohi[Dd*Dd], g_wolo[Dd*Dd];
__device__ h16 g_qhi[(size_t)Mm*Dd];                       // A in scores: hi only
__device__ h16 g_khi[(size_t)Mm*Dd], g_klo[(size_t)Mm*Dd]; // B in scores: hi+lo
__device__ h16 g_vhi[(size_t)Mm*Dd], g_vlo[(size_t)Mm*Dd];
__device__ h16 g_vThi[(size_t)Bb*Dd*Nn], g_vTlo[(size_t)Bb*Dd*Nn];
__device__ h16 g_ctxhi[(size_t)Mm*Dd];                     // A in final: hi only
__device__ h16 g_whi[(size_t)Bb*Nn*Nn];                    // A in context: hi only
__device__ float  g_w [(size_t)Bb*Nn*Nn];
__device__ float  g_qp[Mm*2];
__device__ double g_s1[Bb], g_s2[Bb];
__device__ float  g_thr[Bb];

// ---------------- PTX helpers -----------------------------------------------
__device__ __forceinline__ uint32_t smem_u32(const void* p) {
    uint32_t a;
    asm("{ .reg .u64 t; cvta.to.shared.u64 t, %1; cvt.u32.u64 %0, t; }" : "=r"(a) : "l"(p));
    return a;
}
#define CP16(dst, src) \
    asm volatile("cp.async.cg.shared.global [%0], [%1], 16;" :: "r"(dst), "l"(src) : "memory")
#define CP_COMMIT() asm volatile("cp.async.commit_group;" ::: "memory")

#define LDM_X4(r, addr) \
    asm volatile("ldmatrix.sync.aligned.m8n8.x4.shared.b16 {%0,%1,%2,%3}, [%4];" \
        : "=r"((r)[0]), "=r"((r)[1]), "=r"((r)[2]), "=r"((r)[3]) : "r"(addr))

#define MMA_F16(d, a, b) \
    asm volatile("mma.sync.aligned.m16n8k16.row.col.f32.f16.f16.f32 " \
        "{%0,%1,%2,%3}, {%4,%5,%6,%7}, {%8,%9}, {%0,%1,%2,%3};" \
        : "+f"((d)[0]), "+f"((d)[1]), "+f"((d)[2]), "+f"((d)[3]) \
        : "r"((a)[0]), "r"((a)[1]), "r"((a)[2]), "r"((a)[3]), "r"((b)[0]), "r"((b)[1]))

// ---------------- tiling constants ------------------------------------------
#define KS 32
#define LDSB 64
#define TILEB (128*LDSB)          // 8192 B
#define STAGEB (3*TILEB)          // 24576 B: Ahi, Bhi, Blo
#define NSTAGE 4
#define SMEM_BYTES (NSTAGE*STAGEB)   // 98304 -> 2 CTAs/SM

__device__ __forceinline__ uint32_t swz(uint32_t r, uint32_t c) {
    return (uint32_t)r * LDSB + ((c ^ ((r + (r >> 2)) & 3)) << 4);
}

// ---------------- stage load via cp.async -----------------------------------
__device__ __forceinline__ void load_stage(uint32_t sb,
        const h16* __restrict__ A, size_t lda,
        const h16* __restrict__ Bhi, const h16* __restrict__ Blo, size_t ldb,
        int kt) {
    int tid = threadIdx.x;
    int r0 = tid >> 2, seg = tid & 3;
    size_t koff = (size_t)kt * KS + seg * 8;
#pragma unroll
    for (int p = 0; p < 2; p++) {
        int row = r0 + p * 64;
        uint32_t ds = sb + swz((uint32_t)row, (uint32_t)seg);
        CP16(ds,           A   + (size_t)row * lda + koff);
        CP16(ds +   TILEB, Bhi + (size_t)row * ldb + koff);
        CP16(ds + 2*TILEB, Blo + (size_t)row * ldb + koff);
    }
    CP_COMMIT();
}

// ---------------- per-stage compute: 2-term fp16 -----------------------------
__device__ __forceinline__ void compute_stage(uint32_t sb, int wm, int wn, int lane,
                                              float acc[4][4][4]) {
    int arow = lane & 15;
    int acol = (lane >> 4) << 3;
    int brow = (lane & 7) + ((lane >> 4) << 3);
    int bcol = ((lane >> 3) & 1) << 3;
#pragma unroll
    for (int ks = 0; ks < 2; ks++) {
        uint32_t ah[4][4];
        uint32_t ca = (uint32_t)(2*ks + (acol >> 3));
#pragma unroll
        for (int am = 0; am < 4; am++) {
            uint32_t ad = sb + swz((uint32_t)(wm*64 + am*16 + arow), ca);
            LDM_X4(ah[am], ad);
        }
        uint32_t bh[4][2], bl[4][2];
        uint32_t cbk = (uint32_t)(2*ks + (bcol >> 3));
#pragma unroll
        for (int bp = 0; bp < 2; bp++) {
            uint32_t bd = sb + TILEB + swz((uint32_t)(wn*32 + bp*16 + brow), cbk);
            uint32_t t[4];
            LDM_X4(t, bd);
            bh[2*bp][0] = t[0]; bh[2*bp][1] = t[1];
            bh[2*bp+1][0] = t[2]; bh[2*bp+1][1] = t[3];
            LDM_X4(t, bd + TILEB);
            bl[2*bp][0] = t[0]; bl[2*bp][1] = t[1];
            bl[2*bp+1][0] = t[2]; bl[2*bp+1][1] = t[3];
        }
#pragma unroll
        for (int am = 0; am < 4; am++)
#pragma unroll
            for (int bn = 0; bn < 4; bn++) {
                MMA_F16(acc[am][bn], ah[am], bh[bn]);
                MMA_F16(acc[am][bn], ah[am], bl[bn]);
            }
    }
}

// D[128,128] fp32 = A[128,K] * (Bhi+Blo)[128,K]^T, 4-stage cp.async pipeline
__device__ __forceinline__ void mma_mainloop(
        const h16* __restrict__ A, size_t lda,
        const h16* __restrict__ Bhi, const h16* __restrict__ Blo, size_t ldb,
        int kIters, float acc[4][4][4]) {
    extern __shared__ __align__(16) char smem[];
    uint32_t sb = smem_u32(smem);
    int tid = threadIdx.x, lane = tid & 31, wid = tid >> 5;
    int wm = wid >> 2, wn = wid & 3;
    load_stage(sb, A, lda, Bhi, Blo, ldb, 0);
    if (kIters > 1) load_stage(sb + STAGEB,   A, lda, Bhi, Blo, ldb, 1);
    if (kIters > 2) load_stage(sb + 2*STAGEB, A, lda, Bhi, Blo, ldb, 2);
    for (int kt = 0; kt < kIters; kt++) {
        if (kt + 2 < kIters)      asm volatile("cp.async.wait_group 2;" ::: "memory");
        else if (kt + 1 < kIters) asm volatile("cp.async.wait_group 1;" ::: "memory");
        else                      asm volatile("cp.async.wait_group 0;" ::: "memory");
        __syncthreads();
        if (kt + 3 < kIters)
            load_stage(sb + (uint32_t)((kt+3) & 3) * STAGEB, A, lda, Bhi, Blo, ldb, kt + 3);
        compute_stage(sb + (uint32_t)(kt & 3) * STAGEB, wm, wn, lane, acc);
    }
}

__device__ __forceinline__ uint32_t packh(h16 a, h16 b) {
    union { __half2 h; uint32_t u; } c;
    c.h = __halves2half2(a, b);
    return c.u;
}
__device__ __forceinline__ void split1(float v, h16& h, h16& l) {
    h = __float2half(v);
    l = __float2half(v - __half2float(h));
}

// ---------------- conversion kernels ----------------------------------------
// split with scale (weights: scale=32 keeps lo parts fp16-normal)
__global__ void __launch_bounds__(256) cvt_kernel(const float* __restrict__ src,
                                                  h16* __restrict__ hi,
                                                  h16* __restrict__ lo,
                                                  float scale, int n4) {
    int i = blockIdx.x * 256 + threadIdx.x;
    if (i >= n4) return;
    float4 v = ((const float4*)src)[i];
    h16 h0,l0,h1,l1,h2,l2,h3,l3;
    split1(v.x*scale,h0,l0); split1(v.y*scale,h1,l1);
    split1(v.z*scale,h2,l2); split1(v.w*scale,h3,l3);
    *(uint2*)(hi + 4*(size_t)i) = make_uint2(packh(h0,h1), packh(h2,h3));
    *(uint2*)(lo + 4*(size_t)i) = make_uint2(packh(l0,l1), packh(l2,l3));
}
// hi-only conversion (A operands)
__global__ void __launch_bounds__(256) cvt_hi_kernel(const float* __restrict__ src,
                                                     h16* __restrict__ hi, int n4) {
    int i = blockIdx.x * 256 + threadIdx.x;
    if (i >= n4) return;
    float4 v = ((const float4*)src)[i];
    *(uint2*)(hi + 4*(size_t)i) =
        make_uint2(packh(__float2half(v.x), __float2half(v.y)),
                   packh(__float2half(v.z), __float2half(v.w)));
}

// ---------------- small SIMT kernels ----------------------------------------
__global__ void __launch_bounds__(256) qp_kernel(const float* __restrict__ X,
                                                 const float* __restrict__ Wtq,
                                                 const float* __restrict__ btq) {
    if (blockIdx.x == 0 && threadIdx.x < Bb) {
        g_s1[threadIdx.x] = 0.0; g_s2[threadIdx.x] = 0.0;
    }
    int warp = threadIdx.x >> 5, lane = threadIdx.x & 31;
    int row = blockIdx.x * 8 + warp;
    const float* x = X + (size_t)row * Dd;
    float s0 = 0.f, s1 = 0.f;
    for (int k = lane * 4; k < Dd; k += 128) {
        float4 xv = *(const float4*)(x + k);
        float4 w0 = *(const float4*)(Wtq + k);
        float4 w1 = *(const float4*)(Wtq + Dd + k);
        s0 += xv.x*w0.x + xv.y*w0.y + xv.z*w0.z + xv.w*w0.w;
        s1 += xv.x*w1.x + xv.y*w1.y + xv.z*w1.z + xv.w*w1.w;
    }
#pragma unroll
    for (int o = 16; o; o >>= 1) {
        s0 += __shfl_xor_sync(0xffffffffu, s0, o);
        s1 += __shfl_xor_sync(0xffffffffu, s1, o);
    }
    if (lane == 0) { g_qp[row*2+0] = s0 + btq[0]; g_qp[row*2+1] = s1 + btq[1]; }
}
__global__ void __launch_bounds__(256) stats_kernel() {
    __shared__ float r1[256], r2[256];
    int b = blockIdx.y, i = blockIdx.x, tid = threadIdx.x;
    const float2* qp2 = (const float2*)g_qp + (size_t)b * Nn;
    float2 qi = qp2[i];
    float s1 = 0.f, s2 = 0.f;
    for (int j = tid; j < Nn; j += 256) {
        float2 qj = qp2[j];
        float dx = qi.x - qj.x, dy = qi.y - qj.y;
        float d = dx*dx + dy*dy;
        s1 += d; s2 += d*d;
    }
    r1[tid] = s1; r2[tid] = s2; __syncthreads();
    for (int o = 128; o; o >>= 1) {
        if (tid < o) { r1[tid] += r1[tid+o]; r2[tid] += r2[tid+o]; }
        __syncthreads();
    }
    if (tid == 0) { atomicAdd(&g_s1[b], (double)r1[0]); atomicAdd(&g_s2[b], (double)r2[0]); }
}
__global__ void thr_kernel() {
    int b = threadIdx.x;
    if (b < Bb) {
        double M = (double)Nn * (double)Nn;
        double mean = g_s1[b] / M;
        double var = (g_s2[b] - g_s1[b]*g_s1[b]/M) / (M - 1.0);
        if (var < 0.0) var = 0.0;
        g_thr[b] = (float)(mean + 1.25 * sqrt(var));
    }
}

// ---------------- v transpose -----------------------------------------------
__global__ void __launch_bounds__(256) vtrans_kernel() {
    __shared__ h16 t[64][66];
    int b = blockIdx.z >> 1;
    const h16* src = (blockIdx.z & 1) ? g_vlo : g_vhi;
    h16* dst       = (blockIdx.z & 1) ? g_vTlo : g_vThi;
    int tok0 = blockIdx.x * 64, d0 = blockIdx.y * 64;
    int tid = threadIdx.x, r = tid >> 2, seg = tid & 3;
    const h16* sp = src + ((size_t)(b*Nn + tok0 + r)) * Dd + d0;
#pragma unroll
    for (int p = 0; p < 2; p++) {
        int c0 = (seg + 4*p) * 8;
        union { uint4 u; h16 h[8]; } v;
        v.u = *(const uint4*)(sp + c0);
#pragma unroll
        for (int e = 0; e < 8; e++) t[r][c0 + e] = v.h[e];
    }
    __syncthreads();
    h16* dp = dst + (size_t)b*Dd*Nn + (size_t)(d0 + r)*Nn + tok0;
#pragma unroll
    for (int p = 0; p < 2; p++) {
        int c0 = (seg + 4*p) * 8;
        union { uint4 u; h16 h[8]; } v;
#pragma unroll
        for (int e = 0; e < 8; e++) v.h[e] = t[c0 + e][r];
        *(uint4*)(dp + c0) = v.u;
    }
}

// ---------------- GEMM kernels ----------------------------------------------
// projection epilogue: acc*(1/32) + bias; writes hi (and optionally lo)
__device__ __forceinline__ void proj_epilogue(float acc[4][4][4], const float* bias,
                                              h16* OH, h16* OL, int m0, int n0,
                                              bool wlo) {
    int tid = threadIdx.x, lane = tid & 31, wid = tid >> 5;
    int rb = (wid >> 2)*64 + (lane >> 2);
    int cb = (wid & 3)*32 + (lane & 3)*2;
    float2 b2[4];
#pragma unroll
    for (int bn = 0; bn < 4; bn++) b2[bn] = *(const float2*)(bias + n0 + cb + bn*8);
#pragma unroll
    for (int am = 0; am < 4; am++)
#pragma unroll
    for (int h = 0; h < 2; h++) {
        int row = m0 + rb + am*16 + h*8;
        h16* oh = OH + (size_t)row*Dd + n0 + cb;
        h16* ol = OL + (size_t)row*Dd + n0 + cb;
#pragma unroll
        for (int bn = 0; bn < 4; bn++) {
            float v0 = acc[am][bn][2*h]   * 0.03125f + b2[bn].x;
            float v1 = acc[am][bn][2*h+1] * 0.03125f + b2[bn].y;
            h16 h0,l0,h1,l1;
            split1(v0, h0, l0);
            split1(v1, h1, l1);
            *(uint32_t*)(oh + bn*8) = packh(h0, h1);
            if (wlo) *(uint32_t*)(ol + bn*8) = packh(l0, l1);
        }
    }
}

__global__ void __launch_bounds__(256, 2) mma_qk_kernel(const float* __restrict__ bq,
                                                        const float* __restrict__ bk) {
    int z = blockIdx.z;
    const h16 *Whi = z ? g_wkhi : g_wqhi, *Wlo = z ? g_wklo : g_wqlo;
    const float* bias = z ? bk : bq;
    int m0 = blockIdx.y * 128, n0 = blockIdx.x * 128;
    float acc[4][4][4] = {};
    mma_mainloop(g_xhi + (size_t)m0*Dd, Dd,
                 Whi + (size_t)n0*Dd, Wlo + (size_t)n0*Dd, Dd, Dd/KS, acc);
    if (z) proj_epilogue(acc, bias, g_khi, g_klo, m0, n0, true);   // k: hi+lo (B of scores)
    else   proj_epilogue(acc, bias, g_qhi, g_qhi, m0, n0, false);  // q: hi only
}

__global__ void __launch_bounds__(256, 2) mma_v_kernel(const float* __restrict__ bv) {
    int m0 = blockIdx.y * 128, n0 = blockIdx.x * 128;
    float acc[4][4][4] = {};
    mma_mainloop(g_xhi + (size_t)m0*Dd, Dd,
                 g_wvhi + (size_t)n0*Dd, g_wvlo + (size_t)n0*Dd, Dd, Dd/KS, acc);
    proj_epilogue(acc, bv, g_vhi, g_vlo, m0, n0, true);
}

__global__ void __launch_bounds__(256, 2) mma_scores_kernel() {
    int b = blockIdx.z;
    int t = blockIdx.x;
    int it = (int)((sqrtf(8.f*t + 1.f) - 1.f) * 0.5f);
    while ((it + 1)*(it + 2)/2 <= t) it++;
    while (it*(it + 1)/2 > t) it--;
    int jt = t - it*(it + 1)/2;
    int i0 = it * 128, j0 = jt * 128;
    float acc[4][4][4] = {};
    mma_mainloop(g_qhi + ((size_t)b*Nn + i0)*Dd, Dd,
                 g_khi + ((size_t)b*Nn + j0)*Dd, g_klo + ((size_t)b*Nn + j0)*Dd, Dd,
                 Dd/KS, acc);
    int tid = threadIdx.x, lane = tid & 31, wid = tid >> 5;
    int rb = (wid >> 2)*64 + (lane >> 2);
    int cb = (wid & 3)*32 + (lane & 3)*2;
    float thr = g_thr[b];
    const float2* qp2 = (const float2*)g_qp + (size_t)b * Nn;
    const float NEG = __int_as_float(0xff800000);
    float2 qj0[4], qj1[4];
#pragma unroll
    for (int bn = 0; bn < 4; bn++) {
        qj0[bn] = qp2[j0 + cb + bn*8];
        qj1[bn] = qp2[j0 + cb + bn*8 + 1];
    }
#pragma unroll
    for (int am = 0; am < 4; am++)
#pragma unroll
    for (int h = 0; h < 2; h++) {
        int gi = i0 + rb + am*16 + h*8;
        float2 qi = qp2[gi];
        float* o = g_w + (size_t)b*Nn*Nn + (size_t)gi*Nn + j0 + cb;
#pragma unroll
        for (int bn = 0; bn < 4; bn++) {
            float r[2];
#pragma unroll
            for (int q = 0; q < 2; q++) {
                int gj = j0 + cb + bn*8 + q;
                float2 qj = q ? qj1[bn] : qj0[bn];
                float dx = qi.x - qj.x, dy = qi.y - qj.y;
                float ds = dx*dx + dy*dy;
                bool ok = (gj <= gi) && (ds <= thr);
                if (ok && dx < 0.f && fabsf(dy) < 1e-3f * (-dx)) {
                    float bias = 0.5f * (1.f + cosf(atan2f(dy, dx)));
                    ok = (bias != 0.f);
                }
                r[q] = ok ? acc[am][bn][2*h+q] * 0.03125f : NEG;
            }
            *(float2*)(o + bn*8) = make_float2(r[0], r[1]);
        }
    }
}

// single-pass register softmax; emits hi fp16 only
__global__ void __launch_bounds__(256) softmax_kernel() {
    __shared__ float red[256];
    int row = blockIdx.x;
    int b = row >> 11, i = row & (Nn - 1);
    const float* s = g_w + (size_t)b*Nn*Nn + (size_t)i*Nn;
    h16* oh = g_whi + (size_t)b*Nn*Nn + (size_t)i*Nn;
    int tid = threadIdx.x;
    int jb = tid * 8;
    const float NEG = __int_as_float(0xff800000);
    float v[8];
#pragma unroll
    for (int k = 0; k < 8; k++) {
        int j = jb + k;
        v[k] = (j <= i) ? s[j] : NEG;
    }
    float mx = v[0];
#pragma unroll
    for (int k = 1; k < 8; k++) mx = fmaxf(mx, v[k]);
    red[tid] = mx; __syncthreads();
    for (int o = 128; o; o >>= 1) {
        if (tid < o) red[tid] = fmaxf(red[tid], red[tid+o]);
        __syncthreads();
    }
    mx = red[0]; __syncthreads();
    float sum = 0.f;
#pragma unroll
    for (int k = 0; k < 8; k++) {
        int j = jb + k;
        float e = (j <= i) ? expf(v[k] - mx) : 0.f;
        v[k] = e; sum += e;
    }
    red[tid] = sum; __syncthreads();
    for (int o = 128; o; o >>= 1) {
        if (tid < o) red[tid] += red[tid+o];
        __syncthreads();
    }
    float inv = 1.f / red[0];
    union { uint4 u; h16 hh[8]; } ph;
#pragma unroll
    for (int k = 0; k < 8; k++) ph.hh[k] = __float2half(v[k] * inv);
    *(uint4*)(oh + jb) = ph.u;
}

__global__ void __launch_bounds__(256, 2) mma_context_kernel() {
    int b = blockIdx.z, m0 = blockIdx.y * 128, n0 = blockIdx.x * 128;
    float acc[4][4][4] = {};
    mma_mainloop(g_whi + ((size_t)b*Nn + m0)*Nn, Nn,
                 g_vThi + ((size_t)b*Dd + n0)*Nn, g_vTlo + ((size_t)b*Dd + n0)*Nn, Nn,
                 (m0 + 128)/KS, acc);
    int tid = threadIdx.x, lane = tid & 31, wid = tid >> 5;
    int rb = (wid >> 2)*64 + (lane >> 2);
    int cb = (wid & 3)*32 + (lane & 3)*2;
#pragma unroll
    for (int am = 0; am < 4; am++)
#pragma unroll
    for (int h = 0; h < 2; h++) {
        int row = b*Nn + m0 + rb + am*16 + h*8;
        h16* oh = g_ctxhi + (size_t)row*Dd + n0 + cb;
#pragma unroll
        for (int bn = 0; bn < 4; bn++)
            *(uint32_t*)(oh + bn*8) = packh(__float2half(acc[am][bn][2*h]),
                                            __float2half(acc[am][bn][2*h+1]));
    }
}

__global__ void __launch_bounds__(256, 2) mma_final_kernel(const float* __restrict__ X,
                                                           const float* __restrict__ bo,
                                                           const float* __restrict__ Wfq,
                                                           const float* __restrict__ bfq,
                                                           float* __restrict__ out) {
    int m0 = blockIdx.y * 128, n0 = blockIdx.x * 128;
    float acc[4][4][4] = {};
    mma_mainloop(g_ctxhi + (size_t)m0*Dd, Dd,
                 g_wohi + (size_t)n0*Dd, g_wolo + (size_t)n0*Dd, Dd, Dd/KS, acc);
    int tid = threadIdx.x, lane = tid & 31, wid = tid >> 5;
    int rb = (wid >> 2)*64 + (lane >> 2);
    int cb = (wid & 3)*32 + (lane & 3)*2;
    float2 bo2[4], bfq2[4]; float4 wf[4];
#pragma unroll
    for (int bn = 0; bn < 4; bn++) {
        int c = n0 + cb + bn*8;
        bo2[bn]  = *(const float2*)(bo  + c);
        bfq2[bn] = *(const float2*)(bfq + c);
        wf[bn]   = *(const float4*)(Wfq + 2*c);
    }
#pragma unroll
    for (int am = 0; am < 4; am++)
#pragma unroll
    for (int h = 0; h < 2; h++) {
        int row = m0 + rb + am*16 + h*8;
        float2 qp = ((const float2*)g_qp)[row];
        float nrm = fmaxf(sqrtf(qp.x*qp.x + qp.y*qp.y), 1e-12f);
        float r0 = qp.x / nrm, r1 = qp.y / nrm;
        const float* hx = X + (size_t)row*Dd + n0 + cb;
        float* o = out + (size_t)row*Dd + n0 + cb;
#pragma unroll
        for (int bn = 0; bn < 4; bn++) {
            float2 hv = *(const float2*)(hx + bn*8);
            float v0 = hv.x + acc[am][bn][2*h]*0.03125f + bo2[bn].x
                     + 0.1f*(r0*wf[bn].x + r1*wf[bn].y + bfq2[bn].x);
            float v1 = hv.y + acc[am][bn][2*h+1]*0.03125f + bo2[bn].y
                     + 0.1f*(r0*wf[bn].z + r1*wf[bn].w + bfq2[bn].y);
            *(float2*)(o + bn*8) = make_float2(v0, v1);
        }
    }
}

// ---------------- launch ----------------------------------------------------
extern "C" void kernel_launch(void* const* d_in, const int* in_sizes, int n_in,
                              void* d_out, int out_size) {
    const float* X   = (const float*)d_in[0];
    const float* Wq  = (const float*)d_in[1];
    const float* bq  = (const float*)d_in[2];
    const float* Wk  = (const float*)d_in[3];
    const float* bk  = (const float*)d_in[4];
    const float* Wv  = (const float*)d_in[5];
    const float* bv  = (const float*)d_in[6];
    const float* Wo  = (const float*)d_in[7];
    const float* bo  = (const float*)d_in[8];
    const float* Wtq = (const float*)d_in[9];
    const float* btq = (const float*)d_in[10];
    const float* Wfq = (const float*)d_in[11];
    const float* bfq = (const float*)d_in[12];
    float* out = (float*)d_out;

    static bool init_done = false;
    static bool use_streams = false;
    static cudaStream_t sA, sB, sC;
    static cudaEvent_t evRoot, evX, evA, evB, evC;
    if (!init_done) {
        cudaFuncSetAttribute(mma_qk_kernel,      cudaFuncAttributeMaxDynamicSharedMemorySize, SMEM_BYTES);
        cudaFuncSetAttribute(mma_v_kernel,       cudaFuncAttributeMaxDynamicSharedMemorySize, SMEM_BYTES);
        cudaFuncSetAttribute(mma_scores_kernel,  cudaFuncAttributeMaxDynamicSharedMemorySize, SMEM_BYTES);
        cudaFuncSetAttribute(mma_context_kernel, cudaFuncAttributeMaxDynamicSharedMemorySize, SMEM_BYTES);
        cudaFuncSetAttribute(mma_final_kernel,   cudaFuncAttributeMaxDynamicSharedMemorySize, SMEM_BYTES);
        bool ok = true;
        ok &= (cudaStreamCreateWithFlags(&sA, cudaStreamNonBlocking) == cudaSuccess);
        ok &= (cudaStreamCreateWithFlags(&sB, cudaStreamNonBlocking) == cudaSuccess);
        ok &= (cudaStreamCreateWithFlags(&sC, cudaStreamNonBlocking) == cudaSuccess);
        ok &= (cudaEventCreateWithFlags(&evRoot, cudaEventDisableTiming) == cudaSuccess);
        ok &= (cudaEventCreateWithFlags(&evX,    cudaEventDisableTiming) == cudaSuccess);
        ok &= (cudaEventCreateWithFlags(&evA,    cudaEventDisableTiming) == cudaSuccess);
        ok &= (cudaEventCreateWithFlags(&evB,    cudaEventDisableTiming) == cudaSuccess);
        ok &= (cudaEventCreateWithFlags(&evC,    cudaEventDisableTiming) == cudaSuccess);
        use_streams = ok;
        init_done = true;
    }

    h16 *xhi, *wqh, *wql, *wkh, *wkl, *wvh, *wvl, *woh, *wol;
    cudaGetSymbolAddress((void**)&xhi, g_xhi);
    cudaGetSymbolAddress((void**)&wqh, g_wqhi); cudaGetSymbolAddress((void**)&wql, g_wqlo);
    cudaGetSymbolAddress((void**)&wkh, g_wkhi); cudaGetSymbolAddress((void**)&wkl, g_wklo);
    cudaGetSymbolAddress((void**)&wvh, g_wvhi); cudaGetSymbolAddress((void**)&wvl, g_wvlo);
    cudaGetSymbolAddress((void**)&woh, g_wohi); cudaGetSymbolAddress((void**)&wol, g_wolo);

    int n4x = (int)((size_t)Mm*Dd/4), n4w = Dd*Dd/4;
    const float WSCALE = 32.f;

    if (use_streams) {
        cudaEventRecord(evRoot, 0);
        cudaStreamWaitEvent(sA, evRoot, 0);
        qp_kernel<<<Mm/8, 256, 0, sA>>>(X, Wtq, btq);
        stats_kernel<<<dim3(Nn, Bb), 256, 0, sA>>>();
        thr_kernel<<<1, 32, 0, sA>>>();
        cudaEventRecord(evA, sA);
        cudaStreamWaitEvent(sB, evRoot, 0);
        cvt_kernel<<<(n4w + 255)/256, 256, 0, sB>>>(Wo, woh, wol, WSCALE, n4w);
        cudaEventRecord(evB, sB);
        cvt_hi_kernel<<<(n4x + 255)/256, 256>>>(X, xhi, n4x);
        cudaEventRecord(evX, 0);
        cvt_kernel<<<(n4w + 255)/256, 256>>>(Wq, wqh, wql, WSCALE, n4w);
        cvt_kernel<<<(n4w + 255)/256, 256>>>(Wk, wkh, wkl, WSCALE, n4w);
        cudaStreamWaitEvent(sC, evX, 0);
        cvt_kernel<<<(n4w + 255)/256, 256, 0, sC>>>(Wv, wvh, wvl, WSCALE, n4w);
        mma_v_kernel<<<dim3(Dd/128, Mm/128), 256, SMEM_BYTES, sC>>>(bv);
        vtrans_kernel<<<dim3(Nn/64, Dd/64, Bb*2), 256, 0, sC>>>();
        cudaEventRecord(evC, sC);
        mma_qk_kernel<<<dim3(Dd/128, Mm/128, 2), 256, SMEM_BYTES>>>(bq, bk);
        cudaStreamWaitEvent(0, evA, 0);
        mma_scores_kernel<<<dim3(136, 1, Bb), 256, SMEM_BYTES>>>();
        softmax_kernel<<<Mm, 256>>>();
        cudaStreamWaitEvent(0, evC, 0);
        mma_context_kernel<<<dim3(Dd/128, Nn/128, Bb), 256, SMEM_BYTES>>>();
        cudaStreamWaitEvent(0, evB, 0);
        mma_final_kernel<<<dim3(Dd/128, Mm/128), 256, SMEM_BYTES>>>(X, bo, Wfq, bfq, out);
    } else {
        qp_kernel<<<Mm/8, 256>>>(X, Wtq, btq);
        stats_kernel<<<dim3(Nn, Bb), 256>>>();
        thr_kernel<<<1, 32>>>();
        cvt_hi_kernel<<<(n4x + 255)/256, 256>>>(X, xhi, n4x);
        cvt_kernel<<<(n4w + 255)/256, 256>>>(Wq, wqh, wql, WSCALE, n4w);
        cvt_kernel<<<(n4w + 255)/256, 256>>>(Wk, wkh, wkl, WSCALE, n4w);
        cvt_kernel<<<(n4w + 255)/256, 256>>>(Wv, wvh, wvl, WSCALE, n4w);
        cvt_kernel<<<(n4w + 255)/256, 256>>>(Wo, woh, wol, WSCALE, n4w);
        mma_qk_kernel<<<dim3(Dd/128, Mm/128, 2), 256, SMEM_BYTES>>>(bq, bk);
        mma_v_kernel<<<dim3(Dd/128, Mm/128), 256, SMEM_BYTES>>>(bv);
        vtrans_kernel<<<dim3(Nn/64, Dd/64, Bb*2), 256>>>();
        mma_scores_kernel<<<dim3(136, 1, Bb), 256, SMEM_BYTES>>>();
        softmax_kernel<<<Mm, 256>>>();
        mma_context_kernel<<<dim3(Dd/128, Nn/128, Bb), 256, SMEM_BYTES>>>();
        mma_final_kernel<<<dim3(Dd/128, Mm/128), 256, SMEM_BYTES>>>(X, bo, Wfq, bfq, out);
    }
}

// round 9
// speedup vs baseline: 6.6834x; 1.5684x over previous
#include <cuda_runtime.h>
#include <cuda_fp16.h>
#include <math.h>
#include <stdint.h>

#define Bb 4
#define Nn 2048
#define Dd 1024
#define Mm (Bb*Nn)

typedef __half h16;

// ---------------- scratch (static device globals) ---------------------------
__device__ h16 g_xhi[(size_t)Mm*Dd];
__device__ h16 g_wqhi[Dd*Dd], g_wkhi[Dd*Dd], g_wvhi[Dd*Dd], g_wohi[Dd*Dd]; // x32
__device__ h16 g_qhi[(size_t)Mm*Dd], g_khi[(size_t)Mm*Dd];
__device__ h16 g_vhi[(size_t)Mm*Dd];
__device__ h16 g_vThi[(size_t)Bb*Dd*Nn];
__device__ h16 g_ctxhi[(size_t)Mm*Dd];
__device__ h16 g_whi[(size_t)Bb*Nn*Nn];
__device__ float  g_w [(size_t)Bb*Nn*Nn];
__device__ float  g_qp[Mm*2];
__device__ double g_s1[Bb], g_s2[Bb];
__device__ float  g_thr[Bb];

// ---------------- PTX helpers -----------------------------------------------
__device__ __forceinline__ uint32_t smem_u32(const void* p) {
    uint32_t a;
    asm("{ .reg .u64 t; cvta.to.shared.u64 t, %1; cvt.u32.u64 %0, t; }" : "=r"(a) : "l"(p));
    return a;
}
#define CP16(dst, src) \
    asm volatile("cp.async.cg.shared.global [%0], [%1], 16;" :: "r"(dst), "l"(src) : "memory")
#define CP_COMMIT() asm volatile("cp.async.commit_group;" ::: "memory")

#define LDM_X4(r, addr) \
    asm volatile("ldmatrix.sync.aligned.m8n8.x4.shared.b16 {%0,%1,%2,%3}, [%4];" \
        : "=r"((r)[0]), "=r"((r)[1]), "=r"((r)[2]), "=r"((r)[3]) : "r"(addr))

#define MMA_F16(d, a, b) \
    asm volatile("mma.sync.aligned.m16n8k16.row.col.f32.f16.f16.f32 " \
        "{%0,%1,%2,%3}, {%4,%5,%6,%7}, {%8,%9}, {%0,%1,%2,%3};" \
        : "+f"((d)[0]), "+f"((d)[1]), "+f"((d)[2]), "+f"((d)[3]) \
        : "r"((a)[0]), "r"((a)[1]), "r"((a)[2]), "r"((a)[3]), "r"((b)[0]), "r"((b)[1]))

// ---------------- tiling constants ------------------------------------------
#define KS 32
#define LDSB 64
#define TILEB (128*LDSB)          // 8192 B
#define STAGEB (2*TILEB)          // 16384 B: A, B
#define NSTAGE 4
#define SMEM_BYTES (NSTAGE*STAGEB)   // 65536 B

__device__ __forceinline__ uint32_t swz(uint32_t r, uint32_t c) {
    return (uint32_t)r * LDSB + ((c ^ ((r + (r >> 2)) & 3)) << 4);
}

// ---------------- stage load via cp.async -----------------------------------
__device__ __forceinline__ void load_stage(uint32_t sb,
        const h16* __restrict__ A, size_t lda,
        const h16* __restrict__ B, size_t ldb, int kt) {
    int tid = threadIdx.x;
    int r0 = tid >> 2, seg = tid & 3;
    size_t koff = (size_t)kt * KS + seg * 8;
#pragma unroll
    for (int p = 0; p < 2; p++) {
        int row = r0 + p * 64;
        uint32_t ds = sb + swz((uint32_t)row, (uint32_t)seg);
        CP16(ds,         A + (size_t)row * lda + koff);
        CP16(ds + TILEB, B + (size_t)row * ldb + koff);
    }
    CP_COMMIT();
}

// ---------------- per-stage compute: 1-term fp16 -----------------------------
__device__ __forceinline__ void compute_stage(uint32_t sb, int wm, int wn, int lane,
                                              float acc[4][4][4]) {
    int arow = lane & 15;
    int acol = (lane >> 4) << 3;
    int brow = (lane & 7) + ((lane >> 4) << 3);
    int bcol = ((lane >> 3) & 1) << 3;
#pragma unroll
    for (int ks = 0; ks < 2; ks++) {
        uint32_t ah[4][4];
        uint32_t ca = (uint32_t)(2*ks + (acol >> 3));
#pragma unroll
        for (int am = 0; am < 4; am++) {
            uint32_t ad = sb + swz((uint32_t)(wm*64 + am*16 + arow), ca);
            LDM_X4(ah[am], ad);
        }
        uint32_t bh[4][2];
        uint32_t cbk = (uint32_t)(2*ks + (bcol >> 3));
#pragma unroll
        for (int bp = 0; bp < 2; bp++) {
            uint32_t bd = sb + TILEB + swz((uint32_t)(wn*32 + bp*16 + brow), cbk);
            uint32_t t[4];
            LDM_X4(t, bd);
            bh[2*bp][0] = t[0]; bh[2*bp][1] = t[1];
            bh[2*bp+1][0] = t[2]; bh[2*bp+1][1] = t[3];
        }
#pragma unroll
        for (int am = 0; am < 4; am++)
#pragma unroll
            for (int bn = 0; bn < 4; bn++)
                MMA_F16(acc[am][bn], ah[am], bh[bn]);
    }
}

// D[128,128] fp32 = A[128,K] * B[128,K]^T, 4-stage cp.async pipeline
__device__ __forceinline__ void mma_mainloop(
        const h16* __restrict__ A, size_t lda,
        const h16* __restrict__ B, size_t ldb,
        int kIters, float acc[4][4][4]) {
    extern __shared__ __align__(16) char smem[];
    uint32_t sb = smem_u32(smem);
    int tid = threadIdx.x, lane = tid & 31, wid = tid >> 5;
    int wm = wid >> 2, wn = wid & 3;
    load_stage(sb, A, lda, B, ldb, 0);
    if (kIters > 1) load_stage(sb + STAGEB,   A, lda, B, ldb, 1);
    if (kIters > 2) load_stage(sb + 2*STAGEB, A, lda, B, ldb, 2);
    for (int kt = 0; kt < kIters; kt++) {
        if (kt + 2 < kIters)      asm volatile("cp.async.wait_group 2;" ::: "memory");
        else if (kt + 1 < kIters) asm volatile("cp.async.wait_group 1;" ::: "memory");
        else                      asm volatile("cp.async.wait_group 0;" ::: "memory");
        __syncthreads();
        if (kt + 3 < kIters)
            load_stage(sb + (uint32_t)((kt+3) & 3) * STAGEB, A, lda, B, ldb, kt + 3);
        compute_stage(sb + (uint32_t)(kt & 3) * STAGEB, wm, wn, lane, acc);
    }
}

__device__ __forceinline__ uint32_t packh(h16 a, h16 b) {
    union { __half2 h; uint32_t u; } c;
    c.h = __halves2half2(a, b);
    return c.u;
}

// ---------------- conversion kernel (hi only, optional scale) ----------------
__global__ void __launch_bounds__(256) cvt_hi_kernel(const float* __restrict__ src,
                                                     h16* __restrict__ hi,
                                                     float scale, int n4) {
    int i = blockIdx.x * 256 + threadIdx.x;
    if (i >= n4) return;
    float4 v = ((const float4*)src)[i];
    *(uint2*)(hi + 4*(size_t)i) =
        make_uint2(packh(__float2half(v.x*scale), __float2half(v.y*scale)),
                   packh(__float2half(v.z*scale), __float2half(v.w*scale)));
}

// ---------------- small SIMT kernels ----------------------------------------
__global__ void __launch_bounds__(256) qp_kernel(const float* __restrict__ X,
                                                 const float* __restrict__ Wtq,
                                                 const float* __restrict__ btq) {
    if (blockIdx.x == 0 && threadIdx.x < Bb) {
        g_s1[threadIdx.x] = 0.0; g_s2[threadIdx.x] = 0.0;
    }
    int warp = threadIdx.x >> 5, lane = threadIdx.x & 31;
    int row = blockIdx.x * 8 + warp;
    const float* x = X + (size_t)row * Dd;
    float s0 = 0.f, s1 = 0.f;
    for (int k = lane * 4; k < Dd; k += 128) {
        float4 xv = *(const float4*)(x + k);
        float4 w0 = *(const float4*)(Wtq + k);
        float4 w1 = *(const float4*)(Wtq + Dd + k);
        s0 += xv.x*w0.x + xv.y*w0.y + xv.z*w0.z + xv.w*w0.w;
        s1 += xv.x*w1.x + xv.y*w1.y + xv.z*w1.z + xv.w*w1.w;
    }
#pragma unroll
    for (int o = 16; o; o >>= 1) {
        s0 += __shfl_xor_sync(0xffffffffu, s0, o);
        s1 += __shfl_xor_sync(0xffffffffu, s1, o);
    }
    if (lane == 0) { g_qp[row*2+0] = s0 + btq[0]; g_qp[row*2+1] = s1 + btq[1]; }
}
__global__ void __launch_bounds__(256) stats_kernel() {
    __shared__ float r1[256], r2[256];
    int b = blockIdx.y, i = blockIdx.x, tid = threadIdx.x;
    const float2* qp2 = (const float2*)g_qp + (size_t)b * Nn;
    float2 qi = qp2[i];
    float s1 = 0.f, s2 = 0.f;
    for (int j = tid; j < Nn; j += 256) {
        float2 qj = qp2[j];
        float dx = qi.x - qj.x, dy = qi.y - qj.y;
        float d = dx*dx + dy*dy;
        s1 += d; s2 += d*d;
    }
    r1[tid] = s1; r2[tid] = s2; __syncthreads();
    for (int o = 128; o; o >>= 1) {
        if (tid < o) { r1[tid] += r1[tid+o]; r2[tid] += r2[tid+o]; }
        __syncthreads();
    }
    if (tid == 0) { atomicAdd(&g_s1[b], (double)r1[0]); atomicAdd(&g_s2[b], (double)r2[0]); }
}
__global__ void thr_kernel() {
    int b = threadIdx.x;
    if (b < Bb) {
        double M = (double)Nn * (double)Nn;
        double mean = g_s1[b] / M;
        double var = (g_s2[b] - g_s1[b]*g_s1[b]/M) / (M - 1.0);
        if (var < 0.0) var = 0.0;
        g_thr[b] = (float)(mean + 1.25 * sqrt(var));
    }
}

// ---------------- v transpose (hi only) --------------------------------------
__global__ void __launch_bounds__(256) vtrans_kernel() {
    __shared__ h16 t[64][66];
    int b = blockIdx.z;
    int tok0 = blockIdx.x * 64, d0 = blockIdx.y * 64;
    int tid = threadIdx.x, r = tid >> 2, seg = tid & 3;
    const h16* sp = g_vhi + ((size_t)(b*Nn + tok0 + r)) * Dd + d0;
#pragma unroll
    for (int p = 0; p < 2; p++) {
        int c0 = (seg + 4*p) * 8;
        union { uint4 u; h16 h[8]; } v;
        v.u = *(const uint4*)(sp + c0);
#pragma unroll
        for (int e = 0; e < 8; e++) t[r][c0 + e] = v.h[e];
    }
    __syncthreads();
    h16* dp = g_vThi + (size_t)b*Dd*Nn + (size_t)(d0 + r)*Nn + tok0;
#pragma unroll
    for (int p = 0; p < 2; p++) {
        int c0 = (seg + 4*p) * 8;
        union { uint4 u; h16 h[8]; } v;
#pragma unroll
        for (int e = 0; e < 8; e++) v.h[e] = t[c0 + e][r];
        *(uint4*)(dp + c0) = v.u;
    }
}

// ---------------- GEMM kernels ----------------------------------------------
__device__ __forceinline__ void proj_epilogue(float acc[4][4][4], const float* bias,
                                              h16* OH, int m0, int n0) {
    int tid = threadIdx.x, lane = tid & 31, wid = tid >> 5;
    int rb = (wid >> 2)*64 + (lane >> 2);
    int cb = (wid & 3)*32 + (lane & 3)*2;
    float2 b2[4];
#pragma unroll
    for (int bn = 0; bn < 4; bn++) b2[bn] = *(const float2*)(bias + n0 + cb + bn*8);
#pragma unroll
    for (int am = 0; am < 4; am++)
#pragma unroll
    for (int h = 0; h < 2; h++) {
        int row = m0 + rb + am*16 + h*8;
        h16* oh = OH + (size_t)row*Dd + n0 + cb;
#pragma unroll
        for (int bn = 0; bn < 4; bn++) {
            float v0 = acc[am][bn][2*h]   * 0.03125f + b2[bn].x;
            float v1 = acc[am][bn][2*h+1] * 0.03125f + b2[bn].y;
            *(uint32_t*)(oh + bn*8) = packh(__float2half(v0), __float2half(v1));
        }
    }
}

__global__ void __launch_bounds__(256, 2) mma_qk_kernel(const float* __restrict__ bq,
                                                        const float* __restrict__ bk) {
    int z = blockIdx.z;
    const h16* Whi = z ? g_wkhi : g_wqhi;
    const float* bias = z ? bk : bq;
    int m0 = blockIdx.y * 128, n0 = blockIdx.x * 128;
    float acc[4][4][4] = {};
    mma_mainloop(g_xhi + (size_t)m0*Dd, Dd, Whi + (size_t)n0*Dd, Dd, Dd/KS, acc);
    proj_epilogue(acc, bias, z ? g_khi : g_qhi, m0, n0);
}

__global__ void __launch_bounds__(256, 2) mma_v_kernel(const float* __restrict__ bv) {
    int m0 = blockIdx.y * 128, n0 = blockIdx.x * 128;
    float acc[4][4][4] = {};
    mma_mainloop(g_xhi + (size_t)m0*Dd, Dd, g_wvhi + (size_t)n0*Dd, Dd, Dd/KS, acc);
    proj_epilogue(acc, bv, g_vhi, m0, n0);
}

__global__ void __launch_bounds__(256, 2) mma_scores_kernel() {
    int b = blockIdx.z;
    int t = blockIdx.x;
    int it = (int)((sqrtf(8.f*t + 1.f) - 1.f) * 0.5f);
    while ((it + 1)*(it + 2)/2 <= t) it++;
    while (it*(it + 1)/2 > t) it--;
    int jt = t - it*(it + 1)/2;
    int i0 = it * 128, j0 = jt * 128;
    float acc[4][4][4] = {};
    mma_mainloop(g_qhi + ((size_t)b*Nn + i0)*Dd, Dd,
                 g_khi + ((size_t)b*Nn + j0)*Dd, Dd, Dd/KS, acc);
    int tid = threadIdx.x, lane = tid & 31, wid = tid >> 5;
    int rb = (wid >> 2)*64 + (lane >> 2);
    int cb = (wid & 3)*32 + (lane & 3)*2;
    float thr = g_thr[b];
    const float2* qp2 = (const float2*)g_qp + (size_t)b * Nn;
    const float NEG = __int_as_float(0xff800000);
    float2 qj0[4], qj1[4];
#pragma unroll
    for (int bn = 0; bn < 4; bn++) {
        qj0[bn] = qp2[j0 + cb + bn*8];
        qj1[bn] = qp2[j0 + cb + bn*8 + 1];
    }
#pragma unroll
    for (int am = 0; am < 4; am++)
#pragma unroll
    for (int h = 0; h < 2; h++) {
        int gi = i0 + rb + am*16 + h*8;
        float2 qi = qp2[gi];
        float* o = g_w + (size_t)b*Nn*Nn + (size_t)gi*Nn + j0 + cb;
#pragma unroll
        for (int bn = 0; bn < 4; bn++) {
            float r[2];
#pragma unroll
            for (int q = 0; q < 2; q++) {
                int gj = j0 + cb + bn*8 + q;
                float2 qj = q ? qj1[bn] : qj0[bn];
                float dx = qi.x - qj.x, dy = qi.y - qj.y;
                float ds = dx*dx + dy*dy;
                bool ok = (gj <= gi) && (ds <= thr);
                if (ok && dx < 0.f && fabsf(dy) < 1e-3f * (-dx)) {
                    float bias = 0.5f * (1.f + cosf(atan2f(dy, dx)));
                    ok = (bias != 0.f);
                }
                r[q] = ok ? acc[am][bn][2*h+q] * 0.03125f : NEG;
            }
            *(float2*)(o + bn*8) = make_float2(r[0], r[1]);
        }
    }
}

__global__ void __launch_bounds__(256) softmax_kernel() {
    __shared__ float red[256];
    int row = blockIdx.x;
    int b = row >> 11, i = row & (Nn - 1);
    const float* s = g_w + (size_t)b*Nn*Nn + (size_t)i*Nn;
    h16* oh = g_whi + (size_t)b*Nn*Nn + (size_t)i*Nn;
    int tid = threadIdx.x;
    int jb = tid * 8;
    const float NEG = __int_as_float(0xff800000);
    float v[8];
#pragma unroll
    for (int k = 0; k < 8; k++) {
        int j = jb + k;
        v[k] = (j <= i) ? s[j] : NEG;
    }
    float mx = v[0];
#pragma unroll
    for (int k = 1; k < 8; k++) mx = fmaxf(mx, v[k]);
    red[tid] = mx; __syncthreads();
    for (int o = 128; o; o >>= 1) {
        if (tid < o) red[tid] = fmaxf(red[tid], red[tid+o]);
        __syncthreads();
    }
    mx = red[0]; __syncthreads();
    float sum = 0.f;
#pragma unroll
    for (int k = 0; k < 8; k++) {
        int j = jb + k;
        float e = (j <= i) ? expf(v[k] - mx) : 0.f;
        v[k] = e; sum += e;
    }
    red[tid] = sum; __syncthreads();
    for (int o = 128; o; o >>= 1) {
        if (tid < o) red[tid] += red[tid+o];
        __syncthreads();
    }
    float inv = 1.f / red[0];
    union { uint4 u; h16 hh[8]; } ph;
#pragma unroll
    for (int k = 0; k < 8; k++) ph.hh[k] = __float2half(v[k] * inv);
    *(uint4*)(oh + jb) = ph.u;
}

__global__ void __launch_bounds__(256, 2) mma_context_kernel() {
    int b = blockIdx.z, m0 = blockIdx.y * 128, n0 = blockIdx.x * 128;
    float acc[4][4][4] = {};
    mma_mainloop(g_whi + ((size_t)b*Nn + m0)*Nn, Nn,
                 g_vThi + ((size_t)b*Dd + n0)*Nn, Nn, (m0 + 128)/KS, acc);
    int tid = threadIdx.x, lane = tid & 31, wid = tid >> 5;
    int rb = (wid >> 2)*64 + (lane >> 2);
    int cb = (wid & 3)*32 + (lane & 3)*2;
#pragma unroll
    for (int am = 0; am < 4; am++)
#pragma unroll
    for (int h = 0; h < 2; h++) {
        int row = b*Nn + m0 + rb + am*16 + h*8;
        h16* oh = g_ctxhi + (size_t)row*Dd + n0 + cb;
#pragma unroll
        for (int bn = 0; bn < 4; bn++)
            *(uint32_t*)(oh + bn*8) = packh(__float2half(acc[am][bn][2*h]),
                                            __float2half(acc[am][bn][2*h+1]));
    }
}

__global__ void __launch_bounds__(256, 2) mma_final_kernel(const float* __restrict__ X,
                                                           const float* __restrict__ bo,
                                                           const float* __restrict__ Wfq,
                                                           const float* __restrict__ bfq,
                                                           float* __restrict__ out) {
    int m0 = blockIdx.y * 128, n0 = blockIdx.x * 128;
    float acc[4][4][4] = {};
    mma_mainloop(g_ctxhi + (size_t)m0*Dd, Dd, g_wohi + (size_t)n0*Dd, Dd, Dd/KS, acc);
    int tid = threadIdx.x, lane = tid & 31, wid = tid >> 5;
    int rb = (wid >> 2)*64 + (lane >> 2);
    int cb = (wid & 3)*32 + (lane & 3)*2;
    float2 bo2[4], bfq2[4]; float4 wf[4];
#pragma unroll
    for (int bn = 0; bn < 4; bn++) {
        int c = n0 + cb + bn*8;
        bo2[bn]  = *(const float2*)(bo  + c);
        bfq2[bn] = *(const float2*)(bfq + c);
        wf[bn]   = *(const float4*)(Wfq + 2*c);
    }
#pragma unroll
    for (int am = 0; am < 4; am++)
#pragma unroll
    for (int h = 0; h < 2; h++) {
        int row = m0 + rb + am*16 + h*8;
        float2 qp = ((const float2*)g_qp)[row];
        float nrm = fmaxf(sqrtf(qp.x*qp.x + qp.y*qp.y), 1e-12f);
        float r0 = qp.x / nrm, r1 = qp.y / nrm;
        const float* hx = X + (size_t)row*Dd + n0 + cb;
        float* o = out + (size_t)row*Dd + n0 + cb;
#pragma unroll
        for (int bn = 0; bn < 4; bn++) {
            float2 hv = *(const float2*)(hx + bn*8);
            float v0 = hv.x + acc[am][bn][2*h]*0.03125f + bo2[bn].x
                     + 0.1f*(r0*wf[bn].x + r1*wf[bn].y + bfq2[bn].x);
            float v1 = hv.y + acc[am][bn][2*h+1]*0.03125f + bo2[bn].y
                     + 0.1f*(r0*wf[bn].z + r1*wf[bn].w + bfq2[bn].y);
            *(float2*)(o + bn*8) = make_float2(v0, v1);
        }
    }
}

// ---------------- launch ----------------------------------------------------
extern "C" void kernel_launch(void* const* d_in, const int* in_sizes, int n_in,
                              void* d_out, int out_size) {
    const float* X   = (const float*)d_in[0];
    const float* Wq  = (const float*)d_in[1];
    const float* bq  = (const float*)d_in[2];
    const float* Wk  = (const float*)d_in[3];
    const float* bk  = (const float*)d_in[4];
    const float* Wv  = (const float*)d_in[5];
    const float* bv  = (const float*)d_in[6];
    const float* Wo  = (const float*)d_in[7];
    const float* bo  = (const float*)d_in[8];
    const float* Wtq = (const float*)d_in[9];
    const float* btq = (const float*)d_in[10];
    const float* Wfq = (const float*)d_in[11];
    const float* bfq = (const float*)d_in[12];
    float* out = (float*)d_out;

    static bool init_done = false;
    static bool use_streams = false;
    static cudaStream_t sA, sB, sC;
    static cudaEvent_t evRoot, evX, evA, evB, evC;
    if (!init_done) {
        cudaFuncSetAttribute(mma_qk_kernel,      cudaFuncAttributeMaxDynamicSharedMemorySize, SMEM_BYTES);
        cudaFuncSetAttribute(mma_v_kernel,       cudaFuncAttributeMaxDynamicSharedMemorySize, SMEM_BYTES);
        cudaFuncSetAttribute(mma_scores_kernel,  cudaFuncAttributeMaxDynamicSharedMemorySize, SMEM_BYTES);
        cudaFuncSetAttribute(mma_context_kernel, cudaFuncAttributeMaxDynamicSharedMemorySize, SMEM_BYTES);
        cudaFuncSetAttribute(mma_final_kernel,   cudaFuncAttributeMaxDynamicSharedMemorySize, SMEM_BYTES);
        bool ok = true;
        ok &= (cudaStreamCreateWithFlags(&sA, cudaStreamNonBlocking) == cudaSuccess);
        ok &= (cudaStreamCreateWithFlags(&sB, cudaStreamNonBlocking) == cudaSuccess);
        ok &= (cudaStreamCreateWithFlags(&sC, cudaStreamNonBlocking) == cudaSuccess);
        ok &= (cudaEventCreateWithFlags(&evRoot, cudaEventDisableTiming) == cudaSuccess);
        ok &= (cudaEventCreateWithFlags(&evX,    cudaEventDisableTiming) == cudaSuccess);
        ok &= (cudaEventCreateWithFlags(&evA,    cudaEventDisableTiming) == cudaSuccess);
        ok &= (cudaEventCreateWithFlags(&evB,    cudaEventDisableTiming) == cudaSuccess);
        ok &= (cudaEventCreateWithFlags(&evC,    cudaEventDisableTiming) == cudaSuccess);
        use_streams = ok;
        init_done = true;
    }

    h16 *xhi, *wqh, *wkh, *wvh, *woh;
    cudaGetSymbolAddress((void**)&xhi, g_xhi);
    cudaGetSymbolAddress((void**)&wqh, g_wqhi);
    cudaGetSymbolAddress((void**)&wkh, g_wkhi);
    cudaGetSymbolAddress((void**)&wvh, g_wvhi);
    cudaGetSymbolAddress((void**)&woh, g_wohi);

    int n4x = (int)((size_t)Mm*Dd/4), n4w = Dd*Dd/4;
    const float WSCALE = 32.f;

    if (use_streams) {
        cudaEventRecord(evRoot, 0);
        cudaStreamWaitEvent(sA, evRoot, 0);
        qp_kernel<<<Mm/8, 256, 0, sA>>>(X, Wtq, btq);
        stats_kernel<<<dim3(Nn, Bb), 256, 0, sA>>>();
        thr_kernel<<<1, 32, 0, sA>>>();
        cudaEventRecord(evA, sA);
        cudaStreamWaitEvent(sB, evRoot, 0);
        cvt_hi_kernel<<<(n4w + 255)/256, 256, 0, sB>>>(Wo, woh, WSCALE, n4w);
        cudaEventRecord(evB, sB);
        cvt_hi_kernel<<<(n4x + 255)/256, 256>>>(X, xhi, 1.f, n4x);
        cudaEventRecord(evX, 0);
        cvt_hi_kernel<<<(n4w + 255)/256, 256>>>(Wq, wqh, WSCALE, n4w);
        cvt_hi_kernel<<<(n4w + 255)/256, 256>>>(Wk, wkh, WSCALE, n4w);
        cudaStreamWaitEvent(sC, evX, 0);
        cvt_hi_kernel<<<(n4w + 255)/256, 256, 0, sC>>>(Wv, wvh, WSCALE, n4w);
        mma_v_kernel<<<dim3(Dd/128, Mm/128), 256, SMEM_BYTES, sC>>>(bv);
        vtrans_kernel<<<dim3(Nn/64, Dd/64, Bb), 256, 0, sC>>>();
        cudaEventRecord(evC, sC);
        mma_qk_kernel<<<dim3(Dd/128, Mm/128, 2), 256, SMEM_BYTES>>>(bq, bk);
        cudaStreamWaitEvent(0, evA, 0);
        mma_scores_kernel<<<dim3(136, 1, Bb), 256, SMEM_BYTES>>>();
        softmax_kernel<<<Mm, 256>>>();
        cudaStreamWaitEvent(0, evC, 0);
        mma_context_kernel<<<dim3(Dd/128, Nn/128, Bb), 256, SMEM_BYTES>>>();
        cudaStreamWaitEvent(0, evB, 0);
        mma_final_kernel<<<dim3(Dd/128, Mm/128), 256, SMEM_BYTES>>>(X, bo, Wfq, bfq, out);
    } else {
        qp_kernel<<<Mm/8, 256>>>(X, Wtq, btq);
        stats_kernel<<<dim3(Nn, Bb), 256>>>();
        thr_kernel<<<1, 32>>>();
        cvt_hi_kernel<<<(n4x + 255)/256, 256>>>(X, xhi, 1.f, n4x);
        cvt_hi_kernel<<<(n4w + 255)/256, 256>>>(Wq, wqh, WSCALE, n4w);
        cvt_hi_kernel<<<(n4w + 255)/256, 256>>>(Wk, wkh, WSCALE, n4w);
        cvt_hi_kernel<<<(n4w + 255)/256, 256>>>(Wv, wvh, WSCALE, n4w);
        cvt_hi_kernel<<<(n4w + 255)/256, 256>>>(Wo, woh, WSCALE, n4w);
        mma_qk_kernel<<<dim3(Dd/128, Mm/128, 2), 256, SMEM_BYTES>>>(bq, bk);
        mma_v_kernel<<<dim3(Dd/128, Mm/128), 256, SMEM_BYTES>>>(bv);
        vtrans_kernel<<<dim3(Nn/64, Dd/64, Bb), 256>>>();
        mma_scores_kernel<<<dim3(136, 1, Bb), 256, SMEM_BYTES>>>();
        softmax_kernel<<<Mm, 256>>>();
        mma_context_kernel<<<dim3(Dd/128, Nn/128, Bb), 256, SMEM_BYTES>>>();
        mma_final_kernel<<<dim3(Dd/128, Mm/128), 256, SMEM_BYTES>>>(X, bo, Wfq, bfq, out);
    }
}

// round 13
// speedup vs baseline: 6.7747x; 1.0137x over previous
#include <cuda_runtime.h>
#include <cuda_fp16.h>
#include <math.h>
#include <stdint.h>

#define Bb 4
#define Nn 2048
#define Dd 1024
#define Mm (Bb*Nn)

typedef __half h16;

// ---------------- scratch (static device globals) ---------------------------
__device__ h16 g_xhi[(size_t)Mm*Dd];
__device__ h16 g_wqhi[Dd*Dd], g_wkhi[Dd*Dd], g_wvhi[Dd*Dd], g_wohi[Dd*Dd]; // x32
__device__ h16 g_qhi[(size_t)Mm*Dd], g_khi[(size_t)Mm*Dd];
__device__ h16 g_vhi[(size_t)Mm*Dd];
__device__ h16 g_vThi[(size_t)Bb*Dd*Nn];
__device__ h16 g_ctxhi[(size_t)Mm*Dd];
__device__ h16 g_whi[(size_t)Bb*Nn*Nn];  // fp16 masked scores -> weights (in place)
__device__ float  g_qp[Mm*2];
__device__ double g_s1[Bb], g_s2[Bb];
__device__ float  g_thr[Bb];

// ---------------- PTX helpers -----------------------------------------------
__device__ __forceinline__ uint32_t smem_u32(const void* p) {
    uint32_t a;
    asm("{ .reg .u64 t; cvta.to.shared.u64 t, %1; cvt.u32.u64 %0, t; }" : "=r"(a) : "l"(p));
    return a;
}
#define CP16(dst, src) \
    asm volatile("cp.async.cg.shared.global [%0], [%1], 16;" :: "r"(dst), "l"(src) : "memory")
#define CP_COMMIT() asm volatile("cp.async.commit_group;" ::: "memory")

#define LDM_X4(r, addr) \
    asm volatile("ldmatrix.sync.aligned.m8n8.x4.shared.b16 {%0,%1,%2,%3}, [%4];" \
        : "=r"((r)[0]), "=r"((r)[1]), "=r"((r)[2]), "=r"((r)[3]) : "r"(addr))

#define MMA_F16(d, a, b) \
    asm volatile("mma.sync.aligned.m16n8k16.row.col.f32.f16.f16.f32 " \
        "{%0,%1,%2,%3}, {%4,%5,%6,%7}, {%8,%9}, {%0,%1,%2,%3};" \
        : "+f"((d)[0]), "+f"((d)[1]), "+f"((d)[2]), "+f"((d)[3]) \
        : "r"((a)[0]), "r"((a)[1]), "r"((a)[2]), "r"((a)[3]), "r"((b)[0]), "r"((b)[1]))

// ---------------- tiling constants ------------------------------------------
#define KS 32
#define LDSB 64
#define TILEB (128*LDSB)          // 8192 B
#define STAGEB (2*TILEB)          // 16384 B: A, B
#define NSTAGE 4
#define SMEM_BYTES (NSTAGE*STAGEB)   // 65536 B

__device__ __forceinline__ uint32_t swz(uint32_t r, uint32_t c) {
    return (uint32_t)r * LDSB + ((c ^ ((r + (r >> 2)) & 3)) << 4);
}

// ---------------- stage load via cp.async -----------------------------------
__device__ __forceinline__ void load_stage(uint32_t sb,
        const h16* __restrict__ A, size_t lda,
        const h16* __restrict__ B, size_t ldb, int kt) {
    int tid = threadIdx.x;
    int r0 = tid >> 2, seg = tid & 3;
    size_t koff = (size_t)kt * KS + seg * 8;
#pragma unroll
    for (int p = 0; p < 2; p++) {
        int row = r0 + p * 64;
        uint32_t ds = sb + swz((uint32_t)row, (uint32_t)seg);
        CP16(ds,         A + (size_t)row * lda + koff);
        CP16(ds + TILEB, B + (size_t)row * ldb + koff);
    }
    CP_COMMIT();
}

// ---------------- per-stage compute: 1-term fp16 -----------------------------
__device__ __forceinline__ void compute_stage(uint32_t sb, int wm, int wn, int lane,
                                              float acc[4][4][4]) {
    int arow = lane & 15;
    int acol = (lane >> 4) << 3;
    int brow = (lane & 7) + ((lane >> 4) << 3);
    int bcol = ((lane >> 3) & 1) << 3;
#pragma unroll
    for (int ks = 0; ks < 2; ks++) {
        uint32_t ah[4][4];
        uint32_t ca = (uint32_t)(2*ks + (acol >> 3));
#pragma unroll
        for (int am = 0; am < 4; am++) {
            uint32_t ad = sb + swz((uint32_t)(wm*64 + am*16 + arow), ca);
            LDM_X4(ah[am], ad);
        }
        uint32_t bh[4][2];
        uint32_t cbk = (uint32_t)(2*ks + (bcol >> 3));
#pragma unroll
        for (int bp = 0; bp < 2; bp++) {
            uint32_t bd = sb + TILEB + swz((uint32_t)(wn*32 + bp*16 + brow), cbk);
            uint32_t t[4];
            LDM_X4(t, bd);
            bh[2*bp][0] = t[0]; bh[2*bp][1] = t[1];
            bh[2*bp+1][0] = t[2]; bh[2*bp+1][1] = t[3];
        }
#pragma unroll
        for (int am = 0; am < 4; am++)
#pragma unroll
            for (int bn = 0; bn < 4; bn++)
                MMA_F16(acc[am][bn], ah[am], bh[bn]);
    }
}

// D[128,128] fp32 = A[128,K] * B[128,K]^T, 4-stage cp.async pipeline
__device__ __forceinline__ void mma_mainloop(
        const h16* __restrict__ A, size_t lda,
        const h16* __restrict__ B, size_t ldb,
        int kIters, float acc[4][4][4]) {
    extern __shared__ __align__(16) char smem[];
    uint32_t sb = smem_u32(smem);
    int tid = threadIdx.x, lane = tid & 31, wid = tid >> 5;
    int wm = wid >> 2, wn = wid & 3;
    load_stage(sb, A, lda, B, ldb, 0);
    if (kIters > 1) load_stage(sb + STAGEB,   A, lda, B, ldb, 1);
    if (kIters > 2) load_stage(sb + 2*STAGEB, A, lda, B, ldb, 2);
    for (int kt = 0; kt < kIters; kt++) {
        if (kt + 2 < kIters)      asm volatile("cp.async.wait_group 2;" ::: "memory");
        else if (kt + 1 < kIters) asm volatile("cp.async.wait_group 1;" ::: "memory");
        else                      asm volatile("cp.async.wait_group 0;" ::: "memory");
        __syncthreads();
        if (kt + 3 < kIters)
            load_stage(sb + (uint32_t)((kt+3) & 3) * STAGEB, A, lda, B, ldb, kt + 3);
        compute_stage(sb + (uint32_t)(kt & 3) * STAGEB, wm, wn, lane, acc);
    }
}

__device__ __forceinline__ uint32_t packh(h16 a, h16 b) {
    union { __half2 h; uint32_t u; } c;
    c.h = __halves2half2(a, b);
    return c.u;
}

// ---------------- conversion kernel (hi only, optional scale) ----------------
__global__ void __launch_bounds__(256) cvt_hi_kernel(const float* __restrict__ src,
                                                     h16* __restrict__ hi,
                                                     float scale, int n4) {
    int i = blockIdx.x * 256 + threadIdx.x;
    if (i >= n4) return;
    float4 v = ((const float4*)src)[i];
    *(uint2*)(hi + 4*(size_t)i) =
        make_uint2(packh(__float2half(v.x*scale), __float2half(v.y*scale)),
                   packh(__float2half(v.z*scale), __float2half(v.w*scale)));
}

// ---------------- small SIMT kernels ----------------------------------------
__global__ void __launch_bounds__(256) qp_kernel(const float* __restrict__ X,
                                                 const float* __restrict__ Wtq,
                                                 const float* __restrict__ btq) {
    if (blockIdx.x == 0 && threadIdx.x < Bb) {
        g_s1[threadIdx.x] = 0.0; g_s2[threadIdx.x] = 0.0;
    }
    int warp = threadIdx.x >> 5, lane = threadIdx.x & 31;
    int row = blockIdx.x * 8 + warp;
    const float* x = X + (size_t)row * Dd;
    float s0 = 0.f, s1 = 0.f;
    for (int k = lane * 4; k < Dd; k += 128) {
        float4 xv = *(const float4*)(x + k);
        float4 w0 = *(const float4*)(Wtq + k);
        float4 w1 = *(const float4*)(Wtq + Dd + k);
        s0 += xv.x*w0.x + xv.y*w0.y + xv.z*w0.z + xv.w*w0.w;
        s1 += xv.x*w1.x + xv.y*w1.y + xv.z*w1.z + xv.w*w1.w;
    }
#pragma unroll
    for (int o = 16; o; o >>= 1) {
        s0 += __shfl_xor_sync(0xffffffffu, s0, o);
        s1 += __shfl_xor_sync(0xffffffffu, s1, o);
    }
    if (lane == 0) { g_qp[row*2+0] = s0 + btq[0]; g_qp[row*2+1] = s1 + btq[1]; }
}
__global__ void __launch_bounds__(256) stats_kernel() {
    __shared__ float r1[256], r2[256];
    int b = blockIdx.y, i = blockIdx.x, tid = threadIdx.x;
    const float2* qp2 = (const float2*)g_qp + (size_t)b * Nn;
    float2 qi = qp2[i];
    float s1 = 0.f, s2 = 0.f;
    for (int j = tid; j < Nn; j += 256) {
        float2 qj = qp2[j];
        float dx = qi.x - qj.x, dy = qi.y - qj.y;
        float d = dx*dx + dy*dy;
        s1 += d; s2 += d*d;
    }
    r1[tid] = s1; r2[tid] = s2; __syncthreads();
    for (int o = 128; o; o >>= 1) {
        if (tid < o) { r1[tid] += r1[tid+o]; r2[tid] += r2[tid+o]; }
        __syncthreads();
    }
    if (tid == 0) { atomicAdd(&g_s1[b], (double)r1[0]); atomicAdd(&g_s2[b], (double)r2[0]); }
}
__global__ void thr_kernel() {
    int b = threadIdx.x;
    if (b < Bb) {
        double M = (double)Nn * (double)Nn;
        double mean = g_s1[b] / M;
        double var = (g_s2[b] - g_s1[b]*g_s1[b]/M) / (M - 1.0);
        if (var < 0.0) var = 0.0;
        g_thr[b] = (float)(mean + 1.25 * sqrt(var));
    }
}

// ---------------- v transpose (hi only) --------------------------------------
__global__ void __launch_bounds__(256) vtrans_kernel() {
    __shared__ h16 t[64][66];
    int b = blockIdx.z;
    int tok0 = blockIdx.x * 64, d0 = blockIdx.y * 64;
    int tid = threadIdx.x, r = tid >> 2, seg = tid & 3;
    const h16* sp = g_vhi + ((size_t)(b*Nn + tok0 + r)) * Dd + d0;
#pragma unroll
    for (int p = 0; p < 2; p++) {
        int c0 = (seg + 4*p) * 8;
        union { uint4 u; h16 h[8]; } v;
        v.u = *(const uint4*)(sp + c0);
#pragma unroll
        for (int e = 0; e < 8; e++) t[r][c0 + e] = v.h[e];
    }
    __syncthreads();
    h16* dp = g_vThi + (size_t)b*Dd*Nn + (size_t)(d0 + r)*Nn + tok0;
#pragma unroll
    for (int p = 0; p < 2; p++) {
        int c0 = (seg + 4*p) * 8;
        union { uint4 u; h16 h[8]; } v;
#pragma unroll
        for (int e = 0; e < 8; e++) v.h[e] = t[c0 + e][r];
        *(uint4*)(dp + c0) = v.u;
    }
}

// ---------------- GEMM kernels ----------------------------------------------
__device__ __forceinline__ void proj_epilogue(float acc[4][4][4], const float* bias,
                                              h16* OH, int m0, int n0) {
    int tid = threadIdx.x, lane = tid & 31, wid = tid >> 5;
    int rb = (wid >> 2)*64 + (lane >> 2);
    int cb = (wid & 3)*32 + (lane & 3)*2;
    float2 b2[4];
#pragma unroll
    for (int bn = 0; bn < 4; bn++) b2[bn] = *(const float2*)(bias + n0 + cb + bn*8);
#pragma unroll
    for (int am = 0; am < 4; am++)
#pragma unroll
    for (int h = 0; h < 2; h++) {
        int row = m0 + rb + am*16 + h*8;
        h16* oh = OH + (size_t)row*Dd + n0 + cb;
#pragma unroll
        for (int bn = 0; bn < 4; bn++) {
            float v0 = acc[am][bn][2*h]   * 0.03125f + b2[bn].x;
            float v1 = acc[am][bn][2*h+1] * 0.03125f + b2[bn].y;
            *(uint32_t*)(oh + bn*8) = packh(__float2half(v0), __float2half(v1));
        }
    }
}

__global__ void __launch_bounds__(256, 2) mma_qk_kernel(const float* __restrict__ bq,
                                                        const float* __restrict__ bk) {
    int z = blockIdx.z;
    const h16* Whi = z ? g_wkhi : g_wqhi;
    const float* bias = z ? bk : bq;
    int m0 = blockIdx.y * 128, n0 = blockIdx.x * 128;
    float acc[4][4][4] = {};
    mma_mainloop(g_xhi + (size_t)m0*Dd, Dd, Whi + (size_t)n0*Dd, Dd, Dd/KS, acc);
    proj_epilogue(acc, bias, z ? g_khi : g_qhi, m0, n0);
}

__global__ void __launch_bounds__(256, 2) mma_v_kernel(const float* __restrict__ bv) {
    int m0 = blockIdx.y * 128, n0 = blockIdx.x * 128;
    float acc[4][4][4] = {};
    mma_mainloop(g_xhi + (size_t)m0*Dd, Dd, g_wvhi + (size_t)n0*Dd, Dd, Dd/KS, acc);
    proj_epilogue(acc, bv, g_vhi, m0, n0);
}

// scores -> fp16 masked scores straight into g_whi (in-place softmax buffer)
__global__ void __launch_bounds__(256, 2) mma_scores_kernel() {
    int b = blockIdx.z;
    int t = blockIdx.x;
    int it = (int)((sqrtf(8.f*t + 1.f) - 1.f) * 0.5f);
    while ((it + 1)*(it + 2)/2 <= t) it++;
    while (it*(it + 1)/2 > t) it--;
    int jt = t - it*(it + 1)/2;
    int i0 = it * 128, j0 = jt * 128;
    float acc[4][4][4] = {};
    mma_mainloop(g_qhi + ((size_t)b*Nn + i0)*Dd, Dd,
                 g_khi + ((size_t)b*Nn + j0)*Dd, Dd, Dd/KS, acc);
    int tid = threadIdx.x, lane = tid & 31, wid = tid >> 5;
    int rb = (wid >> 2)*64 + (lane >> 2);
    int cb = (wid & 3)*32 + (lane & 3)*2;
    float thr = g_thr[b];
    const float2* qp2 = (const float2*)g_qp + (size_t)b * Nn;
    const float NEG = __int_as_float(0xff800000);
    float2 qj0[4], qj1[4];
#pragma unroll
    for (int bn = 0; bn < 4; bn++) {
        qj0[bn] = qp2[j0 + cb + bn*8];
        qj1[bn] = qp2[j0 + cb + bn*8 + 1];
    }
#pragma unroll
    for (int am = 0; am < 4; am++)
#pragma unroll
    for (int h = 0; h < 2; h++) {
        int gi = i0 + rb + am*16 + h*8;
        float2 qi = qp2[gi];
        h16* o = g_whi + (size_t)b*Nn*Nn + (size_t)gi*Nn + j0 + cb;
#pragma unroll
        for (int bn = 0; bn < 4; bn++) {
            float r[2];
#pragma unroll
            for (int q = 0; q < 2; q++) {
                int gj = j0 + cb + bn*8 + q;
                float2 qj = q ? qj1[bn] : qj0[bn];
                float dx = qi.x - qj.x, dy = qi.y - qj.y;
                float ds = dx*dx + dy*dy;
                bool ok = (gj <= gi) && (ds <= thr);
                if (ok && dx < 0.f && fabsf(dy) < 1e-3f * (-dx)) {
                    float bias = 0.5f * (1.f + cosf(atan2f(dy, dx)));
                    ok = (bias != 0.f);
                }
                r[q] = ok ? acc[am][bn][2*h+q] * 0.03125f : NEG;
            }
            *(uint32_t*)(o + bn*8) = packh(__float2half(r[0]), __float2half(r[1]));
        }
    }
}

// single-pass softmax: reads fp16 scores, overwrites with fp16 weights (in place)
__global__ void __launch_bounds__(256) softmax_kernel() {
    __shared__ float red[256];
    int row = blockIdx.x;
    int b = row >> 11, i = row & (Nn - 1);
    h16* s = g_whi + (size_t)b*Nn*Nn + (size_t)i*Nn;
    int tid = threadIdx.x;
    int jb = tid * 8;
    const float NEG = __int_as_float(0xff800000);
    union { uint4 u; h16 hh[8]; } in;
    in.u = *(const uint4*)(s + jb);
    float v[8];
#pragma unroll
    for (int k = 0; k < 8; k++) {
        int j = jb + k;
        v[k] = (j <= i) ? __half2float(in.hh[k]) : NEG;
    }
    float mx = v[0];
#pragma unroll
    for (int k = 1; k < 8; k++) mx = fmaxf(mx, v[k]);
    red[tid] = mx; __syncthreads();
    for (int o = 128; o; o >>= 1) {
        if (tid < o) red[tid] = fmaxf(red[tid], red[tid+o]);
        __syncthreads();
    }
    mx = red[0]; __syncthreads();
    float sum = 0.f;
#pragma unroll
    for (int k = 0; k < 8; k++) {
        int j = jb + k;
        float e = (j <= i) ? expf(v[k] - mx) : 0.f;
        v[k] = e; sum += e;
    }
    red[tid] = sum; __syncthreads();
    for (int o = 128; o; o >>= 1) {
        if (tid < o) red[tid] += red[tid+o];
        __syncthreads();
    }
    float inv = 1.f / red[0];
    union { uint4 u; h16 hh[8]; } ph;
#pragma unroll
    for (int k = 0; k < 8; k++) ph.hh[k] = __float2half(v[k] * inv);
    *(uint4*)(s + jb) = ph.u;
}

__global__ void __launch_bounds__(256, 2) mma_context_kernel() {
    int b = blockIdx.z, m0 = blockIdx.y * 128, n0 = blockIdx.x * 128;
    float acc[4][4][4] = {};
    mma_mainloop(g_whi + ((size_t)b*Nn + m0)*Nn, Nn,
                 g_vThi + ((size_t)b*Dd + n0)*Nn, Nn, (m0 + 128)/KS, acc);
    int tid = threadIdx.x, lane = tid & 31, wid = tid >> 5;
    int rb = (wid >> 2)*64 + (lane >> 2);
    int cb = (wid & 3)*32 + (lane & 3)*2;
#pragma unroll
    for (int am = 0; am < 4; am++)
#pragma unroll
    for (int h = 0; h < 2; h++) {
        int row = b*Nn + m0 + rb + am*16 + h*8;
        h16* oh = g_ctxhi + (size_t)row*Dd + n0 + cb;
#pragma unroll
        for (int bn = 0; bn < 4; bn++)
            *(uint32_t*)(oh + bn*8) = packh(__float2half(acc[am][bn][2*h]),
                                            __float2half(acc[am][bn][2*h+1]));
    }
}

__global__ void __launch_bounds__(256, 2) mma_final_kernel(const float* __restrict__ X,
                                                           const float* __restrict__ bo,
                                                           const float* __restrict__ Wfq,
                                                           const float* __restrict__ bfq,
                                                           float* __restrict__ out) {
    int m0 = blockIdx.y * 128, n0 = blockIdx.x * 128;
    float acc[4][4][4] = {};
    mma_mainloop(g_ctxhi + (size_t)m0*Dd, Dd, g_wohi + (size_t)n0*Dd, Dd, Dd/KS, acc);
    int tid = threadIdx.x, lane = tid & 31, wid = tid >> 5;
    int rb = (wid >> 2)*64 + (lane >> 2);
    int cb = (wid & 3)*32 + (lane & 3)*2;
    float2 bo2[4], bfq2[4]; float4 wf[4];
#pragma unroll
    for (int bn = 0; bn < 4; bn++) {
        int c = n0 + cb + bn*8;
        bo2[bn]  = *(const float2*)(bo  + c);
        bfq2[bn] = *(const float2*)(bfq + c);
        wf[bn]   = *(const float4*)(Wfq + 2*c);
    }
#pragma unroll
    for (int am = 0; am < 4; am++)
#pragma unroll
    for (int h = 0; h < 2; h++) {
        int row = m0 + rb + am*16 + h*8;
        float2 qp = ((const float2*)g_qp)[row];
        float nrm = fmaxf(sqrtf(qp.x*qp.x + qp.y*qp.y), 1e-12f);
        float r0 = qp.x / nrm, r1 = qp.y / nrm;
        const float* hx = X + (size_t)row*Dd + n0 + cb;
        float* o = out + (size_t)row*Dd + n0 + cb;
#pragma unroll
        for (int bn = 0; bn < 4; bn++) {
            float2 hv = *(const float2*)(hx + bn*8);
            float v0 = hv.x + acc[am][bn][2*h]*0.03125f + bo2[bn].x
                     + 0.1f*(r0*wf[bn].x + r1*wf[bn].y + bfq2[bn].x);
            float v1 = hv.y + acc[am][bn][2*h+1]*0.03125f + bo2[bn].y
                     + 0.1f*(r0*wf[bn].z + r1*wf[bn].w + bfq2[bn].y);
            *(float2*)(o + bn*8) = make_float2(v0, v1);
        }
    }
}

// ---------------- launch ----------------------------------------------------
extern "C" void kernel_launch(void* const* d_in, const int* in_sizes, int n_in,
                              void* d_out, int out_size) {
    const float* X   = (const float*)d_in[0];
    const float* Wq  = (const float*)d_in[1];
    const float* bq  = (const float*)d_in[2];
    const float* Wk  = (const float*)d_in[3];
    const float* bk  = (const float*)d_in[4];
    const float* Wv  = (const float*)d_in[5];
    const float* bv  = (const float*)d_in[6];
    const float* Wo  = (const float*)d_in[7];
    const float* bo  = (const float*)d_in[8];
    const float* Wtq = (const float*)d_in[9];
    const float* btq = (const float*)d_in[10];
    const float* Wfq = (const float*)d_in[11];
    const float* bfq = (const float*)d_in[12];
    float* out = (float*)d_out;

    static bool init_done = false;
    static bool use_streams = false;
    static cudaStream_t sA, sB, sC;
    static cudaEvent_t evRoot, evX, evA, evB, evC;
    if (!init_done) {
        cudaFuncSetAttribute(mma_qk_kernel,      cudaFuncAttributeMaxDynamicSharedMemorySize, SMEM_BYTES);
        cudaFuncSetAttribute(mma_v_kernel,       cudaFuncAttributeMaxDynamicSharedMemorySize, SMEM_BYTES);
        cudaFuncSetAttribute(mma_scores_kernel,  cudaFuncAttributeMaxDynamicSharedMemorySize, SMEM_BYTES);
        cudaFuncSetAttribute(mma_context_kernel, cudaFuncAttributeMaxDynamicSharedMemorySize, SMEM_BYTES);
        cudaFuncSetAttribute(mma_final_kernel,   cudaFuncAttributeMaxDynamicSharedMemorySize, SMEM_BYTES);
        bool ok = true;
        ok &= (cudaStreamCreateWithFlags(&sA, cudaStreamNonBlocking) == cudaSuccess);
        ok &= (cudaStreamCreateWithFlags(&sB, cudaStreamNonBlocking) == cudaSuccess);
        ok &= (cudaStreamCreateWithFlags(&sC, cudaStreamNonBlocking) == cudaSuccess);
        ok &= (cudaEventCreateWithFlags(&evRoot, cudaEventDisableTiming) == cudaSuccess);
        ok &= (cudaEventCreateWithFlags(&evX,    cudaEventDisableTiming) == cudaSuccess);
        ok &= (cudaEventCreateWithFlags(&evA,    cudaEventDisableTiming) == cudaSuccess);
        ok &= (cudaEventCreateWithFlags(&evB,    cudaEventDisableTiming) == cudaSuccess);
        ok &= (cudaEventCreateWithFlags(&evC,    cudaEventDisableTiming) == cudaSuccess);
        use_streams = ok;
        init_done = true;
    }

    h16 *xhi, *wqh, *wkh, *wvh, *woh;
    cudaGetSymbolAddress((void**)&xhi, g_xhi);
    cudaGetSymbolAddress((void**)&wqh, g_wqhi);
    cudaGetSymbolAddress((void**)&wkh, g_wkhi);
    cudaGetSymbolAddress((void**)&wvh, g_wvhi);
    cudaGetSymbolAddress((void**)&woh, g_wohi);

    int n4x = (int)((size_t)Mm*Dd/4), n4w = Dd*Dd/4;
    const float WSCALE = 32.f;

    if (use_streams) {
        cudaEventRecord(evRoot, 0);
        cudaStreamWaitEvent(sA, evRoot, 0);
        qp_kernel<<<Mm/8, 256, 0, sA>>>(X, Wtq, btq);
        stats_kernel<<<dim3(Nn, Bb), 256, 0, sA>>>();
        thr_kernel<<<1, 32, 0, sA>>>();
        cudaEventRecord(evA, sA);
        cudaStreamWaitEvent(sB, evRoot, 0);
        cvt_hi_kernel<<<(n4w + 255)/256, 256, 0, sB>>>(Wo, woh, WSCALE, n4w);
        cudaEventRecord(evB, sB);
        cvt_hi_kernel<<<(n4x + 255)/256, 256>>>(X, xhi, 1.f, n4x);
        cudaEventRecord(evX, 0);
        cvt_hi_kernel<<<(n4w + 255)/256, 256>>>(Wq, wqh, WSCALE, n4w);
        cvt_hi_kernel<<<(n4w + 255)/256, 256>>>(Wk, wkh, WSCALE, n4w);
        cudaStreamWaitEvent(sC, evX, 0);
        cvt_hi_kernel<<<(n4w + 255)/256, 256, 0, sC>>>(Wv, wvh, WSCALE, n4w);
        mma_v_kernel<<<dim3(Dd/128, Mm/128), 256, SMEM_BYTES, sC>>>(bv);
        vtrans_kernel<<<dim3(Nn/64, Dd/64, Bb), 256, 0, sC>>>();
        cudaEventRecord(evC, sC);
        mma_qk_kernel<<<dim3(Dd/128, Mm/128, 2), 256, SMEM_BYTES>>>(bq, bk);
        cudaStreamWaitEvent(0, evA, 0);
        mma_scores_kernel<<<dim3(136, 1, Bb), 256, SMEM_BYTES>>>();
        softmax_kernel<<<Mm, 256>>>();
        cudaStreamWaitEvent(0, evC, 0);
        mma_context_kernel<<<dim3(Dd/128, Nn/128, Bb), 256, SMEM_BYTES>>>();
        cudaStreamWaitEvent(0, evB, 0);
        mma_final_kernel<<<dim3(Dd/128, Mm/128), 256, SMEM_BYTES>>>(X, bo, Wfq, bfq, out);
    } else {
        qp_kernel<<<Mm/8, 256>>>(X, Wtq, btq);
        stats_kernel<<<dim3(Nn, Bb), 256>>>();
        thr_kernel<<<1, 32>>>();
        cvt_hi_kernel<<<(n4x + 255)/256, 256>>>(X, xhi, 1.f, n4x);
        cvt_hi_kernel<<<(n4w + 255)/256, 256>>>(Wq, wqh, WSCALE, n4w);
        cvt_hi_kernel<<<(n4w + 255)/256, 256>>>(Wk, wkh, WSCALE, n4w);
        cvt_hi_kernel<<<(n4w + 255)/256, 256>>>(Wv, wvh, WSCALE, n4w);
        cvt_hi_kernel<<<(n4w + 255)/256, 256>>>(Wo, woh, WSCALE, n4w);
        mma_qk_kernel<<<dim3(Dd/128, Mm/128, 2), 256, SMEM_BYTES>>>(bq, bk);
        mma_v_kernel<<<dim3(Dd/128, Mm/128), 256, SMEM_BYTES>>>(bv);
        vtrans_kernel<<<dim3(Nn/64, Dd/64, Bb), 256>>>();
        mma_scores_kernel<<<dim3(136, 1, Bb), 256, SMEM_BYTES>>>();
        softmax_kernel<<<Mm, 256>>>();
        mma_context_kernel<<<dim3(Dd/128, Nn/128, Bb), 256, SMEM_BYTES>>>();
        mma_final_kernel<<<dim3(Dd/128, Mm/128), 256, SMEM_BYTES>>>(X, bo, Wfq, bfq, out);
    }
}

// round 14
// speedup vs baseline: 7.1893x; 1.0612x over previous
#include <cuda_runtime.h>
#include <cuda_fp16.h>
#include <math.h>
#include <stdint.h>

#define Bb 4
#define Nn 2048
#define Dd 1024
#define Mm (Bb*Nn)

typedef __half h16;

// ---------------- scratch (static device globals) ---------------------------
__device__ h16 g_xhi[(size_t)Mm*Dd];
__device__ h16 g_wqhi[Dd*Dd], g_wkhi[Dd*Dd], g_wvhi[Dd*Dd], g_wohi[Dd*Dd]; // x32
__device__ h16 g_qhi[(size_t)Mm*Dd], g_khi[(size_t)Mm*Dd];
__device__ h16 g_vhi[(size_t)Mm*Dd];
__device__ h16 g_vThi[(size_t)Bb*Dd*Nn];
__device__ h16 g_ctxhi[(size_t)Mm*Dd];
__device__ h16 g_whi[(size_t)Bb*Nn*Nn];  // fp16 masked scores -> weights (in place)
__device__ float  g_qp[Mm*2];
__device__ double g_s1[Bb], g_s2[Bb];
__device__ float  g_thr[Bb];

// ---------------- PTX helpers -----------------------------------------------
__device__ __forceinline__ uint32_t smem_u32(const void* p) {
    uint32_t a;
    asm("{ .reg .u64 t; cvta.to.shared.u64 t, %1; cvt.u32.u64 %0, t; }" : "=r"(a) : "l"(p));
    return a;
}
#define CP16(dst, src) \
    asm volatile("cp.async.cg.shared.global [%0], [%1], 16;" :: "r"(dst), "l"(src) : "memory")
#define CP_COMMIT() asm volatile("cp.async.commit_group;" ::: "memory")

#define LDM_X4(r, addr) \
    asm volatile("ldmatrix.sync.aligned.m8n8.x4.shared.b16 {%0,%1,%2,%3}, [%4];" \
        : "=r"((r)[0]), "=r"((r)[1]), "=r"((r)[2]), "=r"((r)[3]) : "r"(addr))

#define MMA_F16(d, a, b) \
    asm volatile("mma.sync.aligned.m16n8k16.row.col.f32.f16.f16.f32 " \
        "{%0,%1,%2,%3}, {%4,%5,%6,%7}, {%8,%9}, {%0,%1,%2,%3};" \
        : "+f"((d)[0]), "+f"((d)[1]), "+f"((d)[2]), "+f"((d)[3]) \
        : "r"((a)[0]), "r"((a)[1]), "r"((a)[2]), "r"((a)[3]), "r"((b)[0]), "r"((b)[1]))

// ---------------- tiling constants ------------------------------------------
#define KS 64                 // k elements per stage (128-B rows)
#define LDSB 128              // smem row stride in bytes
#define TILEB (128*LDSB)      // 16384 B
#define STAGEB (2*TILEB)      // 32768 B: A, B
#define NSTAGE 3
#define SMEM_BYTES (NSTAGE*STAGEB)   // 98304 B -> 2 CTAs/SM

// 16B-chunk swizzle within 128B rows: c in 0..7
__device__ __forceinline__ uint32_t swz(uint32_t r, uint32_t c) {
    return r * LDSB + ((c ^ (r & 7)) << 4);
}

// ---------------- stage load via cp.async -----------------------------------
__device__ __forceinline__ void load_stage(uint32_t sb,
        const h16* __restrict__ A, size_t lda,
        const h16* __restrict__ B, size_t ldb, int kt) {
    int tid = threadIdx.x;
    int r0 = tid >> 3, seg = tid & 7;
    size_t koff = (size_t)kt * KS + seg * 8;
#pragma unroll
    for (int p = 0; p < 4; p++) {
        int row = r0 + p * 32;
        uint32_t ds = sb + swz((uint32_t)row, (uint32_t)seg);
        CP16(ds,         A + (size_t)row * lda + koff);
        CP16(ds + TILEB, B + (size_t)row * ldb + koff);
    }
    CP_COMMIT();
}

// ---------------- per-stage compute: 4 x k16, 1-term fp16 --------------------
__device__ __forceinline__ void compute_stage(uint32_t sb, int wm, int wn, int lane,
                                              float acc[4][4][4]) {
    int arow = lane & 15;
    int acol = (lane >> 4) << 3;
    int brow = (lane & 7) + ((lane >> 4) << 3);
    int bcol = ((lane >> 3) & 1) << 3;
#pragma unroll
    for (int ks = 0; ks < 4; ks++) {
        uint32_t ah[4][4];
        uint32_t ca = (uint32_t)(2*ks + (acol >> 3));
#pragma unroll
        for (int am = 0; am < 4; am++) {
            uint32_t ad = sb + swz((uint32_t)(wm*64 + am*16 + arow), ca);
            LDM_X4(ah[am], ad);
        }
        uint32_t bh[4][2];
        uint32_t cbk = (uint32_t)(2*ks + (bcol >> 3));
#pragma unroll
        for (int bp = 0; bp < 2; bp++) {
            uint32_t bd = sb + TILEB + swz((uint32_t)(wn*32 + bp*16 + brow), cbk);
            uint32_t t[4];
            LDM_X4(t, bd);
            bh[2*bp][0] = t[0]; bh[2*bp][1] = t[1];
            bh[2*bp+1][0] = t[2]; bh[2*bp+1][1] = t[3];
        }
#pragma unroll
        for (int am = 0; am < 4; am++)
#pragma unroll
            for (int bn = 0; bn < 4; bn++)
                MMA_F16(acc[am][bn], ah[am], bh[bn]);
    }
}

// D[128,128] fp32 = A[128,K] * B[128,K]^T, 3-stage cp.async pipeline (KS=64)
__device__ __forceinline__ void mma_mainloop(
        const h16* __restrict__ A, size_t lda,
        const h16* __restrict__ B, size_t ldb,
        int kIters, float acc[4][4][4]) {
    extern __shared__ __align__(16) char smem[];
    uint32_t sb = smem_u32(smem);
    int tid = threadIdx.x, lane = tid & 31, wid = tid >> 5;
    int wm = wid >> 2, wn = wid & 3;
    load_stage(sb, A, lda, B, ldb, 0);
    if (kIters > 1) load_stage(sb + STAGEB, A, lda, B, ldb, 1);
    int slot = 0;
    for (int kt = 0; kt < kIters; kt++) {
        if (kt + 1 < kIters) asm volatile("cp.async.wait_group 1;" ::: "memory");
        else                 asm volatile("cp.async.wait_group 0;" ::: "memory");
        __syncthreads();
        if (kt + 2 < kIters) {
            int ns = slot + 2; if (ns >= NSTAGE) ns -= NSTAGE;
            load_stage(sb + (uint32_t)ns * STAGEB, A, lda, B, ldb, kt + 2);
        }
        compute_stage(sb + (uint32_t)slot * STAGEB, wm, wn, lane, acc);
        if (++slot == NSTAGE) slot = 0;
    }
}

__device__ __forceinline__ uint32_t packh(h16 a, h16 b) {
    union { __half2 h; uint32_t u; } c;
    c.h = __halves2half2(a, b);
    return c.u;
}

// ---------------- conversion kernel (hi only, optional scale) ----------------
__global__ void __launch_bounds__(256) cvt_hi_kernel(const float* __restrict__ src,
                                                     h16* __restrict__ hi,
                                                     float scale, int n4) {
    int i = blockIdx.x * 256 + threadIdx.x;
    if (i >= n4) return;
    float4 v = ((const float4*)src)[i];
    *(uint2*)(hi + 4*(size_t)i) =
        make_uint2(packh(__float2half(v.x*scale), __float2half(v.y*scale)),
                   packh(__float2half(v.z*scale), __float2half(v.w*scale)));
}

// ---------------- small SIMT kernels ----------------------------------------
__global__ void __launch_bounds__(256) qp_kernel(const float* __restrict__ X,
                                                 const float* __restrict__ Wtq,
                                                 const float* __restrict__ btq) {
    if (blockIdx.x == 0 && threadIdx.x < Bb) {
        g_s1[threadIdx.x] = 0.0; g_s2[threadIdx.x] = 0.0;
    }
    int warp = threadIdx.x >> 5, lane = threadIdx.x & 31;
    int row = blockIdx.x * 8 + warp;
    const float* x = X + (size_t)row * Dd;
    float s0 = 0.f, s1 = 0.f;
    for (int k = lane * 4; k < Dd; k += 128) {
        float4 xv = *(const float4*)(x + k);
        float4 w0 = *(const float4*)(Wtq + k);
        float4 w1 = *(const float4*)(Wtq + Dd + k);
        s0 += xv.x*w0.x + xv.y*w0.y + xv.z*w0.z + xv.w*w0.w;
        s1 += xv.x*w1.x + xv.y*w1.y + xv.z*w1.z + xv.w*w1.w;
    }
#pragma unroll
    for (int o = 16; o; o >>= 1) {
        s0 += __shfl_xor_sync(0xffffffffu, s0, o);
        s1 += __shfl_xor_sync(0xffffffffu, s1, o);
    }
    if (lane == 0) { g_qp[row*2+0] = s0 + btq[0]; g_qp[row*2+1] = s1 + btq[1]; }
}
__global__ void __launch_bounds__(256) stats_kernel() {
    __shared__ float r1[256], r2[256];
    int b = blockIdx.y, i = blockIdx.x, tid = threadIdx.x;
    const float2* qp2 = (const float2*)g_qp + (size_t)b * Nn;
    float2 qi = qp2[i];
    float s1 = 0.f, s2 = 0.f;
    for (int j = tid; j < Nn; j += 256) {
        float2 qj = qp2[j];
        float dx = qi.x - qj.x, dy = qi.y - qj.y;
        float d = dx*dx + dy*dy;
        s1 += d; s2 += d*d;
    }
    r1[tid] = s1; r2[tid] = s2; __syncthreads();
    for (int o = 128; o; o >>= 1) {
        if (tid < o) { r1[tid] += r1[tid+o]; r2[tid] += r2[tid+o]; }
        __syncthreads();
    }
    if (tid == 0) { atomicAdd(&g_s1[b], (double)r1[0]); atomicAdd(&g_s2[b], (double)r2[0]); }
}
__global__ void thr_kernel() {
    int b = threadIdx.x;
    if (b < Bb) {
        double M = (double)Nn * (double)Nn;
        double mean = g_s1[b] / M;
        double var = (g_s2[b] - g_s1[b]*g_s1[b]/M) / (M - 1.0);
        if (var < 0.0) var = 0.0;
        g_thr[b] = (float)(mean + 1.25 * sqrt(var));
    }
}

// ---------------- v transpose (hi only) --------------------------------------
__global__ void __launch_bounds__(256) vtrans_kernel() {
    __shared__ h16 t[64][66];
    int b = blockIdx.z;
    int tok0 = blockIdx.x * 64, d0 = blockIdx.y * 64;
    int tid = threadIdx.x, r = tid >> 2, seg = tid & 3;
    const h16* sp = g_vhi + ((size_t)(b*Nn + tok0 + r)) * Dd + d0;
#pragma unroll
    for (int p = 0; p < 2; p++) {
        int c0 = (seg + 4*p) * 8;
        union { uint4 u; h16 h[8]; } v;
        v.u = *(const uint4*)(sp + c0);
#pragma unroll
        for (int e = 0; e < 8; e++) t[r][c0 + e] = v.h[e];
    }
    __syncthreads();
    h16* dp = g_vThi + (size_t)b*Dd*Nn + (size_t)(d0 + r)*Nn + tok0;
#pragma unroll
    for (int p = 0; p < 2; p++) {
        int c0 = (seg + 4*p) * 8;
        union { uint4 u; h16 h[8]; } v;
#pragma unroll
        for (int e = 0; e < 8; e++) v.h[e] = t[c0 + e][r];
        *(uint4*)(dp + c0) = v.u;
    }
}

// ---------------- GEMM kernels ----------------------------------------------
__device__ __forceinline__ void proj_epilogue(float acc[4][4][4], const float* bias,
                                              h16* OH, int m0, int n0) {
    int tid = threadIdx.x, lane = tid & 31, wid = tid >> 5;
    int rb = (wid >> 2)*64 + (lane >> 2);
    int cb = (wid & 3)*32 + (lane & 3)*2;
    float2 b2[4];
#pragma unroll
    for (int bn = 0; bn < 4; bn++) b2[bn] = *(const float2*)(bias + n0 + cb + bn*8);
#pragma unroll
    for (int am = 0; am < 4; am++)
#pragma unroll
    for (int h = 0; h < 2; h++) {
        int row = m0 + rb + am*16 + h*8;
        h16* oh = OH + (size_t)row*Dd + n0 + cb;
#pragma unroll
        for (int bn = 0; bn < 4; bn++) {
            float v0 = acc[am][bn][2*h]   * 0.03125f + b2[bn].x;
            float v1 = acc[am][bn][2*h+1] * 0.03125f + b2[bn].y;
            *(uint32_t*)(oh + bn*8) = packh(__float2half(v0), __float2half(v1));
        }
    }
}

__global__ void __launch_bounds__(256, 2) mma_qk_kernel(const float* __restrict__ bq,
                                                        const float* __restrict__ bk) {
    int z = blockIdx.z;
    const h16* Whi = z ? g_wkhi : g_wqhi;
    const float* bias = z ? bk : bq;
    int m0 = blockIdx.y * 128, n0 = blockIdx.x * 128;
    float acc[4][4][4] = {};
    mma_mainloop(g_xhi + (size_t)m0*Dd, Dd, Whi + (size_t)n0*Dd, Dd, Dd/KS, acc);
    proj_epilogue(acc, bias, z ? g_khi : g_qhi, m0, n0);
}

__global__ void __launch_bounds__(256, 2) mma_v_kernel(const float* __restrict__ bv) {
    int m0 = blockIdx.y * 128, n0 = blockIdx.x * 128;
    float acc[4][4][4] = {};
    mma_mainloop(g_xhi + (size_t)m0*Dd, Dd, g_wvhi + (size_t)n0*Dd, Dd, Dd/KS, acc);
    proj_epilogue(acc, bv, g_vhi, m0, n0);
}

// scores -> fp16 masked scores straight into g_whi (in-place softmax buffer)
__global__ void __launch_bounds__(256, 2) mma_scores_kernel() {
    int b = blockIdx.z;
    int t = blockIdx.x;
    int it = (int)((sqrtf(8.f*t + 1.f) - 1.f) * 0.5f);
    while ((it + 1)*(it + 2)/2 <= t) it++;
    while (it*(it + 1)/2 > t) it--;
    int jt = t - it*(it + 1)/2;
    int i0 = it * 128, j0 = jt * 128;
    float acc[4][4][4] = {};
    mma_mainloop(g_qhi + ((size_t)b*Nn + i0)*Dd, Dd,
                 g_khi + ((size_t)b*Nn + j0)*Dd, Dd, Dd/KS, acc);
    int tid = threadIdx.x, lane = tid & 31, wid = tid >> 5;
    int rb = (wid >> 2)*64 + (lane >> 2);
    int cb = (wid & 3)*32 + (lane & 3)*2;
    float thr = g_thr[b];
    const float2* qp2 = (const float2*)g_qp + (size_t)b * Nn;
    const float NEG = __int_as_float(0xff800000);
    float2 qj0[4], qj1[4];
#pragma unroll
    for (int bn = 0; bn < 4; bn++) {
        qj0[bn] = qp2[j0 + cb + bn*8];
        qj1[bn] = qp2[j0 + cb + bn*8 + 1];
    }
#pragma unroll
    for (int am = 0; am < 4; am++)
#pragma unroll
    for (int h = 0; h < 2; h++) {
        int gi = i0 + rb + am*16 + h*8;
        float2 qi = qp2[gi];
        h16* o = g_whi + (size_t)b*Nn*Nn + (size_t)gi*Nn + j0 + cb;
#pragma unroll
        for (int bn = 0; bn < 4; bn++) {
            float r[2];
#pragma unroll
            for (int q = 0; q < 2; q++) {
                int gj = j0 + cb + bn*8 + q;
                float2 qj = q ? qj1[bn] : qj0[bn];
                float dx = qi.x - qj.x, dy = qi.y - qj.y;
                float ds = dx*dx + dy*dy;
                bool ok = (gj <= gi) && (ds <= thr);
                if (ok && dx < 0.f && fabsf(dy) < 1e-3f * (-dx)) {
                    float bias = 0.5f * (1.f + cosf(atan2f(dy, dx)));
                    ok = (bias != 0.f);
                }
                r[q] = ok ? acc[am][bn][2*h+q] * 0.03125f : NEG;
            }
            *(uint32_t*)(o + bn*8) = packh(__float2half(r[0]), __float2half(r[1]));
        }
    }
}

// single-pass softmax: reads fp16 scores, overwrites with fp16 weights (in place)
__global__ void __launch_bounds__(256) softmax_kernel() {
    __shared__ float red[256];
    int row = blockIdx.x;
    int b = row >> 11, i = row & (Nn - 1);
    h16* s = g_whi + (size_t)b*Nn*Nn + (size_t)i*Nn;
    int tid = threadIdx.x;
    int jb = tid * 8;
    const float NEG = __int_as_float(0xff800000);
    union { uint4 u; h16 hh[8]; } in;
    in.u = *(const uint4*)(s + jb);
    float v[8];
#pragma unroll
    for (int k = 0; k < 8; k++) {
        int j = jb + k;
        v[k] = (j <= i) ? __half2float(in.hh[k]) : NEG;
    }
    float mx = v[0];
#pragma unroll
    for (int k = 1; k < 8; k++) mx = fmaxf(mx, v[k]);
    red[tid] = mx; __syncthreads();
    for (int o = 128; o; o >>= 1) {
        if (tid < o) red[tid] = fmaxf(red[tid], red[tid+o]);
        __syncthreads();
    }
    mx = red[0]; __syncthreads();
    float sum = 0.f;
#pragma unroll
    for (int k = 0; k < 8; k++) {
        int j = jb + k;
        float e = (j <= i) ? __expf(v[k] - mx) : 0.f;
        v[k] = e; sum += e;
    }
    red[tid] = sum; __syncthreads();
    for (int o = 128; o; o >>= 1) {
        if (tid < o) red[tid] += red[tid+o];
        __syncthreads();
    }
    float inv = 1.f / red[0];
    union { uint4 u; h16 hh[8]; } ph;
#pragma unroll
    for (int k = 0; k < 8; k++) ph.hh[k] = __float2half(v[k] * inv);
    *(uint4*)(s + jb) = ph.u;
}

__global__ void __launch_bounds__(256, 2) mma_context_kernel() {
    int b = blockIdx.z, m0 = blockIdx.y * 128, n0 = blockIdx.x * 128;
    float acc[4][4][4] = {};
    mma_mainloop(g_whi + ((size_t)b*Nn + m0)*Nn, Nn,
                 g_vThi + ((size_t)b*Dd + n0)*Nn, Nn, (m0 + 128)/KS, acc);
    int tid = threadIdx.x, lane = tid & 31, wid = tid >> 5;
    int rb = (wid >> 2)*64 + (lane >> 2);
    int cb = (wid & 3)*32 + (lane & 3)*2;
#pragma unroll
    for (int am = 0; am < 4; am++)
#pragma unroll
    for (int h = 0; h < 2; h++) {
        int row = b*Nn + m0 + rb + am*16 + h*8;
        h16* oh = g_ctxhi + (size_t)row*Dd + n0 + cb;
#pragma unroll
        for (int bn = 0; bn < 4; bn++)
            *(uint32_t*)(oh + bn*8) = packh(__float2half(acc[am][bn][2*h]),
                                            __float2half(acc[am][bn][2*h+1]));
    }
}

__global__ void __launch_bounds__(256, 2) mma_final_kernel(const float* __restrict__ X,
                                                           const float* __restrict__ bo,
                                                           const float* __restrict__ Wfq,
                                                           const float* __restrict__ bfq,
                                                           float* __restrict__ out) {
    int m0 = blockIdx.y * 128, n0 = blockIdx.x * 128;
    float acc[4][4][4] = {};
    mma_mainloop(g_ctxhi + (size_t)m0*Dd, Dd, g_wohi + (size_t)n0*Dd, Dd, Dd/KS, acc);
    int tid = threadIdx.x, lane = tid & 31, wid = tid >> 5;
    int rb = (wid >> 2)*64 + (lane >> 2);
    int cb = (wid & 3)*32 + (lane & 3)*2;
    float2 bo2[4], bfq2[4]; float4 wf[4];
#pragma unroll
    for (int bn = 0; bn < 4; bn++) {
        int c = n0 + cb + bn*8;
        bo2[bn]  = *(const float2*)(bo  + c);
        bfq2[bn] = *(const float2*)(bfq + c);
        wf[bn]   = *(const float4*)(Wfq + 2*c);
    }
#pragma unroll
    for (int am = 0; am < 4; am++)
#pragma unroll
    for (int h = 0; h < 2; h++) {
        int row = m0 + rb + am*16 + h*8;
        float2 qp = ((const float2*)g_qp)[row];
        float nrm = fmaxf(sqrtf(qp.x*qp.x + qp.y*qp.y), 1e-12f);
        float r0 = qp.x / nrm, r1 = qp.y / nrm;
        const float* hx = X + (size_t)row*Dd + n0 + cb;
        float* o = out + (size_t)row*Dd + n0 + cb;
#pragma unroll
        for (int bn = 0; bn < 4; bn++) {
            float2 hv = *(const float2*)(hx + bn*8);
            float v0 = hv.x + acc[am][bn][2*h]*0.03125f + bo2[bn].x
                     + 0.1f*(r0*wf[bn].x + r1*wf[bn].y + bfq2[bn].x);
            float v1 = hv.y + acc[am][bn][2*h+1]*0.03125f + bo2[bn].y
                     + 0.1f*(r0*wf[bn].z + r1*wf[bn].w + bfq2[bn].y);
            *(float2*)(o + bn*8) = make_float2(v0, v1);
        }
    }
}

// ---------------- launch ----------------------------------------------------
extern "C" void kernel_launch(void* const* d_in, const int* in_sizes, int n_in,
                              void* d_out, int out_size) {
    const float* X   = (const float*)d_in[0];
    const float* Wq  = (const float*)d_in[1];
    const float* bq  = (const float*)d_in[2];
    const float* Wk  = (const float*)d_in[3];
    const float* bk  = (const float*)d_in[4];
    const float* Wv  = (const float*)d_in[5];
    const float* bv  = (const float*)d_in[6];
    const float* Wo  = (const float*)d_in[7];
    const float* bo  = (const float*)d_in[8];
    const float* Wtq = (const float*)d_in[9];
    const float* btq = (const float*)d_in[10];
    const float* Wfq = (const float*)d_in[11];
    const float* bfq = (const float*)d_in[12];
    float* out = (float*)d_out;

    static bool init_done = false;
    static bool use_streams = false;
    static cudaStream_t sA, sB, sC;
    static cudaEvent_t evRoot, evX, evA, evB, evC;
    if (!init_done) {
        cudaFuncSetAttribute(mma_qk_kernel,      cudaFuncAttributeMaxDynamicSharedMemorySize, SMEM_BYTES);
        cudaFuncSetAttribute(mma_v_kernel,       cudaFuncAttributeMaxDynamicSharedMemorySize, SMEM_BYTES);
        cudaFuncSetAttribute(mma_scores_kernel,  cudaFuncAttributeMaxDynamicSharedMemorySize, SMEM_BYTES);
        cudaFuncSetAttribute(mma_context_kernel, cudaFuncAttributeMaxDynamicSharedMemorySize, SMEM_BYTES);
        cudaFuncSetAttribute(mma_final_kernel,   cudaFuncAttributeMaxDynamicSharedMemorySize, SMEM_BYTES);
        bool ok = true;
        ok &= (cudaStreamCreateWithFlags(&sA, cudaStreamNonBlocking) == cudaSuccess);
        ok &= (cudaStreamCreateWithFlags(&sB, cudaStreamNonBlocking) == cudaSuccess);
        ok &= (cudaStreamCreateWithFlags(&sC, cudaStreamNonBlocking) == cudaSuccess);
        ok &= (cudaEventCreateWithFlags(&evRoot, cudaEventDisableTiming) == cudaSuccess);
        ok &= (cudaEventCreateWithFlags(&evX,    cudaEventDisableTiming) == cudaSuccess);
        ok &= (cudaEventCreateWithFlags(&evA,    cudaEventDisableTiming) == cudaSuccess);
        ok &= (cudaEventCreateWithFlags(&evB,    cudaEventDisableTiming) == cudaSuccess);
        ok &= (cudaEventCreateWithFlags(&evC,    cudaEventDisableTiming) == cudaSuccess);
        use_streams = ok;
        init_done = true;
    }

    h16 *xhi, *wqh, *wkh, *wvh, *woh;
    cudaGetSymbolAddress((void**)&xhi, g_xhi);
    cudaGetSymbolAddress((void**)&wqh, g_wqhi);
    cudaGetSymbolAddress((void**)&wkh, g_wkhi);
    cudaGetSymbolAddress((void**)&wvh, g_wvhi);
    cudaGetSymbolAddress((void**)&woh, g_wohi);

    int n4x = (int)((size_t)Mm*Dd/4), n4w = Dd*Dd/4;
    const float WSCALE = 32.f;

    if (use_streams) {
        cudaEventRecord(evRoot, 0);
        cudaStreamWaitEvent(sA, evRoot, 0);
        qp_kernel<<<Mm/8, 256, 0, sA>>>(X, Wtq, btq);
        stats_kernel<<<dim3(Nn, Bb), 256, 0, sA>>>();
        thr_kernel<<<1, 32, 0, sA>>>();
        cudaEventRecord(evA, sA);
        cudaStreamWaitEvent(sB, evRoot, 0);
        cvt_hi_kernel<<<(n4w + 255)/256, 256, 0, sB>>>(Wo, woh, WSCALE, n4w);
        cudaEventRecord(evB, sB);
        cvt_hi_kernel<<<(n4x + 255)/256, 256>>>(X, xhi, 1.f, n4x);
        cudaEventRecord(evX, 0);
        cvt_hi_kernel<<<(n4w + 255)/256, 256>>>(Wq, wqh, WSCALE, n4w);
        cvt_hi_kernel<<<(n4w + 255)/256, 256>>>(Wk, wkh, WSCALE, n4w);
        cudaStreamWaitEvent(sC, evX, 0);
        cvt_hi_kernel<<<(n4w + 255)/256, 256, 0, sC>>>(Wv, wvh, WSCALE, n4w);
        mma_v_kernel<<<dim3(Dd/128, Mm/128), 256, SMEM_BYTES, sC>>>(bv);
        vtrans_kernel<<<dim3(Nn/64, Dd/64, Bb), 256, 0, sC>>>();
        cudaEventRecord(evC, sC);
        mma_qk_kernel<<<dim3(Dd/128, Mm/128, 2), 256, SMEM_BYTES>>>(bq, bk);
        cudaStreamWaitEvent(0, evA, 0);
        mma_scores_kernel<<<dim3(136, 1, Bb), 256, SMEM_BYTES>>>();
        softmax_kernel<<<Mm, 256>>>();
        cudaStreamWaitEvent(0, evC, 0);
        mma_context_kernel<<<dim3(Dd/128, Nn/128, Bb), 256, SMEM_BYTES>>>();
        cudaStreamWaitEvent(0, evB, 0);
        mma_final_kernel<<<dim3(Dd/128, Mm/128), 256, SMEM_BYTES>>>(X, bo, Wfq, bfq, out);
    } else {
        qp_kernel<<<Mm/8, 256>>>(X, Wtq, btq);
        stats_kernel<<<dim3(Nn, Bb), 256>>>();
        thr_kernel<<<1, 32>>>();
        cvt_hi_kernel<<<(n4x + 255)/256, 256>>>(X, xhi, 1.f, n4x);
        cvt_hi_kernel<<<(n4w + 255)/256, 256>>>(Wq, wqh, WSCALE, n4w);
        cvt_hi_kernel<<<(n4w + 255)/256, 256>>>(Wk, wkh, WSCALE, n4w);
        cvt_hi_kernel<<<(n4w + 255)/256, 256>>>(Wv, wvh, WSCALE, n4w);
        cvt_hi_kernel<<<(n4w + 255)/256, 256>>>(Wo, woh, WSCALE, n4w);
        mma_qk_kernel<<<dim3(Dd/128, Mm/128, 2), 256, SMEM_BYTES>>>(bq, bk);
        mma_v_kernel<<<dim3(Dd/128, Mm/128), 256, SMEM_BYTES>>>(bv);
        vtrans_kernel<<<dim3(Nn/64, Dd/64, Bb), 256>>>();
        mma_scores_kernel<<<dim3(136, 1, Bb), 256, SMEM_BYTES>>>();
        softmax_kernel<<<Mm, 256>>>();
        mma_context_kernel<<<dim3(Dd/128, Nn/128, Bb), 256, SMEM_BYTES>>>();
        mma_final_kernel<<<dim3(Dd/128, Mm/128), 256, SMEM_BYTES>>>(X, bo, Wfq, bfq, out);
    }
}

// round 15
// speedup vs baseline: 7.2868x; 1.0136x over previous
#include <cuda_runtime.h>
#include <cuda_fp16.h>
#include <math.h>
#include <stdint.h>

#define Bb 4
#define Nn 2048
#define Dd 1024
#define Mm (Bb*Nn)

typedef __half h16;

// ---------------- scratch (static device globals) ---------------------------
__device__ h16 g_xhi[(size_t)Mm*Dd];
__device__ h16 g_wqhi[Dd*Dd], g_wkhi[Dd*Dd], g_wvhi[Dd*Dd], g_wohi[Dd*Dd]; // x32
__device__ h16 g_qhi[(size_t)Mm*Dd], g_khi[(size_t)Mm*Dd];
__device__ h16 g_vhi[(size_t)Mm*Dd];
__device__ h16 g_vThi[(size_t)Bb*Dd*Nn];
__device__ h16 g_ctxhi[(size_t)Mm*Dd];
__device__ h16 g_whi[(size_t)Bb*Nn*Nn];  // fp16 masked scores -> weights (in place)
__device__ float  g_qp[Mm*2];
__device__ double g_s1[Bb], g_s2[Bb];
__device__ float  g_thr[Bb];

// ---------------- PTX helpers -----------------------------------------------
__device__ __forceinline__ uint32_t smem_u32(const void* p) {
    uint32_t a;
    asm("{ .reg .u64 t; cvta.to.shared.u64 t, %1; cvt.u32.u64 %0, t; }" : "=r"(a) : "l"(p));
    return a;
}
#define CP16(dst, src) \
    asm volatile("cp.async.cg.shared.global [%0], [%1], 16;" :: "r"(dst), "l"(src) : "memory")
#define CP_COMMIT() asm volatile("cp.async.commit_group;" ::: "memory")

#define LDM_X4(r, addr) \
    asm volatile("ldmatrix.sync.aligned.m8n8.x4.shared.b16 {%0,%1,%2,%3}, [%4];" \
        : "=r"((r)[0]), "=r"((r)[1]), "=r"((r)[2]), "=r"((r)[3]) : "r"(addr))

#define MMA_F16(d, a, b) \
    asm volatile("mma.sync.aligned.m16n8k16.row.col.f32.f16.f16.f32 " \
        "{%0,%1,%2,%3}, {%4,%5,%6,%7}, {%8,%9}, {%0,%1,%2,%3};" \
        : "+f"((d)[0]), "+f"((d)[1]), "+f"((d)[2]), "+f"((d)[3]) \
        : "r"((a)[0]), "r"((a)[1]), "r"((a)[2]), "r"((a)[3]), "r"((b)[0]), "r"((b)[1]))

// ---------------- tiling constants ------------------------------------------
#define KS 64                 // k elements per stage (128-B rows)
#define LDSB 128              // smem row stride in bytes
#define TILEB (128*LDSB)      // 16384 B
#define STAGEB (2*TILEB)      // 32768 B: A, B
#define NSTAGE 3
#define SMEM_BYTES (NSTAGE*STAGEB)   // 98304 B -> 2 CTAs/SM

// 16B-chunk swizzle within 128B rows: c in 0..7
__device__ __forceinline__ uint32_t swz(uint32_t r, uint32_t c) {
    return r * LDSB + ((c ^ (r & 7)) << 4);
}

// ---------------- stage load via cp.async -----------------------------------
__device__ __forceinline__ void load_stage(uint32_t sb,
        const h16* __restrict__ A, size_t lda,
        const h16* __restrict__ B, size_t ldb, int kt) {
    int tid = threadIdx.x;
    int r0 = tid >> 3, seg = tid & 7;
    size_t koff = (size_t)kt * KS + seg * 8;
#pragma unroll
    for (int p = 0; p < 4; p++) {
        int row = r0 + p * 32;
        uint32_t ds = sb + swz((uint32_t)row, (uint32_t)seg);
        CP16(ds,         A + (size_t)row * lda + koff);
        CP16(ds + TILEB, B + (size_t)row * ldb + koff);
    }
    CP_COMMIT();
}

// ---------------- per-stage compute: 4 x k16, 1-term fp16 --------------------
__device__ __forceinline__ void compute_stage(uint32_t sb, int wm, int wn, int lane,
                                              float acc[4][4][4]) {
    int arow = lane & 15;
    int acol = (lane >> 4) << 3;
    int brow = (lane & 7) + ((lane >> 4) << 3);
    int bcol = ((lane >> 3) & 1) << 3;
#pragma unroll
    for (int ks = 0; ks < 4; ks++) {
        uint32_t ah[4][4];
        uint32_t ca = (uint32_t)(2*ks + (acol >> 3));
#pragma unroll
        for (int am = 0; am < 4; am++) {
            uint32_t ad = sb + swz((uint32_t)(wm*64 + am*16 + arow), ca);
            LDM_X4(ah[am], ad);
        }
        uint32_t bh[4][2];
        uint32_t cbk = (uint32_t)(2*ks + (bcol >> 3));
#pragma unroll
        for (int bp = 0; bp < 2; bp++) {
            uint32_t bd = sb + TILEB + swz((uint32_t)(wn*32 + bp*16 + brow), cbk);
            uint32_t t[4];
            LDM_X4(t, bd);
            bh[2*bp][0] = t[0]; bh[2*bp][1] = t[1];
            bh[2*bp+1][0] = t[2]; bh[2*bp+1][1] = t[3];
        }
#pragma unroll
        for (int am = 0; am < 4; am++)
#pragma unroll
            for (int bn = 0; bn < 4; bn++)
                MMA_F16(acc[am][bn], ah[am], bh[bn]);
    }
}

// D[128,128] fp32 = A[128,K] * B[128,K]^T, 3-stage cp.async pipeline (KS=64)
__device__ __forceinline__ void mma_mainloop(
        const h16* __restrict__ A, size_t lda,
        const h16* __restrict__ B, size_t ldb,
        int kIters, float acc[4][4][4]) {
    extern __shared__ __align__(16) char smem[];
    uint32_t sb = smem_u32(smem);
    int tid = threadIdx.x, lane = tid & 31, wid = tid >> 5;
    int wm = wid >> 2, wn = wid & 3;
    load_stage(sb, A, lda, B, ldb, 0);
    if (kIters > 1) load_stage(sb + STAGEB, A, lda, B, ldb, 1);
    int slot = 0;
    for (int kt = 0; kt < kIters; kt++) {
        if (kt + 1 < kIters) asm volatile("cp.async.wait_group 1;" ::: "memory");
        else                 asm volatile("cp.async.wait_group 0;" ::: "memory");
        __syncthreads();
        if (kt + 2 < kIters) {
            int ns = slot + 2; if (ns >= NSTAGE) ns -= NSTAGE;
            load_stage(sb + (uint32_t)ns * STAGEB, A, lda, B, ldb, kt + 2);
        }
        compute_stage(sb + (uint32_t)slot * STAGEB, wm, wn, lane, acc);
        if (++slot == NSTAGE) slot = 0;
    }
}

__device__ __forceinline__ uint32_t packh(h16 a, h16 b) {
    union { __half2 h; uint32_t u; } c;
    c.h = __halves2half2(a, b);
    return c.u;
}

// ---------------- conversion kernel (hi only, optional scale) ----------------
__global__ void __launch_bounds__(256) cvt_hi_kernel(const float* __restrict__ src,
                                                     h16* __restrict__ hi,
                                                     float scale, int n4) {
    int i = blockIdx.x * 256 + threadIdx.x;
    if (i >= n4) return;
    float4 v = ((const float4*)src)[i];
    *(uint2*)(hi + 4*(size_t)i) =
        make_uint2(packh(__float2half(v.x*scale), __float2half(v.y*scale)),
                   packh(__float2half(v.z*scale), __float2half(v.w*scale)));
}

// ---------------- small SIMT kernels ----------------------------------------
__global__ void __launch_bounds__(256) qp_kernel(const float* __restrict__ X,
                                                 const float* __restrict__ Wtq,
                                                 const float* __restrict__ btq) {
    if (blockIdx.x == 0 && threadIdx.x < Bb) {
        g_s1[threadIdx.x] = 0.0; g_s2[threadIdx.x] = 0.0;
    }
    int warp = threadIdx.x >> 5, lane = threadIdx.x & 31;
    int row = blockIdx.x * 8 + warp;
    const float* x = X + (size_t)row * Dd;
    float s0 = 0.f, s1 = 0.f;
    for (int k = lane * 4; k < Dd; k += 128) {
        float4 xv = *(const float4*)(x + k);
        float4 w0 = *(const float4*)(Wtq + k);
        float4 w1 = *(const float4*)(Wtq + Dd + k);
        s0 += xv.x*w0.x + xv.y*w0.y + xv.z*w0.z + xv.w*w0.w;
        s1 += xv.x*w1.x + xv.y*w1.y + xv.z*w1.z + xv.w*w1.w;
    }
#pragma unroll
    for (int o = 16; o; o >>= 1) {
        s0 += __shfl_xor_sync(0xffffffffu, s0, o);
        s1 += __shfl_xor_sync(0xffffffffu, s1, o);
    }
    if (lane == 0) { g_qp[row*2+0] = s0 + btq[0]; g_qp[row*2+1] = s1 + btq[1]; }
}
__global__ void __launch_bounds__(256) stats_kernel() {
    __shared__ float r1[256], r2[256];
    int b = blockIdx.y, i = blockIdx.x, tid = threadIdx.x;
    const float2* qp2 = (const float2*)g_qp + (size_t)b * Nn;
    float2 qi = qp2[i];
    float s1 = 0.f, s2 = 0.f;
    for (int j = tid; j < Nn; j += 256) {
        float2 qj = qp2[j];
        float dx = qi.x - qj.x, dy = qi.y - qj.y;
        float d = dx*dx + dy*dy;
        s1 += d; s2 += d*d;
    }
    r1[tid] = s1; r2[tid] = s2; __syncthreads();
    for (int o = 128; o; o >>= 1) {
        if (tid < o) { r1[tid] += r1[tid+o]; r2[tid] += r2[tid+o]; }
        __syncthreads();
    }
    if (tid == 0) { atomicAdd(&g_s1[b], (double)r1[0]); atomicAdd(&g_s2[b], (double)r2[0]); }
}
__global__ void thr_kernel() {
    int b = threadIdx.x;
    if (b < Bb) {
        double M = (double)Nn * (double)Nn;
        double mean = g_s1[b] / M;
        double var = (g_s2[b] - g_s1[b]*g_s1[b]/M) / (M - 1.0);
        if (var < 0.0) var = 0.0;
        g_thr[b] = (float)(mean + 1.25 * sqrt(var));
    }
}

// ---------------- v transpose (hi only) --------------------------------------
__global__ void __launch_bounds__(256) vtrans_kernel() {
    __shared__ h16 t[64][66];
    int b = blockIdx.z;
    int tok0 = blockIdx.x * 64, d0 = blockIdx.y * 64;
    int tid = threadIdx.x, r = tid >> 2, seg = tid & 3;
    const h16* sp = g_vhi + ((size_t)(b*Nn + tok0 + r)) * Dd + d0;
#pragma unroll
    for (int p = 0; p < 2; p++) {
        int c0 = (seg + 4*p) * 8;
        union { uint4 u; h16 h[8]; } v;
        v.u = *(const uint4*)(sp + c0);
#pragma unroll
        for (int e = 0; e < 8; e++) t[r][c0 + e] = v.h[e];
    }
    __syncthreads();
    h16* dp = g_vThi + (size_t)b*Dd*Nn + (size_t)(d0 + r)*Nn + tok0;
#pragma unroll
    for (int p = 0; p < 2; p++) {
        int c0 = (seg + 4*p) * 8;
        union { uint4 u; h16 h[8]; } v;
#pragma unroll
        for (int e = 0; e < 8; e++) v.h[e] = t[c0 + e][r];
        *(uint4*)(dp + c0) = v.u;
    }
}

// ---------------- GEMM kernels ----------------------------------------------
__device__ __forceinline__ void proj_epilogue(float acc[4][4][4], const float* bias,
                                              h16* OH, int m0, int n0) {
    int tid = threadIdx.x, lane = tid & 31, wid = tid >> 5;
    int rb = (wid >> 2)*64 + (lane >> 2);
    int cb = (wid & 3)*32 + (lane & 3)*2;
    float2 b2[4];
#pragma unroll
    for (int bn = 0; bn < 4; bn++) b2[bn] = *(const float2*)(bias + n0 + cb + bn*8);
#pragma unroll
    for (int am = 0; am < 4; am++)
#pragma unroll
    for (int h = 0; h < 2; h++) {
        int row = m0 + rb + am*16 + h*8;
        h16* oh = OH + (size_t)row*Dd + n0 + cb;
#pragma unroll
        for (int bn = 0; bn < 4; bn++) {
            float v0 = acc[am][bn][2*h]   * 0.03125f + b2[bn].x;
            float v1 = acc[am][bn][2*h+1] * 0.03125f + b2[bn].y;
            *(uint32_t*)(oh + bn*8) = packh(__float2half(v0), __float2half(v1));
        }
    }
}

__global__ void __launch_bounds__(256, 2) mma_qk_kernel(const float* __restrict__ bq,
                                                        const float* __restrict__ bk) {
    int z = blockIdx.z;
    const h16* Whi = z ? g_wkhi : g_wqhi;
    const float* bias = z ? bk : bq;
    int m0 = blockIdx.y * 128, n0 = blockIdx.x * 128;
    float acc[4][4][4] = {};
    mma_mainloop(g_xhi + (size_t)m0*Dd, Dd, Whi + (size_t)n0*Dd, Dd, Dd/KS, acc);
    proj_epilogue(acc, bias, z ? g_khi : g_qhi, m0, n0);
}

__global__ void __launch_bounds__(256, 2) mma_v_kernel(const float* __restrict__ bv) {
    int m0 = blockIdx.y * 128, n0 = blockIdx.x * 128;
    float acc[4][4][4] = {};
    mma_mainloop(g_xhi + (size_t)m0*Dd, Dd, g_wvhi + (size_t)n0*Dd, Dd, Dd/KS, acc);
    proj_epilogue(acc, bv, g_vhi, m0, n0);
}

// scores -> fp16 masked scores straight into g_whi (in-place softmax buffer)
__global__ void __launch_bounds__(256, 2) mma_scores_kernel() {
    int b = blockIdx.z;
    int t = blockIdx.x;
    int it = (int)((sqrtf(8.f*t + 1.f) - 1.f) * 0.5f);
    while ((it + 1)*(it + 2)/2 <= t) it++;
    while (it*(it + 1)/2 > t) it--;
    int jt = t - it*(it + 1)/2;
    int i0 = it * 128, j0 = jt * 128;
    float acc[4][4][4] = {};
    mma_mainloop(g_qhi + ((size_t)b*Nn + i0)*Dd, Dd,
                 g_khi + ((size_t)b*Nn + j0)*Dd, Dd, Dd/KS, acc);
    int tid = threadIdx.x, lane = tid & 31, wid = tid >> 5;
    int rb = (wid >> 2)*64 + (lane >> 2);
    int cb = (wid & 3)*32 + (lane & 3)*2;
    float thr = g_thr[b];
    const float2* qp2 = (const float2*)g_qp + (size_t)b * Nn;
    const float NEG = __int_as_float(0xff800000);
    float2 qj0[4], qj1[4];
#pragma unroll
    for (int bn = 0; bn < 4; bn++) {
        qj0[bn] = qp2[j0 + cb + bn*8];
        qj1[bn] = qp2[j0 + cb + bn*8 + 1];
    }
#pragma unroll
    for (int am = 0; am < 4; am++)
#pragma unroll
    for (int h = 0; h < 2; h++) {
        int gi = i0 + rb + am*16 + h*8;
        float2 qi = qp2[gi];
        h16* o = g_whi + (size_t)b*Nn*Nn + (size_t)gi*Nn + j0 + cb;
#pragma unroll
        for (int bn = 0; bn < 4; bn++) {
            float r[2];
#pragma unroll
            for (int q = 0; q < 2; q++) {
                int gj = j0 + cb + bn*8 + q;
                float2 qj = q ? qj1[bn] : qj0[bn];
                float dx = qi.x - qj.x, dy = qi.y - qj.y;
                float ds = dx*dx + dy*dy;
                bool ok = (gj <= gi) && (ds <= thr);
                if (ok && dx < 0.f && fabsf(dy) < 1e-3f * (-dx)) {
                    float bias = 0.5f * (1.f + cosf(atan2f(dy, dx)));
                    ok = (bias != 0.f);
                }
                r[q] = ok ? acc[am][bn][2*h+q] * 0.03125f : NEG;
            }
            *(uint32_t*)(o + bn*8) = packh(__float2half(r[0]), __float2half(r[1]));
        }
    }
}

// single-pass softmax: reads fp16 scores, overwrites with fp16 weights (in place)
__global__ void __launch_bounds__(256) softmax_kernel() {
    __shared__ float red[256];
    int row = blockIdx.x;
    int b = row >> 11, i = row & (Nn - 1);
    h16* s = g_whi + (size_t)b*Nn*Nn + (size_t)i*Nn;
    int tid = threadIdx.x;
    int jb = tid * 8;
    const float NEG = __int_as_float(0xff800000);
    union { uint4 u; h16 hh[8]; } in;
    in.u = *(const uint4*)(s + jb);
    float v[8];
#pragma unroll
    for (int k = 0; k < 8; k++) {
        int j = jb + k;
        v[k] = (j <= i) ? __half2float(in.hh[k]) : NEG;
    }
    float mx = v[0];
#pragma unroll
    for (int k = 1; k < 8; k++) mx = fmaxf(mx, v[k]);
    red[tid] = mx; __syncthreads();
    for (int o = 128; o; o >>= 1) {
        if (tid < o) red[tid] = fmaxf(red[tid], red[tid+o]);
        __syncthreads();
    }
    mx = red[0]; __syncthreads();
    float sum = 0.f;
#pragma unroll
    for (int k = 0; k < 8; k++) {
        int j = jb + k;
        float e = (j <= i) ? __expf(v[k] - mx) : 0.f;
        v[k] = e; sum += e;
    }
    red[tid] = sum; __syncthreads();
    for (int o = 128; o; o >>= 1) {
        if (tid < o) red[tid] += red[tid+o];
        __syncthreads();
    }
    float inv = 1.f / red[0];
    union { uint4 u; h16 hh[8]; } ph;
#pragma unroll
    for (int k = 0; k < 8; k++) ph.hh[k] = __float2half(v[k] * inv);
    *(uint4*)(s + jb) = ph.u;
}

__global__ void __launch_bounds__(256, 2) mma_context_kernel(int bbase) {
    int b = bbase + blockIdx.z, m0 = blockIdx.y * 128, n0 = blockIdx.x * 128;
    float acc[4][4][4] = {};
    mma_mainloop(g_whi + ((size_t)b*Nn + m0)*Nn, Nn,
                 g_vThi + ((size_t)b*Dd + n0)*Nn, Nn, (m0 + 128)/KS, acc);
    int tid = threadIdx.x, lane = tid & 31, wid = tid >> 5;
    int rb = (wid >> 2)*64 + (lane >> 2);
    int cb = (wid & 3)*32 + (lane & 3)*2;
#pragma unroll
    for (int am = 0; am < 4; am++)
#pragma unroll
    for (int h = 0; h < 2; h++) {
        int row = b*Nn + m0 + rb + am*16 + h*8;
        h16* oh = g_ctxhi + (size_t)row*Dd + n0 + cb;
#pragma unroll
        for (int bn = 0; bn < 4; bn++)
            *(uint32_t*)(oh + bn*8) = packh(__float2half(acc[am][bn][2*h]),
                                            __float2half(acc[am][bn][2*h+1]));
    }
}

__global__ void __launch_bounds__(256, 2) mma_final_kernel(const float* __restrict__ X,
                                                           const float* __restrict__ bo,
                                                           const float* __restrict__ Wfq,
                                                           const float* __restrict__ bfq,
                                                           float* __restrict__ out,
                                                           int bbase) {
    int m0 = (bbase + blockIdx.z)*Nn + blockIdx.y * 128, n0 = blockIdx.x * 128;
    float acc[4][4][4] = {};
    mma_mainloop(g_ctxhi + (size_t)m0*Dd, Dd, g_wohi + (size_t)n0*Dd, Dd, Dd/KS, acc);
    int tid = threadIdx.x, lane = tid & 31, wid = tid >> 5;
    int rb = (wid >> 2)*64 + (lane >> 2);
    int cb = (wid & 3)*32 + (lane & 3)*2;
    float2 bo2[4], bfq2[4]; float4 wf[4];
#pragma unroll
    for (int bn = 0; bn < 4; bn++) {
        int c = n0 + cb + bn*8;
        bo2[bn]  = *(const float2*)(bo  + c);
        bfq2[bn] = *(const float2*)(bfq + c);
        wf[bn]   = *(const float4*)(Wfq + 2*c);
    }
#pragma unroll
    for (int am = 0; am < 4; am++)
#pragma unroll
    for (int h = 0; h < 2; h++) {
        int row = m0 + rb + am*16 + h*8;
        float2 qp = ((const float2*)g_qp)[row];
        float nrm = fmaxf(sqrtf(qp.x*qp.x + qp.y*qp.y), 1e-12f);
        float r0 = qp.x / nrm, r1 = qp.y / nrm;
        const float* hx = X + (size_t)row*Dd + n0 + cb;
        float* o = out + (size_t)row*Dd + n0 + cb;
#pragma unroll
        for (int bn = 0; bn < 4; bn++) {
            float2 hv = *(const float2*)(hx + bn*8);
            float v0 = hv.x + acc[am][bn][2*h]*0.03125f + bo2[bn].x
                     + 0.1f*(r0*wf[bn].x + r1*wf[bn].y + bfq2[bn].x);
            float v1 = hv.y + acc[am][bn][2*h+1]*0.03125f + bo2[bn].y
                     + 0.1f*(r0*wf[bn].z + r1*wf[bn].w + bfq2[bn].y);
            *(float2*)(o + bn*8) = make_float2(v0, v1);
        }
    }
}

// ---------------- launch ----------------------------------------------------
extern "C" void kernel_launch(void* const* d_in, const int* in_sizes, int n_in,
                              void* d_out, int out_size) {
    const float* X   = (const float*)d_in[0];
    const float* Wq  = (const float*)d_in[1];
    const float* bq  = (const float*)d_in[2];
    const float* Wk  = (const float*)d_in[3];
    const float* bk  = (const float*)d_in[4];
    const float* Wv  = (const float*)d_in[5];
    const float* bv  = (const float*)d_in[6];
    const float* Wo  = (const float*)d_in[7];
    const float* bo  = (const float*)d_in[8];
    const float* Wtq = (const float*)d_in[9];
    const float* btq = (const float*)d_in[10];
    const float* Wfq = (const float*)d_in[11];
    const float* bfq = (const float*)d_in[12];
    float* out = (float*)d_out;

    static bool init_done = false;
    static bool use_streams = false;
    static cudaStream_t sA, sB, sC;
    static cudaEvent_t evRoot, evX, evA, evB, evC, evCtx01, evFin01;
    if (!init_done) {
        cudaFuncSetAttribute(mma_qk_kernel,      cudaFuncAttributeMaxDynamicSharedMemorySize, SMEM_BYTES);
        cudaFuncSetAttribute(mma_v_kernel,       cudaFuncAttributeMaxDynamicSharedMemorySize, SMEM_BYTES);
        cudaFuncSetAttribute(mma_scores_kernel,  cudaFuncAttributeMaxDynamicSharedMemorySize, SMEM_BYTES);
        cudaFuncSetAttribute(mma_context_kernel, cudaFuncAttributeMaxDynamicSharedMemorySize, SMEM_BYTES);
        cudaFuncSetAttribute(mma_final_kernel,   cudaFuncAttributeMaxDynamicSharedMemorySize, SMEM_BYTES);
        bool ok = true;
        ok &= (cudaStreamCreateWithFlags(&sA, cudaStreamNonBlocking) == cudaSuccess);
        ok &= (cudaStreamCreateWithFlags(&sB, cudaStreamNonBlocking) == cudaSuccess);
        ok &= (cudaStreamCreateWithFlags(&sC, cudaStreamNonBlocking) == cudaSuccess);
        ok &= (cudaEventCreateWithFlags(&evRoot,  cudaEventDisableTiming) == cudaSuccess);
        ok &= (cudaEventCreateWithFlags(&evX,     cudaEventDisableTiming) == cudaSuccess);
        ok &= (cudaEventCreateWithFlags(&evA,     cudaEventDisableTiming) == cudaSuccess);
        ok &= (cudaEventCreateWithFlags(&evB,     cudaEventDisableTiming) == cudaSuccess);
        ok &= (cudaEventCreateWithFlags(&evC,     cudaEventDisableTiming) == cudaSuccess);
        ok &= (cudaEventCreateWithFlags(&evCtx01, cudaEventDisableTiming) == cudaSuccess);
        ok &= (cudaEventCreateWithFlags(&evFin01, cudaEventDisableTiming) == cudaSuccess);
        use_streams = ok;
        init_done = true;
    }

    h16 *xhi, *wqh, *wkh, *wvh, *woh;
    cudaGetSymbolAddress((void**)&xhi, g_xhi);
    cudaGetSymbolAddress((void**)&wqh, g_wqhi);
    cudaGetSymbolAddress((void**)&wkh, g_wkhi);
    cudaGetSymbolAddress((void**)&wvh, g_wvhi);
    cudaGetSymbolAddress((void**)&woh, g_wohi);

    int n4x = (int)((size_t)Mm*Dd/4), n4w = Dd*Dd/4;
    const float WSCALE = 32.f;

    if (use_streams) {
        cudaEventRecord(evRoot, 0);
        cudaStreamWaitEvent(sA, evRoot, 0);
        qp_kernel<<<Mm/8, 256, 0, sA>>>(X, Wtq, btq);
        stats_kernel<<<dim3(Nn, Bb), 256, 0, sA>>>();
        thr_kernel<<<1, 32, 0, sA>>>();
        cudaEventRecord(evA, sA);
        cudaStreamWaitEvent(sB, evRoot, 0);
        cvt_hi_kernel<<<(n4w + 255)/256, 256, 0, sB>>>(Wo, woh, WSCALE, n4w);
        cudaEventRecord(evB, sB);
        cvt_hi_kernel<<<(n4x + 255)/256, 256>>>(X, xhi, 1.f, n4x);
        cudaEventRecord(evX, 0);
        cvt_hi_kernel<<<(n4w + 255)/256, 256>>>(Wq, wqh, WSCALE, n4w);
        cvt_hi_kernel<<<(n4w + 255)/256, 256>>>(Wk, wkh, WSCALE, n4w);
        cudaStreamWaitEvent(sC, evX, 0);
        cvt_hi_kernel<<<(n4w + 255)/256, 256, 0, sC>>>(Wv, wvh, WSCALE, n4w);
        mma_v_kernel<<<dim3(Dd/128, Mm/128), 256, SMEM_BYTES, sC>>>(bv);
        vtrans_kernel<<<dim3(Nn/64, Dd/64, Bb), 256, 0, sC>>>();
        cudaEventRecord(evC, sC);
        mma_qk_kernel<<<dim3(Dd/128, Mm/128, 2), 256, SMEM_BYTES>>>(bq, bk);
        cudaStreamWaitEvent(0, evA, 0);
        mma_scores_kernel<<<dim3(136, 1, Bb), 256, SMEM_BYTES>>>();
        softmax_kernel<<<Mm, 256>>>();
        cudaStreamWaitEvent(0, evC, 0);
        // context batches 0,1 then 2,3; final 0,1 overlaps context 2,3 on sC
        mma_context_kernel<<<dim3(Dd/128, Nn/128, 2), 256, SMEM_BYTES>>>(0);
        cudaEventRecord(evCtx01, 0);
        cudaStreamWaitEvent(sC, evCtx01, 0);
        cudaStreamWaitEvent(sC, evB, 0);
        mma_final_kernel<<<dim3(Dd/128, Nn/128, 2), 256, SMEM_BYTES, sC>>>(X, bo, Wfq, bfq, out, 0);
        cudaEventRecord(evFin01, sC);
        mma_context_kernel<<<dim3(Dd/128, Nn/128, 2), 256, SMEM_BYTES>>>(2);
        cudaStreamWaitEvent(0, evB, 0);
        mma_final_kernel<<<dim3(Dd/128, Nn/128, 2), 256, SMEM_BYTES>>>(X, bo, Wfq, bfq, out, 2);
        cudaStreamWaitEvent(0, evFin01, 0);
    } else {
        qp_kernel<<<Mm/8, 256>>>(X, Wtq, btq);
        stats_kernel<<<dim3(Nn, Bb), 256>>>();
        thr_kernel<<<1, 32>>>();
        cvt_hi_kernel<<<(n4x + 255)/256, 256>>>(X, xhi, 1.f, n4x);
        cvt_hi_kernel<<<(n4w + 255)/256, 256>>>(Wq, wqh, WSCALE, n4w);
        cvt_hi_kernel<<<(n4w + 255)/256, 256>>>(Wk, wkh, WSCALE, n4w);
        cvt_hi_kernel<<<(n4w + 255)/256, 256>>>(Wv, wvh, WSCALE, n4w);
        cvt_hi_kernel<<<(n4w + 255)/256, 256>>>(Wo, woh, WSCALE, n4w);
        mma_qk_kernel<<<dim3(Dd/128, Mm/128, 2), 256, SMEM_BYTES>>>(bq, bk);
        mma_v_kernel<<<dim3(Dd/128, Mm/128), 256, SMEM_BYTES>>>(bv);
        vtrans_kernel<<<dim3(Nn/64, Dd/64, Bb), 256>>>();
        mma_scores_kernel<<<dim3(136, 1, Bb), 256, SMEM_BYTES>>>();
        softmax_kernel<<<Mm, 256>>>();
        mma_context_kernel<<<dim3(Dd/128, Nn/128, 2), 256, SMEM_BYTES>>>(0);
        mma_context_kernel<<<dim3(Dd/128, Nn/128, 2), 256, SMEM_BYTES>>>(2);
        mma_final_kernel<<<dim3(Dd/128, Nn/128, 2), 256, SMEM_BYTES>>>(X, bo, Wfq, bfq, out, 0);
        mma_final_kernel<<<dim3(Dd/128, Nn/128, 2), 256, SMEM_BYTES>>>(X, bo, Wfq, bfq, out, 2);
    }
}

// round 16
// speedup vs baseline: 7.3209x; 1.0047x over previous
#include <cuda_runtime.h>
#include <cuda_fp16.h>
#include <math.h>
#include <stdint.h>

#define Bb 4
#define Nn 2048
#define Dd 1024
#define Mm (Bb*Nn)

typedef __half h16;

// ---------------- scratch (static device globals) ---------------------------
__device__ h16 g_xhi[(size_t)Mm*Dd];
__device__ h16 g_wqhi[Dd*Dd], g_wkhi[Dd*Dd], g_wvhi[Dd*Dd], g_wohi[Dd*Dd]; // x32
__device__ h16 g_qhi[(size_t)Mm*Dd], g_khi[(size_t)Mm*Dd];
__device__ h16 g_vhi[(size_t)Mm*Dd];
__device__ h16 g_vThi[(size_t)Bb*Dd*Nn];
__device__ h16 g_ctxhi[(size_t)Mm*Dd];
__device__ h16 g_whi[(size_t)Bb*Nn*Nn];  // fp16 masked scores -> weights (in place)
__device__ float  g_qp[Mm*2];
__device__ double g_s1[Bb], g_s2[Bb];
__device__ float  g_thr[Bb];

// ---------------- PTX helpers -----------------------------------------------
__device__ __forceinline__ uint32_t smem_u32(const void* p) {
    uint32_t a;
    asm("{ .reg .u64 t; cvta.to.shared.u64 t, %1; cvt.u32.u64 %0, t; }" : "=r"(a) : "l"(p));
    return a;
}
#define CP16(dst, src) \
    asm volatile("cp.async.cg.shared.global [%0], [%1], 16;" :: "r"(dst), "l"(src) : "memory")
#define CP_COMMIT() asm volatile("cp.async.commit_group;" ::: "memory")

#define LDM_X4(r, addr) \
    asm volatile("ldmatrix.sync.aligned.m8n8.x4.shared.b16 {%0,%1,%2,%3}, [%4];" \
        : "=r"((r)[0]), "=r"((r)[1]), "=r"((r)[2]), "=r"((r)[3]) : "r"(addr))

#define MMA_F16(d, a, b) \
    asm volatile("mma.sync.aligned.m16n8k16.row.col.f32.f16.f16.f32 " \
        "{%0,%1,%2,%3}, {%4,%5,%6,%7}, {%8,%9}, {%0,%1,%2,%3};" \
        : "+f"((d)[0]), "+f"((d)[1]), "+f"((d)[2]), "+f"((d)[3]) \
        : "r"((a)[0]), "r"((a)[1]), "r"((a)[2]), "r"((a)[3]), "r"((b)[0]), "r"((b)[1]))

// ---------------- tiling constants ------------------------------------------
#define KS 64                 // k elements per stage (128-B rows)
#define LDSB 128              // smem row stride in bytes
#define TILEB (128*LDSB)      // 16384 B
#define STAGEB (2*TILEB)      // 32768 B: A, B
#define NSTAGE 3
#define SMEM_BYTES (NSTAGE*STAGEB)   // 98304 B -> 2 CTAs/SM

// 16B-chunk swizzle within 128B rows: c in 0..7
__device__ __forceinline__ uint32_t swz(uint32_t r, uint32_t c) {
    return r * LDSB + ((c ^ (r & 7)) << 4);
}

// ---------------- stage load via cp.async -----------------------------------
__device__ __forceinline__ void load_stage(uint32_t sb,
        const h16* __restrict__ A, size_t lda,
        const h16* __restrict__ B, size_t ldb, int kt) {
    int tid = threadIdx.x;
    int r0 = tid >> 3, seg = tid & 7;
    size_t koff = (size_t)kt * KS + seg * 8;
#pragma unroll
    for (int p = 0; p < 4; p++) {
        int row = r0 + p * 32;
        uint32_t ds = sb + swz((uint32_t)row, (uint32_t)seg);
        CP16(ds,         A + (size_t)row * lda + koff);
        CP16(ds + TILEB, B + (size_t)row * ldb + koff);
    }
    CP_COMMIT();
}

// ---------------- per-stage compute: 4 x k16, 1-term fp16 --------------------
__device__ __forceinline__ void compute_stage(uint32_t sb, int wm, int wn, int lane,
                                              float acc[4][4][4]) {
    int arow = lane & 15;
    int acol = (lane >> 4) << 3;
    int brow = (lane & 7) + ((lane >> 4) << 3);
    int bcol = ((lane >> 3) & 1) << 3;
#pragma unroll
    for (int ks = 0; ks < 4; ks++) {
        uint32_t ah[4][4];
        uint32_t ca = (uint32_t)(2*ks + (acol >> 3));
#pragma unroll
        for (int am = 0; am < 4; am++) {
            uint32_t ad = sb + swz((uint32_t)(wm*64 + am*16 + arow), ca);
            LDM_X4(ah[am], ad);
        }
        uint32_t bh[4][2];
        uint32_t cbk = (uint32_t)(2*ks + (bcol >> 3));
#pragma unroll
        for (int bp = 0; bp < 2; bp++) {
            uint32_t bd = sb + TILEB + swz((uint32_t)(wn*32 + bp*16 + brow), cbk);
            uint32_t t[4];
            LDM_X4(t, bd);
            bh[2*bp][0] = t[0]; bh[2*bp][1] = t[1];
            bh[2*bp+1][0] = t[2]; bh[2*bp+1][1] = t[3];
        }
#pragma unroll
        for (int am = 0; am < 4; am++)
#pragma unroll
            for (int bn = 0; bn < 4; bn++)
                MMA_F16(acc[am][bn], ah[am], bh[bn]);
    }
}

// D[128,128] fp32 = A[128,K] * B[128,K]^T, 3-stage cp.async pipeline (KS=64)
__device__ __forceinline__ void mma_mainloop(
        const h16* __restrict__ A, size_t lda,
        const h16* __restrict__ B, size_t ldb,
        int kIters, float acc[4][4][4]) {
    extern __shared__ __align__(16) char smem[];
    uint32_t sb = smem_u32(smem);
    int tid = threadIdx.x, lane = tid & 31, wid = tid >> 5;
    int wm = wid >> 2, wn = wid & 3;
    load_stage(sb, A, lda, B, ldb, 0);
    if (kIters > 1) load_stage(sb + STAGEB, A, lda, B, ldb, 1);
    int slot = 0;
    for (int kt = 0; kt < kIters; kt++) {
        if (kt + 1 < kIters) asm volatile("cp.async.wait_group 1;" ::: "memory");
        else                 asm volatile("cp.async.wait_group 0;" ::: "memory");
        __syncthreads();
        if (kt + 2 < kIters) {
            int ns = slot + 2; if (ns >= NSTAGE) ns -= NSTAGE;
            load_stage(sb + (uint32_t)ns * STAGEB, A, lda, B, ldb, kt + 2);
        }
        compute_stage(sb + (uint32_t)slot * STAGEB, wm, wn, lane, acc);
        if (++slot == NSTAGE) slot = 0;
    }
}

__device__ __forceinline__ uint32_t packh(h16 a, h16 b) {
    union { __half2 h; uint32_t u; } c;
    c.h = __halves2half2(a, b);
    return c.u;
}

// ---------------- conversion kernel (hi only, optional scale) ----------------
__global__ void __launch_bounds__(256) cvt_hi_kernel(const float* __restrict__ src,
                                                     h16* __restrict__ hi,
                                                     float scale, int n4) {
    int i = blockIdx.x * 256 + threadIdx.x;
    if (i >= n4) return;
    float4 v = ((const float4*)src)[i];
    *(uint2*)(hi + 4*(size_t)i) =
        make_uint2(packh(__float2half(v.x*scale), __float2half(v.y*scale)),
                   packh(__float2half(v.z*scale), __float2half(v.w*scale)));
}

// ---------------- small SIMT kernels ----------------------------------------
__global__ void __launch_bounds__(256) qp_kernel(const float* __restrict__ X,
                                                 const float* __restrict__ Wtq,
                                                 const float* __restrict__ btq) {
    if (blockIdx.x == 0 && threadIdx.x < Bb) {
        g_s1[threadIdx.x] = 0.0; g_s2[threadIdx.x] = 0.0;
    }
    int warp = threadIdx.x >> 5, lane = threadIdx.x & 31;
    int row = blockIdx.x * 8 + warp;
    const float* x = X + (size_t)row * Dd;
    float s0 = 0.f, s1 = 0.f;
    for (int k = lane * 4; k < Dd; k += 128) {
        float4 xv = *(const float4*)(x + k);
        float4 w0 = *(const float4*)(Wtq + k);
        float4 w1 = *(const float4*)(Wtq + Dd + k);
        s0 += xv.x*w0.x + xv.y*w0.y + xv.z*w0.z + xv.w*w0.w;
        s1 += xv.x*w1.x + xv.y*w1.y + xv.z*w1.z + xv.w*w1.w;
    }
#pragma unroll
    for (int o = 16; o; o >>= 1) {
        s0 += __shfl_xor_sync(0xffffffffu, s0, o);
        s1 += __shfl_xor_sync(0xffffffffu, s1, o);
    }
    if (lane == 0) { g_qp[row*2+0] = s0 + btq[0]; g_qp[row*2+1] = s1 + btq[1]; }
}
__global__ void __launch_bounds__(256) stats_kernel() {
    __shared__ float r1[256], r2[256];
    int b = blockIdx.y, i = blockIdx.x, tid = threadIdx.x;
    const float2* qp2 = (const float2*)g_qp + (size_t)b * Nn;
    float2 qi = qp2[i];
    float s1 = 0.f, s2 = 0.f;
    for (int j = tid; j < Nn; j += 256) {
        float2 qj = qp2[j];
        float dx = qi.x - qj.x, dy = qi.y - qj.y;
        float d = dx*dx + dy*dy;
        s1 += d; s2 += d*d;
    }
    r1[tid] = s1; r2[tid] = s2; __syncthreads();
    for (int o = 128; o; o >>= 1) {
        if (tid < o) { r1[tid] += r1[tid+o]; r2[tid] += r2[tid+o]; }
        __syncthreads();
    }
    if (tid == 0) { atomicAdd(&g_s1[b], (double)r1[0]); atomicAdd(&g_s2[b], (double)r2[0]); }
}
__global__ void thr_kernel() {
    int b = threadIdx.x;
    if (b < Bb) {
        double M = (double)Nn * (double)Nn;
        double mean = g_s1[b] / M;
        double var = (g_s2[b] - g_s1[b]*g_s1[b]/M) / (M - 1.0);
        if (var < 0.0) var = 0.0;
        g_thr[b] = (float)(mean + 1.25 * sqrt(var));
    }
}

// ---------------- v transpose (hi only) --------------------------------------
__global__ void __launch_bounds__(256) vtrans_kernel() {
    __shared__ h16 t[64][66];
    int b = blockIdx.z;
    int tok0 = blockIdx.x * 64, d0 = blockIdx.y * 64;
    int tid = threadIdx.x, r = tid >> 2, seg = tid & 3;
    const h16* sp = g_vhi + ((size_t)(b*Nn + tok0 + r)) * Dd + d0;
#pragma unroll
    for (int p = 0; p < 2; p++) {
        int c0 = (seg + 4*p) * 8;
        union { uint4 u; h16 h[8]; } v;
        v.u = *(const uint4*)(sp + c0);
#pragma unroll
        for (int e = 0; e < 8; e++) t[r][c0 + e] = v.h[e];
    }
    __syncthreads();
    h16* dp = g_vThi + (size_t)b*Dd*Nn + (size_t)(d0 + r)*Nn + tok0;
#pragma unroll
    for (int p = 0; p < 2; p++) {
        int c0 = (seg + 4*p) * 8;
        union { uint4 u; h16 h[8]; } v;
#pragma unroll
        for (int e = 0; e < 8; e++) v.h[e] = t[c0 + e][r];
        *(uint4*)(dp + c0) = v.u;
    }
}

// ---------------- GEMM kernels ----------------------------------------------
__device__ __forceinline__ void proj_epilogue(float acc[4][4][4], const float* bias,
                                              h16* OH, int m0, int n0) {
    int tid = threadIdx.x, lane = tid & 31, wid = tid >> 5;
    int rb = (wid >> 2)*64 + (lane >> 2);
    int cb = (wid & 3)*32 + (lane & 3)*2;
    float2 b2[4];
#pragma unroll
    for (int bn = 0; bn < 4; bn++) b2[bn] = *(const float2*)(bias + n0 + cb + bn*8);
#pragma unroll
    for (int am = 0; am < 4; am++)
#pragma unroll
    for (int h = 0; h < 2; h++) {
        int row = m0 + rb + am*16 + h*8;
        h16* oh = OH + (size_t)row*Dd + n0 + cb;
#pragma unroll
        for (int bn = 0; bn < 4; bn++) {
            float v0 = acc[am][bn][2*h]   * 0.03125f + b2[bn].x;
            float v1 = acc[am][bn][2*h+1] * 0.03125f + b2[bn].y;
            *(uint32_t*)(oh + bn*8) = packh(__float2half(v0), __float2half(v1));
        }
    }
}

__global__ void __launch_bounds__(256, 2) mma_qk_kernel(const float* __restrict__ bq,
                                                        const float* __restrict__ bk) {
    int z = blockIdx.z;
    const h16* Whi = z ? g_wkhi : g_wqhi;
    const float* bias = z ? bk : bq;
    int m0 = blockIdx.y * 128, n0 = blockIdx.x * 128;
    float acc[4][4][4] = {};
    mma_mainloop(g_xhi + (size_t)m0*Dd, Dd, Whi + (size_t)n0*Dd, Dd, Dd/KS, acc);
    proj_epilogue(acc, bias, z ? g_khi : g_qhi, m0, n0);
}

__global__ void __launch_bounds__(256, 2) mma_v_kernel(const float* __restrict__ bv) {
    int m0 = blockIdx.y * 128, n0 = blockIdx.x * 128;
    float acc[4][4][4] = {};
    mma_mainloop(g_xhi + (size_t)m0*Dd, Dd, g_wvhi + (size_t)n0*Dd, Dd, Dd/KS, acc);
    proj_epilogue(acc, bv, g_vhi, m0, n0);
}

// scores -> fp16 masked scores straight into g_whi (in-place softmax buffer)
__global__ void __launch_bounds__(256, 2) mma_scores_kernel() {
    int b = blockIdx.z;
    int t = blockIdx.x;
    int it = (int)((sqrtf(8.f*t + 1.f) - 1.f) * 0.5f);
    while ((it + 1)*(it + 2)/2 <= t) it++;
    while (it*(it + 1)/2 > t) it--;
    int jt = t - it*(it + 1)/2;
    int i0 = it * 128, j0 = jt * 128;
    float acc[4][4][4] = {};
    mma_mainloop(g_qhi + ((size_t)b*Nn + i0)*Dd, Dd,
                 g_khi + ((size_t)b*Nn + j0)*Dd, Dd, Dd/KS, acc);
    int tid = threadIdx.x, lane = tid & 31, wid = tid >> 5;
    int rb = (wid >> 2)*64 + (lane >> 2);
    int cb = (wid & 3)*32 + (lane & 3)*2;
    float thr = g_thr[b];
    const float2* qp2 = (const float2*)g_qp + (size_t)b * Nn;
    const float NEG = __int_as_float(0xff800000);
    float2 qj0[4], qj1[4];
#pragma unroll
    for (int bn = 0; bn < 4; bn++) {
        qj0[bn] = qp2[j0 + cb + bn*8];
        qj1[bn] = qp2[j0 + cb + bn*8 + 1];
    }
#pragma unroll
    for (int am = 0; am < 4; am++)
#pragma unroll
    for (int h = 0; h < 2; h++) {
        int gi = i0 + rb + am*16 + h*8;
        float2 qi = qp2[gi];
        h16* o = g_whi + (size_t)b*Nn*Nn + (size_t)gi*Nn + j0 + cb;
#pragma unroll
        for (int bn = 0; bn < 4; bn++) {
            float r[2];
#pragma unroll
            for (int q = 0; q < 2; q++) {
                int gj = j0 + cb + bn*8 + q;
                float2 qj = q ? qj1[bn] : qj0[bn];
                float dx = qi.x - qj.x, dy = qi.y - qj.y;
                float ds = dx*dx + dy*dy;
                bool ok = (gj <= gi) && (ds <= thr);
                if (ok && dx < 0.f && fabsf(dy) < 1e-3f * (-dx)) {
                    float bias = 0.5f * (1.f + cosf(atan2f(dy, dx)));
                    ok = (bias != 0.f);
                }
                r[q] = ok ? acc[am][bn][2*h+q] * 0.03125f : NEG;
            }
            *(uint32_t*)(o + bn*8) = packh(__float2half(r[0]), __float2half(r[1]));
        }
    }
}

// single-pass softmax over 2 batches starting at bbase (in place)
__global__ void __launch_bounds__(256) softmax_kernel(int bbase) {
    __shared__ float red[256];
    int row = bbase * Nn + blockIdx.x;
    int b = row >> 11, i = row & (Nn - 1);
    h16* s = g_whi + (size_t)b*Nn*Nn + (size_t)i*Nn;
    int tid = threadIdx.x;
    int jb = tid * 8;
    const float NEG = __int_as_float(0xff800000);
    union { uint4 u; h16 hh[8]; } in;
    in.u = *(const uint4*)(s + jb);
    float v[8];
#pragma unroll
    for (int k = 0; k < 8; k++) {
        int j = jb + k;
        v[k] = (j <= i) ? __half2float(in.hh[k]) : NEG;
    }
    float mx = v[0];
#pragma unroll
    for (int k = 1; k < 8; k++) mx = fmaxf(mx, v[k]);
    red[tid] = mx; __syncthreads();
    for (int o = 128; o; o >>= 1) {
        if (tid < o) red[tid] = fmaxf(red[tid], red[tid+o]);
        __syncthreads();
    }
    mx = red[0]; __syncthreads();
    float sum = 0.f;
#pragma unroll
    for (int k = 0; k < 8; k++) {
        int j = jb + k;
        float e = (j <= i) ? __expf(v[k] - mx) : 0.f;
        v[k] = e; sum += e;
    }
    red[tid] = sum; __syncthreads();
    for (int o = 128; o; o >>= 1) {
        if (tid < o) red[tid] += red[tid+o];
        __syncthreads();
    }
    float inv = 1.f / red[0];
    union { uint4 u; h16 hh[8]; } ph;
#pragma unroll
    for (int k = 0; k < 8; k++) ph.hh[k] = __float2half(v[k] * inv);
    *(uint4*)(s + jb) = ph.u;
}

__global__ void __launch_bounds__(256, 2) mma_context_kernel(int bbase) {
    int b = bbase + blockIdx.z, m0 = blockIdx.y * 128, n0 = blockIdx.x * 128;
    float acc[4][4][4] = {};
    mma_mainloop(g_whi + ((size_t)b*Nn + m0)*Nn, Nn,
                 g_vThi + ((size_t)b*Dd + n0)*Nn, Nn, (m0 + 128)/KS, acc);
    int tid = threadIdx.x, lane = tid & 31, wid = tid >> 5;
    int rb = (wid >> 2)*64 + (lane >> 2);
    int cb = (wid & 3)*32 + (lane & 3)*2;
#pragma unroll
    for (int am = 0; am < 4; am++)
#pragma unroll
    for (int h = 0; h < 2; h++) {
        int row = b*Nn + m0 + rb + am*16 + h*8;
        h16* oh = g_ctxhi + (size_t)row*Dd + n0 + cb;
#pragma unroll
        for (int bn = 0; bn < 4; bn++)
            *(uint32_t*)(oh + bn*8) = packh(__float2half(acc[am][bn][2*h]),
                                            __float2half(acc[am][bn][2*h+1]));
    }
}

__global__ void __launch_bounds__(256, 2) mma_final_kernel(const float* __restrict__ X,
                                                           const float* __restrict__ bo,
                                                           const float* __restrict__ Wfq,
                                                           const float* __restrict__ bfq,
                                                           float* __restrict__ out,
                                                           int bbase) {
    int m0 = (bbase + blockIdx.z)*Nn + blockIdx.y * 128, n0 = blockIdx.x * 128;
    float acc[4][4][4] = {};
    mma_mainloop(g_ctxhi + (size_t)m0*Dd, Dd, g_wohi + (size_t)n0*Dd, Dd, Dd/KS, acc);
    int tid = threadIdx.x, lane = tid & 31, wid = tid >> 5;
    int rb = (wid >> 2)*64 + (lane >> 2);
    int cb = (wid & 3)*32 + (lane & 3)*2;
    float2 bo2[4], bfq2[4]; float4 wf[4];
#pragma unroll
    for (int bn = 0; bn < 4; bn++) {
        int c = n0 + cb + bn*8;
        bo2[bn]  = *(const float2*)(bo  + c);
        bfq2[bn] = *(const float2*)(bfq + c);
        wf[bn]   = *(const float4*)(Wfq + 2*c);
    }
#pragma unroll
    for (int am = 0; am < 4; am++)
#pragma unroll
    for (int h = 0; h < 2; h++) {
        int row = m0 + rb + am*16 + h*8;
        float2 qp = ((const float2*)g_qp)[row];
        float nrm = fmaxf(sqrtf(qp.x*qp.x + qp.y*qp.y), 1e-12f);
        float r0 = qp.x / nrm, r1 = qp.y / nrm;
        const float* hx = X + (size_t)row*Dd + n0 + cb;
        float* o = out + (size_t)row*Dd + n0 + cb;
#pragma unroll
        for (int bn = 0; bn < 4; bn++) {
            float2 hv = *(const float2*)(hx + bn*8);
            float v0 = hv.x + acc[am][bn][2*h]*0.03125f + bo2[bn].x
                     + 0.1f*(r0*wf[bn].x + r1*wf[bn].y + bfq2[bn].x);
            float v1 = hv.y + acc[am][bn][2*h+1]*0.03125f + bo2[bn].y
                     + 0.1f*(r0*wf[bn].z + r1*wf[bn].w + bfq2[bn].y);
            *(float2*)(o + bn*8) = make_float2(v0, v1);
        }
    }
}

// ---------------- launch ----------------------------------------------------
extern "C" void kernel_launch(void* const* d_in, const int* in_sizes, int n_in,
                              void* d_out, int out_size) {
    const float* X   = (const float*)d_in[0];
    const float* Wq  = (const float*)d_in[1];
    const float* bq  = (const float*)d_in[2];
    const float* Wk  = (const float*)d_in[3];
    const float* bk  = (const float*)d_in[4];
    const float* Wv  = (const float*)d_in[5];
    const float* bv  = (const float*)d_in[6];
    const float* Wo  = (const float*)d_in[7];
    const float* bo  = (const float*)d_in[8];
    const float* Wtq = (const float*)d_in[9];
    const float* btq = (const float*)d_in[10];
    const float* Wfq = (const float*)d_in[11];
    const float* bfq = (const float*)d_in[12];
    float* out = (float*)d_out;

    static bool init_done = false;
    static bool use_streams = false;
    static cudaStream_t sA, sB, sC;
    static cudaEvent_t evRoot, evX, evA, evW, evB, evC, evS, evSm23, evCtx01, evFin01;
    if (!init_done) {
        cudaFuncSetAttribute(mma_qk_kernel,      cudaFuncAttributeMaxDynamicSharedMemorySize, SMEM_BYTES);
        cudaFuncSetAttribute(mma_v_kernel,       cudaFuncAttributeMaxDynamicSharedMemorySize, SMEM_BYTES);
        cudaFuncSetAttribute(mma_scores_kernel,  cudaFuncAttributeMaxDynamicSharedMemorySize, SMEM_BYTES);
        cudaFuncSetAttribute(mma_context_kernel, cudaFuncAttributeMaxDynamicSharedMemorySize, SMEM_BYTES);
        cudaFuncSetAttribute(mma_final_kernel,   cudaFuncAttributeMaxDynamicSharedMemorySize, SMEM_BYTES);
        bool ok = true;
        ok &= (cudaStreamCreateWithFlags(&sA, cudaStreamNonBlocking) == cudaSuccess);
        ok &= (cudaStreamCreateWithFlags(&sB, cudaStreamNonBlocking) == cudaSuccess);
        ok &= (cudaStreamCreateWithFlags(&sC, cudaStreamNonBlocking) == cudaSuccess);
        ok &= (cudaEventCreateWithFlags(&evRoot,  cudaEventDisableTiming) == cudaSuccess);
        ok &= (cudaEventCreateWithFlags(&evX,     cudaEventDisableTiming) == cudaSuccess);
        ok &= (cudaEventCreateWithFlags(&evA,     cudaEventDisableTiming) == cudaSuccess);
        ok &= (cudaEventCreateWithFlags(&evW,     cudaEventDisableTiming) == cudaSuccess);
        ok &= (cudaEventCreateWithFlags(&evB,     cudaEventDisableTiming) == cudaSuccess);
        ok &= (cudaEventCreateWithFlags(&evC,     cudaEventDisableTiming) == cudaSuccess);
        ok &= (cudaEventCreateWithFlags(&evS,     cudaEventDisableTiming) == cudaSuccess);
        ok &= (cudaEventCreateWithFlags(&evSm23,  cudaEventDisableTiming) == cudaSuccess);
        ok &= (cudaEventCreateWithFlags(&evCtx01, cudaEventDisableTiming) == cudaSuccess);
        ok &= (cudaEventCreateWithFlags(&evFin01, cudaEventDisableTiming) == cudaSuccess);
        use_streams = ok;
        init_done = true;
    }

    h16 *xhi, *wqh, *wkh, *wvh, *woh;
    cudaGetSymbolAddress((void**)&xhi, g_xhi);
    cudaGetSymbolAddress((void**)&wqh, g_wqhi);
    cudaGetSymbolAddress((void**)&wkh, g_wkhi);
    cudaGetSymbolAddress((void**)&wvh, g_wvhi);
    cudaGetSymbolAddress((void**)&woh, g_wohi);

    int n4x = (int)((size_t)Mm*Dd/4), n4w = Dd*Dd/4;
    const float WSCALE = 32.f;

    if (use_streams) {
        cudaEventRecord(evRoot, 0);
        // side A: mask-threshold chain
        cudaStreamWaitEvent(sA, evRoot, 0);
        qp_kernel<<<Mm/8, 256, 0, sA>>>(X, Wtq, btq);
        stats_kernel<<<dim3(Nn, Bb), 256, 0, sA>>>();
        thr_kernel<<<1, 32, 0, sA>>>();
        cudaEventRecord(evA, sA);
        // side B: Wq/Wk conversions (needed by qk), then Wo (needed by final)
        cudaStreamWaitEvent(sB, evRoot, 0);
        cvt_hi_kernel<<<(n4w + 255)/256, 256, 0, sB>>>(Wq, wqh, WSCALE, n4w);
        cvt_hi_kernel<<<(n4w + 255)/256, 256, 0, sB>>>(Wk, wkh, WSCALE, n4w);
        cudaEventRecord(evW, sB);
        cvt_hi_kernel<<<(n4w + 255)/256, 256, 0, sB>>>(Wo, woh, WSCALE, n4w);
        cudaEventRecord(evB, sB);
        // main: X conversion
        cvt_hi_kernel<<<(n4x + 255)/256, 256>>>(X, xhi, 1.f, n4x);
        cudaEventRecord(evX, 0);
        // side C: v projection + transpose
        cudaStreamWaitEvent(sC, evX, 0);
        cvt_hi_kernel<<<(n4w + 255)/256, 256, 0, sC>>>(Wv, wvh, WSCALE, n4w);
        mma_v_kernel<<<dim3(Dd/128, Mm/128), 256, SMEM_BYTES, sC>>>(bv);
        vtrans_kernel<<<dim3(Nn/64, Dd/64, Bb), 256, 0, sC>>>();
        cudaEventRecord(evC, sC);
        // main chain
        cudaStreamWaitEvent(0, evW, 0);
        mma_qk_kernel<<<dim3(Dd/128, Mm/128, 2), 256, SMEM_BYTES>>>(bq, bk);
        cudaStreamWaitEvent(0, evA, 0);
        mma_scores_kernel<<<dim3(136, 1, Bb), 256, SMEM_BYTES>>>();
        cudaEventRecord(evS, 0);
        // softmax batches 2,3 on sC, concurrent with softmax 0,1 + ctx 0,1 on main
        cudaStreamWaitEvent(sC, evS, 0);
        softmax_kernel<<<2*Nn, 256, 0, sC>>>(2);
        cudaEventRecord(evSm23, sC);
        softmax_kernel<<<2*Nn, 256>>>(0);
        cudaStreamWaitEvent(0, evC, 0);
        mma_context_kernel<<<dim3(Dd/128, Nn/128, 2), 256, SMEM_BYTES>>>(0);
        cudaEventRecord(evCtx01, 0);
        // final 0,1 on sC overlaps ctx 2,3 on main
        cudaStreamWaitEvent(sC, evCtx01, 0);
        cudaStreamWaitEvent(sC, evB, 0);
        mma_final_kernel<<<dim3(Dd/128, Nn/128, 2), 256, SMEM_BYTES, sC>>>(X, bo, Wfq, bfq, out, 0);
        cudaEventRecord(evFin01, sC);
        cudaStreamWaitEvent(0, evSm23, 0);
        mma_context_kernel<<<dim3(Dd/128, Nn/128, 2), 256, SMEM_BYTES>>>(2);
        cudaStreamWaitEvent(0, evB, 0);
        mma_final_kernel<<<dim3(Dd/128, Nn/128, 2), 256, SMEM_BYTES>>>(X, bo, Wfq, bfq, out, 2);
        cudaStreamWaitEvent(0, evFin01, 0);
    } else {
        qp_kernel<<<Mm/8, 256>>>(X, Wtq, btq);
        stats_kernel<<<dim3(Nn, Bb), 256>>>();
        thr_kernel<<<1, 32>>>();
        cvt_hi_kernel<<<(n4x + 255)/256, 256>>>(X, xhi, 1.f, n4x);
        cvt_hi_kernel<<<(n4w + 255)/256, 256>>>(Wq, wqh, WSCALE, n4w);
        cvt_hi_kernel<<<(n4w + 255)/256, 256>>>(Wk, wkh, WSCALE, n4w);
        cvt_hi_kernel<<<(n4w + 255)/256, 256>>>(Wv, wvh, WSCALE, n4w);
        cvt_hi_kernel<<<(n4w + 255)/256, 256>>>(Wo, woh, WSCALE, n4w);
        mma_qk_kernel<<<dim3(Dd/128, Mm/128, 2), 256, SMEM_BYTES>>>(bq, bk);
        mma_v_kernel<<<dim3(Dd/128, Mm/128), 256, SMEM_BYTES>>>(bv);
        vtrans_kernel<<<dim3(Nn/64, Dd/64, Bb), 256>>>();
        mma_scores_kernel<<<dim3(136, 1, Bb), 256, SMEM_BYTES>>>();
        softmax_kernel<<<2*Nn, 256>>>(0);
        softmax_kernel<<<2*Nn, 256>>>(2);
        mma_context_kernel<<<dim3(Dd/128, Nn/128, 2), 256, SMEM_BYTES>>>(0);
        mma_context_kernel<<<dim3(Dd/128, Nn/128, 2), 256, SMEM_BYTES>>>(2);
        mma_final_kernel<<<dim3(Dd/128, Nn/128, 2), 256, SMEM_BYTES>>>(X, bo, Wfq, bfq, out, 0);
        mma_final_kernel<<<dim3(Dd/128, Nn/128, 2), 256, SMEM_BYTES>>>(X, bo, Wfq, bfq, out, 2);
    }
}

// round 17
// speedup vs baseline: 7.4781x; 1.0215x over previous
#include <cuda_runtime.h>
#include <cuda_fp16.h>
#include <math.h>
#include <stdint.h>

#define Bb 4
#define Nn 2048
#define Dd 1024
#define Mm (Bb*Nn)

typedef __half h16;

// ---------------- scratch (static device globals) ---------------------------
__device__ h16 g_xhi[(size_t)Mm*Dd];
__device__ h16 g_wqhi[Dd*Dd], g_wkhi[Dd*Dd], g_wvhi[Dd*Dd], g_wohi[Dd*Dd]; // x32
__device__ h16 g_qhi[(size_t)Mm*Dd], g_khi[(size_t)Mm*Dd];
__device__ h16 g_vhi[(size_t)Mm*Dd];
__device__ h16 g_vThi[(size_t)Bb*Dd*Nn];
__device__ h16 g_ctxhi[(size_t)Mm*Dd];
__device__ h16 g_whi[(size_t)Bb*Nn*Nn];  // fp16 masked scores -> weights (in place)
__device__ float  g_qp[Mm*2];
__device__ double g_s1[Bb], g_s2[Bb];
__device__ float  g_thr[Bb];

// ---------------- PTX helpers -----------------------------------------------
__device__ __forceinline__ uint32_t smem_u32(const void* p) {
    uint32_t a;
    asm("{ .reg .u64 t; cvta.to.shared.u64 t, %1; cvt.u32.u64 %0, t; }" : "=r"(a) : "l"(p));
    return a;
}
#define CP16(dst, src) \
    asm volatile("cp.async.cg.shared.global [%0], [%1], 16;" :: "r"(dst), "l"(src) : "memory")
#define CP_COMMIT() asm volatile("cp.async.commit_group;" ::: "memory")

#define LDM_X4(r, addr) \
    asm volatile("ldmatrix.sync.aligned.m8n8.x4.shared.b16 {%0,%1,%2,%3}, [%4];" \
        : "=r"((r)[0]), "=r"((r)[1]), "=r"((r)[2]), "=r"((r)[3]) : "r"(addr))

#define MMA_F16(d, a, b) \
    asm volatile("mma.sync.aligned.m16n8k16.row.col.f32.f16.f16.f32 " \
        "{%0,%1,%2,%3}, {%4,%5,%6,%7}, {%8,%9}, {%0,%1,%2,%3};" \
        : "+f"((d)[0]), "+f"((d)[1]), "+f"((d)[2]), "+f"((d)[3]) \
        : "r"((a)[0]), "r"((a)[1]), "r"((a)[2]), "r"((a)[3]), "r"((b)[0]), "r"((b)[1]))

// ---------------- tiling constants ------------------------------------------
#define KS 64                 // k elements per stage (128-B rows)
#define LDSB 128              // smem row stride in bytes
#define TILEB (128*LDSB)      // 16384 B
#define STAGEB (2*TILEB)      // 32768 B: A, B
#define NSTAGE 3
#define SMEM_BYTES (NSTAGE*STAGEB)   // 98304 B -> 2 CTAs/SM

// 16B-chunk swizzle within 128B rows: c in 0..7
__device__ __forceinline__ uint32_t swz(uint32_t r, uint32_t c) {
    return r * LDSB + ((c ^ (r & 7)) << 4);
}

// ---------------- stage load via cp.async -----------------------------------
__device__ __forceinline__ void load_stage(uint32_t sb,
        const h16* __restrict__ A, size_t lda,
        const h16* __restrict__ B, size_t ldb, int kt) {
    int tid = threadIdx.x;
    int r0 = tid >> 3, seg = tid & 7;
    size_t koff = (size_t)kt * KS + seg * 8;
#pragma unroll
    for (int p = 0; p < 4; p++) {
        int row = r0 + p * 32;
        uint32_t ds = sb + swz((uint32_t)row, (uint32_t)seg);
        CP16(ds,         A + (size_t)row * lda + koff);
        CP16(ds + TILEB, B + (size_t)row * ldb + koff);
    }
    CP_COMMIT();
}

// ---------------- per-stage compute: 4 x k16, 1-term fp16 --------------------
__device__ __forceinline__ void compute_stage(uint32_t sb, int wm, int wn, int lane,
                                              float acc[4][4][4]) {
    int arow = lane & 15;
    int acol = (lane >> 4) << 3;
    int brow = (lane & 7) + ((lane >> 4) << 3);
    int bcol = ((lane >> 3) & 1) << 3;
#pragma unroll
    for (int ks = 0; ks < 4; ks++) {
        uint32_t ah[4][4];
        uint32_t ca = (uint32_t)(2*ks + (acol >> 3));
#pragma unroll
        for (int am = 0; am < 4; am++) {
            uint32_t ad = sb + swz((uint32_t)(wm*64 + am*16 + arow), ca);
            LDM_X4(ah[am], ad);
        }
        uint32_t bh[4][2];
        uint32_t cbk = (uint32_t)(2*ks + (bcol >> 3));
#pragma unroll
        for (int bp = 0; bp < 2; bp++) {
            uint32_t bd = sb + TILEB + swz((uint32_t)(wn*32 + bp*16 + brow), cbk);
            uint32_t t[4];
            LDM_X4(t, bd);
            bh[2*bp][0] = t[0]; bh[2*bp][1] = t[1];
            bh[2*bp+1][0] = t[2]; bh[2*bp+1][1] = t[3];
        }
#pragma unroll
        for (int am = 0; am < 4; am++)
#pragma unroll
            for (int bn = 0; bn < 4; bn++)
                MMA_F16(acc[am][bn], ah[am], bh[bn]);
    }
}

// D[128,128] fp32 = A[128,K] * B[128,K]^T, 3-stage cp.async pipeline (KS=64)
__device__ __forceinline__ void mma_mainloop(
        const h16* __restrict__ A, size_t lda,
        const h16* __restrict__ B, size_t ldb,
        int kIters, float acc[4][4][4]) {
    extern __shared__ __align__(16) char smem[];
    uint32_t sb = smem_u32(smem);
    int tid = threadIdx.x, lane = tid & 31, wid = tid >> 5;
    int wm = wid >> 2, wn = wid & 3;
    load_stage(sb, A, lda, B, ldb, 0);
    if (kIters > 1) load_stage(sb + STAGEB, A, lda, B, ldb, 1);
    int slot = 0;
    for (int kt = 0; kt < kIters; kt++) {
        if (kt + 1 < kIters) asm volatile("cp.async.wait_group 1;" ::: "memory");
        else                 asm volatile("cp.async.wait_group 0;" ::: "memory");
        __syncthreads();
        if (kt + 2 < kIters) {
            int ns = slot + 2; if (ns >= NSTAGE) ns -= NSTAGE;
            load_stage(sb + (uint32_t)ns * STAGEB, A, lda, B, ldb, kt + 2);
        }
        compute_stage(sb + (uint32_t)slot * STAGEB, wm, wn, lane, acc);
        if (++slot == NSTAGE) slot = 0;
    }
}

__device__ __forceinline__ uint32_t packh(h16 a, h16 b) {
    union { __half2 h; uint32_t u; } c;
    c.h = __halves2half2(a, b);
    return c.u;
}

// ---------------- conversion kernel (hi only, optional scale) ----------------
__global__ void __launch_bounds__(256) cvt_hi_kernel(const float* __restrict__ src,
                                                     h16* __restrict__ hi,
                                                     float scale, int n4) {
    int i = blockIdx.x * 256 + threadIdx.x;
    if (i >= n4) return;
    float4 v = ((const float4*)src)[i];
    *(uint2*)(hi + 4*(size_t)i) =
        make_uint2(packh(__float2half(v.x*scale), __float2half(v.y*scale)),
                   packh(__float2half(v.z*scale), __float2half(v.w*scale)));
}

// ---------------- small SIMT kernels ----------------------------------------
__global__ void __launch_bounds__(256) qp_kernel(const float* __restrict__ X,
                                                 const float* __restrict__ Wtq,
                                                 const float* __restrict__ btq) {
    if (blockIdx.x == 0 && threadIdx.x < Bb) {
        g_s1[threadIdx.x] = 0.0; g_s2[threadIdx.x] = 0.0;
    }
    int warp = threadIdx.x >> 5, lane = threadIdx.x & 31;
    int row = blockIdx.x * 8 + warp;
    const float* x = X + (size_t)row * Dd;
    float s0 = 0.f, s1 = 0.f;
    for (int k = lane * 4; k < Dd; k += 128) {
        float4 xv = *(const float4*)(x + k);
        float4 w0 = *(const float4*)(Wtq + k);
        float4 w1 = *(const float4*)(Wtq + Dd + k);
        s0 += xv.x*w0.x + xv.y*w0.y + xv.z*w0.z + xv.w*w0.w;
        s1 += xv.x*w1.x + xv.y*w1.y + xv.z*w1.z + xv.w*w1.w;
    }
#pragma unroll
    for (int o = 16; o; o >>= 1) {
        s0 += __shfl_xor_sync(0xffffffffu, s0, o);
        s1 += __shfl_xor_sync(0xffffffffu, s1, o);
    }
    if (lane == 0) { g_qp[row*2+0] = s0 + btq[0]; g_qp[row*2+1] = s1 + btq[1]; }
}
__global__ void __launch_bounds__(256) stats_kernel() {
    __shared__ float r1[256], r2[256];
    int b = blockIdx.y, i = blockIdx.x, tid = threadIdx.x;
    const float2* qp2 = (const float2*)g_qp + (size_t)b * Nn;
    float2 qi = qp2[i];
    float s1 = 0.f, s2 = 0.f;
    for (int j = tid; j < Nn; j += 256) {
        float2 qj = qp2[j];
        float dx = qi.x - qj.x, dy = qi.y - qj.y;
        float d = dx*dx + dy*dy;
        s1 += d; s2 += d*d;
    }
    r1[tid] = s1; r2[tid] = s2; __syncthreads();
    for (int o = 128; o; o >>= 1) {
        if (tid < o) { r1[tid] += r1[tid+o]; r2[tid] += r2[tid+o]; }
        __syncthreads();
    }
    if (tid == 0) { atomicAdd(&g_s1[b], (double)r1[0]); atomicAdd(&g_s2[b], (double)r2[0]); }
}
__global__ void thr_kernel() {
    int b = threadIdx.x;
    if (b < Bb) {
        double M = (double)Nn * (double)Nn;
        double mean = g_s1[b] / M;
        double var = (g_s2[b] - g_s1[b]*g_s1[b]/M) / (M - 1.0);
        if (var < 0.0) var = 0.0;
        g_thr[b] = (float)(mean + 1.25 * sqrt(var));
    }
}

// ---------------- v transpose (hi only) --------------------------------------
__global__ void __launch_bounds__(256) vtrans_kernel() {
    __shared__ h16 t[64][66];
    int b = blockIdx.z;
    int tok0 = blockIdx.x * 64, d0 = blockIdx.y * 64;
    int tid = threadIdx.x, r = tid >> 2, seg = tid & 3;
    const h16* sp = g_vhi + ((size_t)(b*Nn + tok0 + r)) * Dd + d0;
#pragma unroll
    for (int p = 0; p < 2; p++) {
        int c0 = (seg + 4*p) * 8;
        union { uint4 u; h16 h[8]; } v;
        v.u = *(const uint4*)(sp + c0);
#pragma unroll
        for (int e = 0; e < 8; e++) t[r][c0 + e] = v.h[e];
    }
    __syncthreads();
    h16* dp = g_vThi + (size_t)b*Dd*Nn + (size_t)(d0 + r)*Nn + tok0;
#pragma unroll
    for (int p = 0; p < 2; p++) {
        int c0 = (seg + 4*p) * 8;
        union { uint4 u; h16 h[8]; } v;
#pragma unroll
        for (int e = 0; e < 8; e++) v.h[e] = t[c0 + e][r];
        *(uint4*)(dp + c0) = v.u;
    }
}

// ---------------- GEMM kernels ----------------------------------------------
__device__ __forceinline__ void proj_epilogue(float acc[4][4][4], const float* bias,
                                              h16* OH, int m0, int n0) {
    int tid = threadIdx.x, lane = tid & 31, wid = tid >> 5;
    int rb = (wid >> 2)*64 + (lane >> 2);
    int cb = (wid & 3)*32 + (lane & 3)*2;
    float2 b2[4];
#pragma unroll
    for (int bn = 0; bn < 4; bn++) b2[bn] = *(const float2*)(bias + n0 + cb + bn*8);
#pragma unroll
    for (int am = 0; am < 4; am++)
#pragma unroll
    for (int h = 0; h < 2; h++) {
        int row = m0 + rb + am*16 + h*8;
        h16* oh = OH + (size_t)row*Dd + n0 + cb;
#pragma unroll
        for (int bn = 0; bn < 4; bn++) {
            float v0 = acc[am][bn][2*h]   * 0.03125f + b2[bn].x;
            float v1 = acc[am][bn][2*h+1] * 0.03125f + b2[bn].y;
            *(uint32_t*)(oh + bn*8) = packh(__float2half(v0), __float2half(v1));
        }
    }
}

__global__ void __launch_bounds__(256, 2) mma_qk_kernel(const float* __restrict__ bq,
                                                        const float* __restrict__ bk) {
    int z = blockIdx.z;
    const h16* Whi = z ? g_wkhi : g_wqhi;
    const float* bias = z ? bk : bq;
    int m0 = blockIdx.y * 128, n0 = blockIdx.x * 128;
    float acc[4][4][4] = {};
    mma_mainloop(g_xhi + (size_t)m0*Dd, Dd, Whi + (size_t)n0*Dd, Dd, Dd/KS, acc);
    proj_epilogue(acc, bias, z ? g_khi : g_qhi, m0, n0);
}

__global__ void __launch_bounds__(256, 2) mma_v_kernel(const float* __restrict__ bv) {
    int m0 = blockIdx.y * 128, n0 = blockIdx.x * 128;
    float acc[4][4][4] = {};
    mma_mainloop(g_xhi + (size_t)m0*Dd, Dd, g_wvhi + (size_t)n0*Dd, Dd, Dd/KS, acc);
    proj_epilogue(acc, bv, g_vhi, m0, n0);
}

// scores -> fp16 masked scores straight into g_whi (in-place softmax buffer)
__global__ void __launch_bounds__(256, 2) mma_scores_kernel(int bbase) {
    int b = bbase + blockIdx.z;
    int t = blockIdx.x;
    int it = (int)((sqrtf(8.f*t + 1.f) - 1.f) * 0.5f);
    while ((it + 1)*(it + 2)/2 <= t) it++;
    while (it*(it + 1)/2 > t) it--;
    int jt = t - it*(it + 1)/2;
    int i0 = it * 128, j0 = jt * 128;
    float acc[4][4][4] = {};
    mma_mainloop(g_qhi + ((size_t)b*Nn + i0)*Dd, Dd,
                 g_khi + ((size_t)b*Nn + j0)*Dd, Dd, Dd/KS, acc);
    int tid = threadIdx.x, lane = tid & 31, wid = tid >> 5;
    int rb = (wid >> 2)*64 + (lane >> 2);
    int cb = (wid & 3)*32 + (lane & 3)*2;
    float thr = g_thr[b];
    const float2* qp2 = (const float2*)g_qp + (size_t)b * Nn;
    const float NEG = __int_as_float(0xff800000);
    float2 qj0[4], qj1[4];
#pragma unroll
    for (int bn = 0; bn < 4; bn++) {
        qj0[bn] = qp2[j0 + cb + bn*8];
        qj1[bn] = qp2[j0 + cb + bn*8 + 1];
    }
#pragma unroll
    for (int am = 0; am < 4; am++)
#pragma unroll
    for (int h = 0; h < 2; h++) {
        int gi = i0 + rb + am*16 + h*8;
        float2 qi = qp2[gi];
        h16* o = g_whi + (size_t)b*Nn*Nn + (size_t)gi*Nn + j0 + cb;
#pragma unroll
        for (int bn = 0; bn < 4; bn++) {
            float r[2];
#pragma unroll
            for (int q = 0; q < 2; q++) {
                int gj = j0 + cb + bn*8 + q;
                float2 qj = q ? qj1[bn] : qj0[bn];
                float dx = qi.x - qj.x, dy = qi.y - qj.y;
                float ds = dx*dx + dy*dy;
                bool ok = (gj <= gi) && (ds <= thr);
                if (ok && dx < 0.f && fabsf(dy) < 1e-3f * (-dx)) {
                    float bias = 0.5f * (1.f + cosf(atan2f(dy, dx)));
                    ok = (bias != 0.f);
                }
                r[q] = ok ? acc[am][bn][2*h+q] * 0.03125f : NEG;
            }
            *(uint32_t*)(o + bn*8) = packh(__float2half(r[0]), __float2half(r[1]));
        }
    }
}

// single-pass softmax over 2 batches starting at bbase (in place)
__global__ void __launch_bounds__(256) softmax_kernel(int bbase) {
    __shared__ float red[256];
    int row = bbase * Nn + blockIdx.x;
    int b = row >> 11, i = row & (Nn - 1);
    h16* s = g_whi + (size_t)b*Nn*Nn + (size_t)i*Nn;
    int tid = threadIdx.x;
    int jb = tid * 8;
    const float NEG = __int_as_float(0xff800000);
    union { uint4 u; h16 hh[8]; } in;
    in.u = *(const uint4*)(s + jb);
    float v[8];
#pragma unroll
    for (int k = 0; k < 8; k++) {
        int j = jb + k;
        v[k] = (j <= i) ? __half2float(in.hh[k]) : NEG;
    }
    float mx = v[0];
#pragma unroll
    for (int k = 1; k < 8; k++) mx = fmaxf(mx, v[k]);
    red[tid] = mx; __syncthreads();
    for (int o = 128; o; o >>= 1) {
        if (tid < o) red[tid] = fmaxf(red[tid], red[tid+o]);
        __syncthreads();
    }
    mx = red[0]; __syncthreads();
    float sum = 0.f;
#pragma unroll
    for (int k = 0; k < 8; k++) {
        int j = jb + k;
        float e = (j <= i) ? __expf(v[k] - mx) : 0.f;
        v[k] = e; sum += e;
    }
    red[tid] = sum; __syncthreads();
    for (int o = 128; o; o >>= 1) {
        if (tid < o) red[tid] += red[tid+o];
        __syncthreads();
    }
    float inv = 1.f / red[0];
    union { uint4 u; h16 hh[8]; } ph;
#pragma unroll
    for (int k = 0; k < 8; k++) ph.hh[k] = __float2half(v[k] * inv);
    *(uint4*)(s + jb) = ph.u;
}

__global__ void __launch_bounds__(256, 2) mma_context_kernel(int bbase) {
    int b = bbase + blockIdx.z, m0 = blockIdx.y * 128, n0 = blockIdx.x * 128;
    float acc[4][4][4] = {};
    mma_mainloop(g_whi + ((size_t)b*Nn + m0)*Nn, Nn,
                 g_vThi + ((size_t)b*Dd + n0)*Nn, Nn, (m0 + 128)/KS, acc);
    int tid = threadIdx.x, lane = tid & 31, wid = tid >> 5;
    int rb = (wid >> 2)*64 + (lane >> 2);
    int cb = (wid & 3)*32 + (lane & 3)*2;
#pragma unroll
    for (int am = 0; am < 4; am++)
#pragma unroll
    for (int h = 0; h < 2; h++) {
        int row = b*Nn + m0 + rb + am*16 + h*8;
        h16* oh = g_ctxhi + (size_t)row*Dd + n0 + cb;
#pragma unroll
        for (int bn = 0; bn < 4; bn++)
            *(uint32_t*)(oh + bn*8) = packh(__float2half(acc[am][bn][2*h]),
                                            __float2half(acc[am][bn][2*h+1]));
    }
}

__global__ void __launch_bounds__(256, 2) mma_final_kernel(const float* __restrict__ X,
                                                           const float* __restrict__ bo,
                                                           const float* __restrict__ Wfq,
                                                           const float* __restrict__ bfq,
                                                           float* __restrict__ out,
                                                           int bbase) {
    int m0 = (bbase + blockIdx.z)*Nn + blockIdx.y * 128, n0 = blockIdx.x * 128;
    float acc[4][4][4] = {};
    mma_mainloop(g_ctxhi + (size_t)m0*Dd, Dd, g_wohi + (size_t)n0*Dd, Dd, Dd/KS, acc);
    int tid = threadIdx.x, lane = tid & 31, wid = tid >> 5;
    int rb = (wid >> 2)*64 + (lane >> 2);
    int cb = (wid & 3)*32 + (lane & 3)*2;
    float2 bo2[4], bfq2[4]; float4 wf[4];
#pragma unroll
    for (int bn = 0; bn < 4; bn++) {
        int c = n0 + cb + bn*8;
        bo2[bn]  = *(const float2*)(bo  + c);
        bfq2[bn] = *(const float2*)(bfq + c);
        wf[bn]   = *(const float4*)(Wfq + 2*c);
    }
#pragma unroll
    for (int am = 0; am < 4; am++)
#pragma unroll
    for (int h = 0; h < 2; h++) {
        int row = m0 + rb + am*16 + h*8;
        float2 qp = ((const float2*)g_qp)[row];
        float nrm = fmaxf(sqrtf(qp.x*qp.x + qp.y*qp.y), 1e-12f);
        float r0 = qp.x / nrm, r1 = qp.y / nrm;
        const float* hx = X + (size_t)row*Dd + n0 + cb;
        float* o = out + (size_t)row*Dd + n0 + cb;
#pragma unroll
        for (int bn = 0; bn < 4; bn++) {
            float2 hv = *(const float2*)(hx + bn*8);
            float v0 = hv.x + acc[am][bn][2*h]*0.03125f + bo2[bn].x
                     + 0.1f*(r0*wf[bn].x + r1*wf[bn].y + bfq2[bn].x);
            float v1 = hv.y + acc[am][bn][2*h+1]*0.03125f + bo2[bn].y
                     + 0.1f*(r0*wf[bn].z + r1*wf[bn].w + bfq2[bn].y);
            *(float2*)(o + bn*8) = make_float2(v0, v1);
        }
    }
}

// ---------------- launch ----------------------------------------------------
extern "C" void kernel_launch(void* const* d_in, const int* in_sizes, int n_in,
                              void* d_out, int out_size) {
    const float* X   = (const float*)d_in[0];
    const float* Wq  = (const float*)d_in[1];
    const float* bq  = (const float*)d_in[2];
    const float* Wk  = (const float*)d_in[3];
    const float* bk  = (const float*)d_in[4];
    const float* Wv  = (const float*)d_in[5];
    const float* bv  = (const float*)d_in[6];
    const float* Wo  = (const float*)d_in[7];
    const float* bo  = (const float*)d_in[8];
    const float* Wtq = (const float*)d_in[9];
    const float* btq = (const float*)d_in[10];
    const float* Wfq = (const float*)d_in[11];
    const float* bfq = (const float*)d_in[12];
    float* out = (float*)d_out;

    static bool init_done = false;
    static bool use_streams = false;
    static cudaStream_t sA, sB, sC;
    static cudaEvent_t evRoot, evX, evA, evW, evB, evC;
    static cudaEvent_t evS01, evS23, evSm01, evSm23, evCtx01, evFin01;
    if (!init_done) {
        cudaFuncSetAttribute(mma_qk_kernel,      cudaFuncAttributeMaxDynamicSharedMemorySize, SMEM_BYTES);
        cudaFuncSetAttribute(mma_v_kernel,       cudaFuncAttributeMaxDynamicSharedMemorySize, SMEM_BYTES);
        cudaFuncSetAttribute(mma_scores_kernel,  cudaFuncAttributeMaxDynamicSharedMemorySize, SMEM_BYTES);
        cudaFuncSetAttribute(mma_context_kernel, cudaFuncAttributeMaxDynamicSharedMemorySize, SMEM_BYTES);
        cudaFuncSetAttribute(mma_final_kernel,   cudaFuncAttributeMaxDynamicSharedMemorySize, SMEM_BYTES);
        bool ok = true;
        ok &= (cudaStreamCreateWithFlags(&sA, cudaStreamNonBlocking) == cudaSuccess);
        ok &= (cudaStreamCreateWithFlags(&sB, cudaStreamNonBlocking) == cudaSuccess);
        ok &= (cudaStreamCreateWithFlags(&sC, cudaStreamNonBlocking) == cudaSuccess);
        ok &= (cudaEventCreateWithFlags(&evRoot,  cudaEventDisableTiming) == cudaSuccess);
        ok &= (cudaEventCreateWithFlags(&evX,     cudaEventDisableTiming) == cudaSuccess);
        ok &= (cudaEventCreateWithFlags(&evA,     cudaEventDisableTiming) == cudaSuccess);
        ok &= (cudaEventCreateWithFlags(&evW,     cudaEventDisableTiming) == cudaSuccess);
        ok &= (cudaEventCreateWithFlags(&evB,     cudaEventDisableTiming) == cudaSuccess);
        ok &= (cudaEventCreateWithFlags(&evC,     cudaEventDisableTiming) == cudaSuccess);
        ok &= (cudaEventCreateWithFlags(&evS01,   cudaEventDisableTiming) == cudaSuccess);
        ok &= (cudaEventCreateWithFlags(&evS23,   cudaEventDisableTiming) == cudaSuccess);
        ok &= (cudaEventCreateWithFlags(&evSm01,  cudaEventDisableTiming) == cudaSuccess);
        ok &= (cudaEventCreateWithFlags(&evSm23,  cudaEventDisableTiming) == cudaSuccess);
        ok &= (cudaEventCreateWithFlags(&evCtx01, cudaEventDisableTiming) == cudaSuccess);
        ok &= (cudaEventCreateWithFlags(&evFin01, cudaEventDisableTiming) == cudaSuccess);
        use_streams = ok;
        init_done = true;
    }

    h16 *xhi, *wqh, *wkh, *wvh, *woh;
    cudaGetSymbolAddress((void**)&xhi, g_xhi);
    cudaGetSymbolAddress((void**)&wqh, g_wqhi);
    cudaGetSymbolAddress((void**)&wkh, g_wkhi);
    cudaGetSymbolAddress((void**)&wvh, g_wvhi);
    cudaGetSymbolAddress((void**)&woh, g_wohi);

    int n4x = (int)((size_t)Mm*Dd/4), n4w = Dd*Dd/4;
    const float WSCALE = 32.f;

    if (use_streams) {
        cudaEventRecord(evRoot, 0);
        // side A: mask-threshold chain
        cudaStreamWaitEvent(sA, evRoot, 0);
        qp_kernel<<<Mm/8, 256, 0, sA>>>(X, Wtq, btq);
        stats_kernel<<<dim3(Nn, Bb), 256, 0, sA>>>();
        thr_kernel<<<1, 32, 0, sA>>>();
        cudaEventRecord(evA, sA);
        // side B: Wq/Wk conversions (for qk), then Wo (for final)
        cudaStreamWaitEvent(sB, evRoot, 0);
        cvt_hi_kernel<<<(n4w + 255)/256, 256, 0, sB>>>(Wq, wqh, WSCALE, n4w);
        cvt_hi_kernel<<<(n4w + 255)/256, 256, 0, sB>>>(Wk, wkh, WSCALE, n4w);
        cudaEventRecord(evW, sB);
        cvt_hi_kernel<<<(n4w + 255)/256, 256, 0, sB>>>(Wo, woh, WSCALE, n4w);
        cudaEventRecord(evB, sB);
        // main: X conversion
        cvt_hi_kernel<<<(n4x + 255)/256, 256>>>(X, xhi, 1.f, n4x);
        cudaEventRecord(evX, 0);
        // side C: v projection + transpose
        cudaStreamWaitEvent(sC, evX, 0);
        cvt_hi_kernel<<<(n4w + 255)/256, 256, 0, sC>>>(Wv, wvh, WSCALE, n4w);
        mma_v_kernel<<<dim3(Dd/128, Mm/128), 256, SMEM_BYTES, sC>>>(bv);
        vtrans_kernel<<<dim3(Nn/64, Dd/64, Bb), 256, 0, sC>>>();
        cudaEventRecord(evC, sC);
        // main chain
        cudaStreamWaitEvent(0, evW, 0);
        mma_qk_kernel<<<dim3(Dd/128, Mm/128, 2), 256, SMEM_BYTES>>>(bq, bk);
        cudaStreamWaitEvent(0, evA, 0);
        mma_scores_kernel<<<dim3(136, 1, 2), 256, SMEM_BYTES>>>(0);
        cudaEventRecord(evS01, 0);
        mma_scores_kernel<<<dim3(136, 1, 2), 256, SMEM_BYTES>>>(2);
        cudaEventRecord(evS23, 0);
        // both softmax halves on sC, hidden behind scores(2,3) / ctx(0,1)
        cudaStreamWaitEvent(sC, evS01, 0);
        softmax_kernel<<<2*Nn, 256, 0, sC>>>(0);
        cudaEventRecord(evSm01, sC);
        cudaStreamWaitEvent(sC, evS23, 0);
        softmax_kernel<<<2*Nn, 256, 0, sC>>>(2);
        cudaEventRecord(evSm23, sC);
        // ctx 0,1 then 2,3; final 0,1 on sC overlaps ctx 2,3
        cudaStreamWaitEvent(0, evSm01, 0);
        mma_context_kernel<<<dim3(Dd/128, Nn/128, 2), 256, SMEM_BYTES>>>(0);
        cudaEventRecord(evCtx01, 0);
        cudaStreamWaitEvent(sC, evCtx01, 0);
        cudaStreamWaitEvent(sC, evB, 0);
        mma_final_kernel<<<dim3(Dd/128, Nn/128, 2), 256, SMEM_BYTES, sC>>>(X, bo, Wfq, bfq, out, 0);
        cudaEventRecord(evFin01, sC);
        cudaStreamWaitEvent(0, evSm23, 0);
        mma_context_kernel<<<dim3(Dd/128, Nn/128, 2), 256, SMEM_BYTES>>>(2);
        cudaStreamWaitEvent(0, evB, 0);
        mma_final_kernel<<<dim3(Dd/128, Nn/128, 2), 256, SMEM_BYTES>>>(X, bo, Wfq, bfq, out, 2);
        cudaStreamWaitEvent(0, evFin01, 0);
    } else {
        qp_kernel<<<Mm/8, 256>>>(X, Wtq, btq);
        stats_kernel<<<dim3(Nn, Bb), 256>>>();
        thr_kernel<<<1, 32>>>();
        cvt_hi_kernel<<<(n4x + 255)/256, 256>>>(X, xhi, 1.f, n4x);
        cvt_hi_kernel<<<(n4w + 255)/256, 256>>>(Wq, wqh, WSCALE, n4w);
        cvt_hi_kernel<<<(n4w + 255)/256, 256>>>(Wk, wkh, WSCALE, n4w);
        cvt_hi_kernel<<<(n4w + 255)/256, 256>>>(Wv, wvh, WSCALE, n4w);
        cvt_hi_kernel<<<(n4w + 255)/256, 256>>>(Wo, woh, WSCALE, n4w);
        mma_qk_kernel<<<dim3(Dd/128, Mm/128, 2), 256, SMEM_BYTES>>>(bq, bk);
        mma_v_kernel<<<dim3(Dd/128, Mm/128), 256, SMEM_BYTES>>>(bv);
        vtrans_kernel<<<dim3(Nn/64, Dd/64, Bb), 256>>>();
        mma_scores_kernel<<<dim3(136, 1, 2), 256, SMEM_BYTES>>>(0);
        mma_scores_kernel<<<dim3(136, 1, 2), 256, SMEM_BYTES>>>(2);
        softmax_kernel<<<2*Nn, 256>>>(0);
        softmax_kernel<<<2*Nn, 256>>>(2);
        mma_context_kernel<<<dim3(Dd/128, Nn/128, 2), 256, SMEM_BYTES>>>(0);
        mma_context_kernel<<<dim3(Dd/128, Nn/128, 2), 256, SMEM_BYTES>>>(2);
        mma_final_kernel<<<dim3(Dd/128, Nn/128, 2), 256, SMEM_BYTES>>>(X, bo, Wfq, bfq, out, 0);
        mma_final_kernel<<<dim3(Dd/128, Nn/128, 2), 256, SMEM_BYTES>>>(X, bo, Wfq, bfq, out, 2);
    }
}